// round 7
// baseline (speedup 1.0000x reference)
#include <cuda_runtime.h>
#include <cuda_fp16.h>
#include <math.h>
#include <cstdint>

#define BATCH 128
#define SEQ   49
#define HID   512
#define VOCAB 32000
#define NSTEP 15
#define BH    (BATCH*HID)

// ---------------- device scratch ----------------
__device__ float  g_x[BATCH*NSTEP*HID];
__device__ float  g_keys[BATCH*SEQ*HID];
__device__ float  g_ctx[BH];
__device__ float  g_h[2*4*BH];
__device__ __half g_hsh[NSTEP*BH];
__device__ float  g_part[6*3*BH];
__device__ __half g_w2h[VOCAB*HID];
#define WG_TOT (1536*1536 + 3*1536*1024)
__device__ __half g_wh[WG_TOT];
__device__ __half g_wl[WG_TOT];
__device__ int    g_cnt[8];
__device__ unsigned g_bcnt = 0;
__device__ unsigned g_bgen = 0;

// ---------------- init ----------------
__global__ void init_kernel() {
    int idx = blockIdx.x * 256 + threadIdx.x;
    if (idx < 4*BH) g_h[idx] = 0.f;
    if (blockIdx.x == 0 && threadIdx.x < 8) g_cnt[threadIdx.x] = 0;
    if (blockIdx.x == 0 && threadIdx.x == 0) { g_bcnt = 0; }
}

// ---------------- fc2 weights -> fp16 ----------------
__global__ void cvt_w2_kernel(const float* __restrict__ w) {
    int i = blockIdx.x * 256 + threadIdx.x;
    const float4* in = (const float4*)w;
    float4 v0 = in[2*i], v1 = in[2*i + 1];
    __half2 h0 = __floats2half2_rn(v0.x, v0.y);
    __half2 h1 = __floats2half2_rn(v0.z, v0.w);
    __half2 h2 = __floats2half2_rn(v1.x, v1.y);
    __half2 h3 = __floats2half2_rn(v1.z, v1.w);
    uint4 o;
    o.x = *(uint32_t*)&h0; o.y = *(uint32_t*)&h1;
    o.z = *(uint32_t*)&h2; o.w = *(uint32_t*)&h3;
    ((uint4*)g_w2h)[i] = o;
}

// ---------------- GRU weights -> packed fp16 hi/lo ----------------
__global__ void wsplit_gru(__half* __restrict__ dh, __half* __restrict__ dl,
                           const float* __restrict__ wih, const float* __restrict__ whh,
                           int Kin, int Ktot) {
    int i = blockIdx.x * 256 + threadIdx.x;
    int k8 = Ktot >> 3;
    int row = i / k8;
    if (row >= 1536) return;
    int c = (i - row * k8) * 8;
    const float* sp = (c < Kin) ? (wih + (size_t)row * Kin + c)
                                : (whh + (size_t)row * 512 + (c - Kin));
    uint32_t hi[4], lo[4];
    #pragma unroll
    for (int j = 0; j < 4; j++) {
        float a = sp[2*j], b = sp[2*j + 1];
        __half2 h2 = __floats2half2_rn(a, b);
        float2 bb = __half22float2(h2);
        __half2 l2 = __floats2half2_rn(a - bb.x, b - bb.y);
        hi[j] = *(uint32_t*)&h2; lo[j] = *(uint32_t*)&l2;
    }
    *(uint4*)(dh + (size_t)row * Ktot + c) = make_uint4(hi[0], hi[1], hi[2], hi[3]);
    *(uint4*)(dl + (size_t)row * Ktot + c) = make_uint4(lo[0], lo[1], lo[2], lo[3]);
}

// ---------------- big SIMT GEMM (x precompute, fp32 exact) ----------------
template<int AMODE>
__global__ void gemm_big(const float* __restrict__ A, const float* __restrict__ W,
                         const float* __restrict__ bias, float* __restrict__ C,
                         int ldN, int Kd, const int* __restrict__ caps)
{
    __shared__ float As[8][132];
    __shared__ float Bs[8][132];
    const int tid = threadIdx.x;
    const int bm = blockIdx.y * 128;
    const int bn = blockIdx.x * 128;
    const int tx = tid & 15, ty = tid >> 4;
    const int arow = tid >> 1;
    const int acol = (tid & 1) * 4;

    const float* a_row_ptr;
    if (AMODE == 1) {
        int m = bm + arow;
        int bb = m / NSTEP, tt = m - bb * NSTEP;
        a_row_ptr = A + (size_t)caps[bb * 16 + tt] * Kd;
    } else {
        a_row_ptr = A + (size_t)(bm + arow) * Kd;
    }
    const float* w_row_ptr = W + (size_t)(bn + arow) * Kd;

    float acc[8][8];
    #pragma unroll
    for (int i = 0; i < 8; i++)
        #pragma unroll
        for (int j = 0; j < 8; j++) acc[i][j] = 0.f;

    for (int k0 = 0; k0 < Kd; k0 += 8) {
        float4 av = *(const float4*)(a_row_ptr + k0 + acol);
        float4 wv = *(const float4*)(w_row_ptr + k0 + acol);
        As[acol+0][arow] = av.x; As[acol+1][arow] = av.y;
        As[acol+2][arow] = av.z; As[acol+3][arow] = av.w;
        Bs[acol+0][arow] = wv.x; Bs[acol+1][arow] = wv.y;
        Bs[acol+2][arow] = wv.z; Bs[acol+3][arow] = wv.w;
        __syncthreads();
        #pragma unroll
        for (int k = 0; k < 8; k++) {
            float af[8], bf[8];
            *(float4*)&af[0] = *(const float4*)&As[k][ty*8];
            *(float4*)&af[4] = *(const float4*)&As[k][ty*8+4];
            *(float4*)&bf[0] = *(const float4*)&Bs[k][tx*8];
            *(float4*)&bf[4] = *(const float4*)&Bs[k][tx*8+4];
            #pragma unroll
            for (int i = 0; i < 8; i++)
                #pragma unroll
                for (int j = 0; j < 8; j++)
                    acc[i][j] += af[i] * bf[j];
        }
        __syncthreads();
    }
    #pragma unroll
    for (int i = 0; i < 8; i++) {
        int m = bm + ty*8 + i;
        float* cptr = C + (size_t)m * ldN + bn + tx*8;
        #pragma unroll
        for (int j = 0; j < 8; j += 4) {
            float4 v;
            v.x = acc[i][j+0] + bias[bn + tx*8 + j+0];
            v.y = acc[i][j+1] + bias[bn + tx*8 + j+1];
            v.z = acc[i][j+2] + bias[bn + tx*8 + j+2];
            v.w = acc[i][j+3] + bias[bn + tx*8 + j+3];
            *(float4*)(cptr + j) = v;
        }
    }
}

// ---------------- keys via mma.sync tf32 ----------------
#define KPAD   36
#define K_ASZ  (128*KPAD)
#define K_BSZ  (256*KPAD)
#define K_SMEMB ((2*K_ASZ + 2*K_BSZ)*4)

__device__ __forceinline__ void hmma_tf32(float& c0, float& c1, float& c2, float& c3,
                                          uint32_t a0, uint32_t a1, uint32_t a2, uint32_t a3,
                                          uint32_t b0, uint32_t b1) {
    asm volatile("mma.sync.aligned.m16n8k8.row.col.f32.tf32.tf32.f32 "
                 "{%0,%1,%2,%3}, {%4,%5,%6,%7}, {%8,%9}, {%0,%1,%2,%3};"
                 : "+f"(c0), "+f"(c1), "+f"(c2), "+f"(c3)
                 : "r"(a0), "r"(a1), "r"(a2), "r"(a3), "r"(b0), "r"(b1));
}
__device__ __forceinline__ void hmma_fp16(float& c0, float& c1, float& c2, float& c3,
                                          uint32_t a0, uint32_t a1, uint32_t a2, uint32_t a3,
                                          uint32_t b0, uint32_t b1) {
    asm volatile("mma.sync.aligned.m16n8k16.row.col.f32.f16.f16.f32 "
                 "{%0,%1,%2,%3}, {%4,%5,%6,%7}, {%8,%9}, {%0,%1,%2,%3};"
                 : "+f"(c0), "+f"(c1), "+f"(c2), "+f"(c3)
                 : "r"(a0), "r"(a1), "r"(a2), "r"(a3), "r"(b0), "r"(b1));
}

__global__ void __launch_bounds__(256, 1) keys_mma(
    const float* __restrict__ A, const float* __restrict__ Bw,
    const float* __restrict__ bias, float* __restrict__ C)
{
    extern __shared__ float smf[];
    float* As = smf;
    float* Bs = smf + 2*K_ASZ;

    const int tid  = threadIdx.x;
    const int lane = tid & 31, wid = tid >> 5;
    const int wm = (wid >> 2) * 64;
    const int wn = (wid & 3)  * 64;
    const int grp = lane >> 2;
    const int tig = lane & 3;
    const int bn = blockIdx.x * 256;
    const int bm = blockIdx.y * 128;

    const float* Ab = A  + (size_t)bm * 512;
    const float* Bb = Bw + (size_t)bn * 512;

    const int lrowA = tid >> 3;
    const int lc4   = (tid & 7) * 4;

    float acc[4][8][4];
    #pragma unroll
    for (int i = 0; i < 4; i++)
        #pragma unroll
        for (int j = 0; j < 8; j++)
            #pragma unroll
            for (int k = 0; k < 4; k++) acc[i][j][k] = 0.f;

    float4 ra[4], rb[8];
    #pragma unroll
    for (int p = 0; p < 4; p++)
        ra[p] = *(const float4*)(Ab + (size_t)(p*32 + lrowA) * 512 + lc4);
    #pragma unroll
    for (int p = 0; p < 8; p++)
        rb[p] = *(const float4*)(Bb + (size_t)(p*32 + lrowA) * 512 + lc4);
    #pragma unroll
    for (int p = 0; p < 4; p++)
        *(float4*)(As + (p*32 + lrowA)*KPAD + lc4) = ra[p];
    #pragma unroll
    for (int p = 0; p < 8; p++)
        *(float4*)(Bs + (p*32 + lrowA)*KPAD + lc4) = rb[p];
    __syncthreads();

    #pragma unroll 1
    for (int kt = 0; kt < 16; kt++) {
        const int buf = kt & 1;
        const float* Asb = As + buf * K_ASZ;
        const float* Bsb = Bs + buf * K_BSZ;

        if (kt < 15) {
            const float* Aq = Ab + (kt+1)*32;
            const float* Bq = Bb + (kt+1)*32;
            #pragma unroll
            for (int p = 0; p < 4; p++)
                ra[p] = *(const float4*)(Aq + (size_t)(p*32 + lrowA) * 512 + lc4);
            #pragma unroll
            for (int p = 0; p < 8; p++)
                rb[p] = *(const float4*)(Bq + (size_t)(p*32 + lrowA) * 512 + lc4);
        }

        #pragma unroll
        for (int k8 = 0; k8 < 4; k8++) {
            const int kc = k8*8 + tig;
            uint32_t af[4][4];
            #pragma unroll
            for (int mi = 0; mi < 4; mi++) {
                const float* ar = Asb + (wm + mi*16 + grp)*KPAD;
                af[mi][0] = __float_as_uint(ar[kc]);
                af[mi][1] = __float_as_uint(ar[8*KPAD + kc]);
                af[mi][2] = __float_as_uint(ar[kc + 4]);
                af[mi][3] = __float_as_uint(ar[8*KPAD + kc + 4]);
            }
            #pragma unroll
            for (int nj = 0; nj < 8; nj++) {
                const float* br = Bsb + (wn + nj*8 + grp)*KPAD + k8*8;
                uint32_t b0 = __float_as_uint(br[tig]);
                uint32_t b1 = __float_as_uint(br[tig + 4]);
                #pragma unroll
                for (int mi = 0; mi < 4; mi++)
                    hmma_tf32(acc[mi][nj][0], acc[mi][nj][1], acc[mi][nj][2], acc[mi][nj][3],
                              af[mi][0], af[mi][1], af[mi][2], af[mi][3], b0, b1);
            }
        }

        if (kt < 15) {
            float* Asn = As + (buf ^ 1) * K_ASZ;
            float* Bsn = Bs + (buf ^ 1) * K_BSZ;
            #pragma unroll
            for (int p = 0; p < 4; p++)
                *(float4*)(Asn + (p*32 + lrowA)*KPAD + lc4) = ra[p];
            #pragma unroll
            for (int p = 0; p < 8; p++)
                *(float4*)(Bsn + (p*32 + lrowA)*KPAD + lc4) = rb[p];
        }
        __syncthreads();
    }

    #pragma unroll
    for (int mi = 0; mi < 4; mi++) {
        const int m = bm + wm + mi*16 + grp;
        #pragma unroll
        for (int nj = 0; nj < 8; nj++) {
            const int n = bn + wn + nj*8 + 2*tig;
            float bx = bias[n], by = bias[n + 1];
            *(float2*)(C + (size_t)m * 512 + n) =
                make_float2(acc[mi][nj][0] + bx, acc[mi][nj][1] + by);
            *(float2*)(C + (size_t)(m + 8) * 512 + n) =
                make_float2(acc[mi][nj][2] + bx, acc[mi][nj][3] + by);
        }
    }
}

// =====================================================================
// Persistent chain kernel: grid barrier + device bodies
// =====================================================================
#define GR_SMEM ((2*5120*2 + 2*2560*2)*2)   // 61440 bytes

__device__ __forceinline__ void grid_bar() {
    __syncthreads();
    if (threadIdx.x == 0) {
        __threadfence();
        unsigned gen = *(volatile unsigned*)&g_bgen;
        if (atomicAdd(&g_bcnt, 1u) == gridDim.x - 1) {
            g_bcnt = 0;
            __threadfence();
            *(volatile unsigned*)&g_bgen = gen + 1;
        } else {
            while (*(volatile unsigned*)&g_bgen == gen) {}
        }
        __threadfence();
    }
    __syncthreads();
}

// ---- attention body (one batch element per call) ----
__device__ void att_body(int b, const float* __restrict__ h3,
                         const float* __restrict__ wq, const float* __restrict__ bq,
                         const float* __restrict__ keys, const float* __restrict__ features,
                         const float* __restrict__ v_w, const float* __restrict__ v_b,
                         const float* __restrict__ fc0_w, const float* __restrict__ fc0_b,
                         float* __restrict__ ctx_out, float* sm)
{
    const int tid = threadIdx.x;
    float* hs_ = sm;
    float* qs  = sm + 512;
    float* vw  = sm + 1024;
    float* cs  = sm + 1536;
    float* e   = sm + 2048;

    for (int i = tid; i < 512; i += 256) {
        hs_[i] = __ldcg(h3 + b*512 + i);
        vw[i]  = v_w[i];
    }
    __syncthreads();

    for (int j = tid; j < 512; j += 256) {
        const float* wr = wq + (size_t)j * 512;
        float acc = 0.f;
        #pragma unroll 8
        for (int k = 0; k < 512; k += 4) {
            float4 w = *(const float4*)(wr + k);
            acc += hs_[k]*w.x + hs_[k+1]*w.y + hs_[k+2]*w.z + hs_[k+3]*w.w;
        }
        qs[j] = acc + bq[j];
    }
    __syncthreads();

    const int warp = tid >> 5, lane = tid & 31;
    for (int s = warp; s < SEQ; s += 8) {
        const float* kp = keys + ((size_t)b * SEQ + s) * 512;
        float acc = 0.f;
        #pragma unroll
        for (int k = lane; k < 512; k += 32)
            acc += tanhf(qs[k] + kp[k]) * vw[k];
        #pragma unroll
        for (int o = 16; o; o >>= 1) acc += __shfl_xor_sync(0xffffffffu, acc, o);
        if (!lane) e[s] = acc + v_b[0];
    }
    __syncthreads();

    if (warp == 0) {
        float v1 = (lane < SEQ) ? e[lane] : -1e30f;
        float v2 = (lane + 32 < SEQ) ? e[lane + 32] : -1e30f;
        float m = fmaxf(v1, v2);
        #pragma unroll
        for (int o = 16; o; o >>= 1) m = fmaxf(m, __shfl_xor_sync(0xffffffffu, m, o));
        float e1 = (lane < SEQ) ? expf(v1 - m) : 0.f;
        float e2 = (lane + 32 < SEQ) ? expf(v2 - m) : 0.f;
        float s = e1 + e2;
        #pragma unroll
        for (int o = 16; o; o >>= 1) s += __shfl_xor_sync(0xffffffffu, s, o);
        float inv = 1.f / s;
        if (lane < SEQ) e[lane] = e1 * inv;
        if (lane + 32 < SEQ) e[lane + 32] = e2 * inv;
    }
    __syncthreads();

    for (int k = tid; k < 512; k += 256) {
        float acc = 0.f;
        const float* f = features + (size_t)b * SEQ * 512 + k;
        #pragma unroll 7
        for (int s = 0; s < SEQ; s++) acc += e[s] * f[(size_t)s * 512];
        cs[k] = acc;
    }
    __syncthreads();

    for (int j = tid; j < 512; j += 256) {
        const float* wr = fc0_w + (size_t)j * 512;
        float acc = 0.f;
        #pragma unroll 8
        for (int k = 0; k < 512; k += 4) {
            float4 w = *(const float4*)(wr + k);
            acc += cs[k]*w.x + cs[k+1]*w.y + cs[k+2]*w.z + cs[k+3]*w.w;
        }
        ctx_out[b*512 + j] = acc + fc0_b[j];
    }
    __syncthreads();
}

// ---- GRU tile body ----
template<int NK>
__device__ void gru_tile(int nt, int kc,
    const float* __restrict__ srcA, int ldA,
    const float* __restrict__ srcB, const float* __restrict__ srcC,
    const __half* __restrict__ Wh, const __half* __restrict__ Wl, int ldK,
    const float* __restrict__ bih, const float* __restrict__ bhh,
    const float* __restrict__ h_old, float* __restrict__ h_new,
    __half* __restrict__ hs_out, __half* smg)
{
    __half* AHI = smg;
    __half* ALO = AHI + 2*5120;
    __half* BHI = ALO + 2*5120;
    __half* BLO = BHI + 2*2560;

    const int tid = threadIdx.x;
    const int lane = tid & 31, wid = tid >> 5;
    const int wm = (wid & 1) * 64;
    const int wn = (wid >> 1) * 16;
    const int grp = lane >> 2, tig = lane & 3;
    const int bn = nt * 64;

    const float* src; int ld;
    {
        int sel = kc >> 1;
        if (sel == 0)      { src = srcA; ld = ldA; }
        else if (sel == 1) { src = srcB; ld = 512; }
        else               { src = srcC; ld = 512; }
    }
    const int koff = (kc & 1) * 256;

    const int arow = tid >> 1;
    const int acol = (tid & 1) * 16;
    const int brow = tid >> 2;
    const int bcol = (tid & 3) * 8;

    const float*  Arow  = src + (size_t)arow * ld + koff + acol;
    const __half* Wrowh = Wh + (size_t)(bn + brow) * ldK + kc*256 + bcol;
    const __half* Wrowl = Wl + (size_t)(bn + brow) * ldK + kc*256 + bcol;

    float acc[4][2][4];
    #pragma unroll
    for (int i = 0; i < 4; i++)
        #pragma unroll
        for (int j = 0; j < 2; j++)
            #pragma unroll
            for (int k = 0; k < 4; k++) acc[i][j][k] = 0.f;

    float fa[16];
    uint4 wh4, wl4;

    #pragma unroll
    for (int p = 0; p < 4; p++)
        *(float4*)&fa[p*4] = __ldcg((const float4*)(Arow + p*4));
    wh4 = *(const uint4*)(Wrowh);
    wl4 = *(const uint4*)(Wrowl);

    {
        uint32_t hi[8], lo[8];
        #pragma unroll
        for (int j = 0; j < 8; j++) {
            __half2 h2 = __floats2half2_rn(fa[2*j], fa[2*j+1]);
            float2 bb = __half22float2(h2);
            __half2 l2 = __floats2half2_rn(fa[2*j] - bb.x, fa[2*j+1] - bb.y);
            hi[j] = *(uint32_t*)&h2; lo[j] = *(uint32_t*)&l2;
        }
        __half* ah = AHI + arow*40 + acol;
        __half* al = ALO + arow*40 + acol;
        *(uint4*)ah       = make_uint4(hi[0], hi[1], hi[2], hi[3]);
        *(uint4*)(ah + 8) = make_uint4(hi[4], hi[5], hi[6], hi[7]);
        *(uint4*)al       = make_uint4(lo[0], lo[1], lo[2], lo[3]);
        *(uint4*)(al + 8) = make_uint4(lo[4], lo[5], lo[6], lo[7]);
        *(uint4*)(BHI + brow*40 + bcol) = wh4;
        *(uint4*)(BLO + brow*40 + bcol) = wl4;
    }
    __syncthreads();

    #pragma unroll 1
    for (int kt = 0; kt < 8; kt++) {
        const int buf = kt & 1;
        const __half* Ah = AHI + buf*5120;
        const __half* Al = ALO + buf*5120;
        const __half* Bh = BHI + buf*2560;
        const __half* Bl = BLO + buf*2560;

        if (kt < 7) {
            #pragma unroll
            for (int p = 0; p < 4; p++)
                *(float4*)&fa[p*4] = __ldcg((const float4*)(Arow + (kt+1)*32 + p*4));
            wh4 = *(const uint4*)(Wrowh + (kt+1)*32);
            wl4 = *(const uint4*)(Wrowl + (kt+1)*32);
        }

        #pragma unroll
        for (int k16 = 0; k16 < 2; k16++) {
            const int kb = k16*16 + tig*2;
            uint32_t ah[4][4], al[4][4];
            #pragma unroll
            for (int mi = 0; mi < 4; mi++) {
                const __half* arh = Ah + (wm + mi*16 + grp)*40;
                const __half* arl = Al + (wm + mi*16 + grp)*40;
                ah[mi][0] = *(const uint32_t*)(arh + kb);
                ah[mi][1] = *(const uint32_t*)(arh + 8*40 + kb);
                ah[mi][2] = *(const uint32_t*)(arh + kb + 8);
                ah[mi][3] = *(const uint32_t*)(arh + 8*40 + kb + 8);
                al[mi][0] = *(const uint32_t*)(arl + kb);
                al[mi][1] = *(const uint32_t*)(arl + 8*40 + kb);
                al[mi][2] = *(const uint32_t*)(arl + kb + 8);
                al[mi][3] = *(const uint32_t*)(arl + 8*40 + kb + 8);
            }
            #pragma unroll
            for (int nj = 0; nj < 2; nj++) {
                const __half* brh = Bh + (wn + nj*8 + grp)*40 + kb;
                const __half* brl = Bl + (wn + nj*8 + grp)*40 + kb;
                uint32_t b0h = *(const uint32_t*)(brh);
                uint32_t b1h = *(const uint32_t*)(brh + 8);
                uint32_t b0l = *(const uint32_t*)(brl);
                uint32_t b1l = *(const uint32_t*)(brl + 8);
                #pragma unroll
                for (int mi = 0; mi < 4; mi++) {
                    hmma_fp16(acc[mi][nj][0], acc[mi][nj][1], acc[mi][nj][2], acc[mi][nj][3],
                              ah[mi][0], ah[mi][1], ah[mi][2], ah[mi][3], b0h, b1h);
                    hmma_fp16(acc[mi][nj][0], acc[mi][nj][1], acc[mi][nj][2], acc[mi][nj][3],
                              ah[mi][0], ah[mi][1], ah[mi][2], ah[mi][3], b0l, b1l);
                    hmma_fp16(acc[mi][nj][0], acc[mi][nj][1], acc[mi][nj][2], acc[mi][nj][3],
                              al[mi][0], al[mi][1], al[mi][2], al[mi][3], b0h, b1h);
                }
            }
        }

        if (kt < 7) {
            const int nb = buf ^ 1;
            uint32_t hi[8], lo[8];
            #pragma unroll
            for (int j = 0; j < 8; j++) {
                __half2 h2 = __floats2half2_rn(fa[2*j], fa[2*j+1]);
                float2 bb = __half22float2(h2);
                __half2 l2 = __floats2half2_rn(fa[2*j] - bb.x, fa[2*j+1] - bb.y);
                hi[j] = *(uint32_t*)&h2; lo[j] = *(uint32_t*)&l2;
            }
            __half* ah = AHI + nb*5120 + arow*40 + acol;
            __half* al = ALO + nb*5120 + arow*40 + acol;
            *(uint4*)ah       = make_uint4(hi[0], hi[1], hi[2], hi[3]);
            *(uint4*)(ah + 8) = make_uint4(hi[4], hi[5], hi[6], hi[7]);
            *(uint4*)al       = make_uint4(lo[0], lo[1], lo[2], lo[3]);
            *(uint4*)(al + 8) = make_uint4(lo[4], lo[5], lo[6], lo[7]);
            *(uint4*)(BHI + nb*2560 + brow*40 + bcol) = wh4;
            *(uint4*)(BLO + nb*2560 + brow*40 + bcol) = wl4;
        }
        __syncthreads();
    }

    {
        float* P = g_part + ((size_t)(kc*24 + nt)) * 8192;
        #pragma unroll
        for (int mi = 0; mi < 4; mi++) {
            #pragma unroll
            for (int nj = 0; nj < 2; nj++) {
                int m = wm + mi*16 + grp;
                int nc = wn + nj*8 + tig*2;
                *(float2*)(P + m*64 + nc)     = make_float2(acc[mi][nj][0], acc[mi][nj][1]);
                *(float2*)(P + (m+8)*64 + nc) = make_float2(acc[mi][nj][2], acc[mi][nj][3]);
            }
        }
    }

    __threadfence();
    __shared__ int sdone;
    if (tid == 0) {
        int g = nt & 7;
        int v = atomicAdd(&g_cnt[g], 1);
        int done = (v == 3*NK - 1);
        if (done) g_cnt[g] = 0;
        sdone = done;
    }
    __syncthreads();
    if (!sdone) return;
    __threadfence();

    const int g = nt & 7;
    const int cc = (tid & 15) * 4;
    const int c  = g*64 + cc;
    float4 bir = *(const float4*)(bih + c);
    float4 biz = *(const float4*)(bih + 512 + c);
    float4 bin = *(const float4*)(bih + 1024 + c);
    float4 bhr = *(const float4*)(bhh + c);
    float4 bhz = *(const float4*)(bhh + 512 + c);
    float4 bhn = *(const float4*)(bhh + 1024 + c);

    #pragma unroll
    for (int i = 0; i < 8; i++) {
        const int m = (tid >> 4) * 8 + i;
        float4 r4 = make_float4(0,0,0,0), z4 = r4, in4 = r4, hn4 = r4;
        #pragma unroll
        for (int kx = 0; kx < NK; kx++) {
            const float* Pr = g_part + ((size_t)(kx*24 + g))      * 8192 + m*64 + cc;
            const float* Pz = g_part + ((size_t)(kx*24 + 8 + g))  * 8192 + m*64 + cc;
            const float* Pn = g_part + ((size_t)(kx*24 + 16 + g)) * 8192 + m*64 + cc;
            float4 a = __ldcg((const float4*)Pr);
            r4.x += a.x; r4.y += a.y; r4.z += a.z; r4.w += a.w;
            a = __ldcg((const float4*)Pz);
            z4.x += a.x; z4.y += a.y; z4.z += a.z; z4.w += a.w;
            a = __ldcg((const float4*)Pn);
            if (kx < NK-2) { in4.x += a.x; in4.y += a.y; in4.z += a.z; in4.w += a.w; }
            else           { hn4.x += a.x; hn4.y += a.y; hn4.z += a.z; hn4.w += a.w; }
        }
        float4 ho = __ldcg((const float4*)(h_old + (size_t)m*512 + c));
        float hv[4];
        #pragma unroll
        for (int q = 0; q < 4; q++) {
            float rp = ((float*)&r4)[q] + ((float*)&bir)[q] + ((float*)&bhr)[q];
            float zp = ((float*)&z4)[q] + ((float*)&biz)[q] + ((float*)&bhz)[q];
            float ip = ((float*)&in4)[q] + ((float*)&bin)[q];
            float hp = ((float*)&hn4)[q] + ((float*)&bhn)[q];
            float r = 1.f / (1.f + expf(-rp));
            float z = 1.f / (1.f + expf(-zp));
            float n = tanhf(ip + r * hp);
            hv[q] = (1.f - z) * n + z * ((float*)&ho)[q];
        }
        *(float4*)(h_new + (size_t)m*512 + c) = make_float4(hv[0], hv[1], hv[2], hv[3]);
        if (hs_out) {
            __half2 o0 = __floats2half2_rn(hv[0], hv[1]);
            __half2 o1 = __floats2half2_rn(hv[2], hv[3]);
            uint2 ov; ov.x = *(uint32_t*)&o0; ov.y = *(uint32_t*)&o1;
            *(uint2*)(hs_out + (size_t)m*512 + c) = ov;
        }
    }
}

// ---- persistent chain kernel ----
__global__ void __launch_bounds__(256, 1) chain_kernel(
    const float* __restrict__ features,
    const float* __restrict__ wq, const float* __restrict__ bq,
    const float* __restrict__ v_w, const float* __restrict__ v_b,
    const float* __restrict__ fc0_w, const float* __restrict__ fc0_b,
    const float* __restrict__ bih0, const float* __restrict__ bhh0,
    const float* __restrict__ bihr, const float* __restrict__ bhhr)
{
    extern __shared__ __half smg[];
    float* smf = (float*)smg;

    for (int t = 0; t < NSTEP; t++) {
        const float* hold = g_h + (t & 1) * (4 * BH);
        float*       hnew = g_h + ((t & 1) ^ 1) * (4 * BH);

        // phase A: attention (q-GEMM + softmax + context + fc0)
        for (int b = blockIdx.x; b < BATCH; b += gridDim.x)
            att_body(b, hold + 3*BH, wq, bq, g_keys, features, v_w, v_b,
                     fc0_w, fc0_b, g_ctx, smf);
        grid_bar();

        // phase L0: K=1536, NK=6 -> 144 tiles
        for (int w = blockIdx.x; w < 144; w += gridDim.x)
            gru_tile<6>(w % 24, w / 24,
                        g_x + t*HID, NSTEP*HID, g_ctx, hold,
                        g_wh, g_wl, 1536, bih0, bhh0, hold, hnew, nullptr, smg);
        grid_bar();

        // phases L1..L3: K=1024, NK=4 -> 96 tiles
        for (int l = 1; l < 4; l++) {
            const size_t off = (size_t)1536*1536 + (size_t)(l-1)*1536*1024;
            __half* hs_out = (l == 3) ? (g_hsh + t * BH) : nullptr;
            for (int w = blockIdx.x; w < 96; w += gridDim.x)
                gru_tile<4>(w % 24, w / 24,
                            hnew + (l-1)*BH, 512, hold + l*BH, nullptr,
                            g_wh + off, g_wl + off, 1024,
                            bihr + (l-1)*1536, bhhr + (l-1)*1536,
                            hold + l*BH, hnew + l*BH, hs_out, smg);
            grid_bar();
        }
    }
}

// ---------------- fc2 via mma.sync fp16 ----------------
#define F2_PAD  40
#define F2_ASZ  (128*F2_PAD)
#define F2_BSZ  (256*F2_PAD)
#define F2_SMEM ((2*F2_ASZ + 2*F2_BSZ)*2)

__global__ void __launch_bounds__(256, 1) fc2_mma_fp16(
    const __half* __restrict__ A, const __half* __restrict__ Bw,
    const float* __restrict__ bias, float* __restrict__ out)
{
    extern __shared__ __half smh[];
    __half* As = smh;
    __half* Bs = smh + 2*F2_ASZ;

    const int tid  = threadIdx.x;
    const int lane = tid & 31, wid = tid >> 5;
    const int wm = (wid >> 2) * 64;
    const int wn = (wid & 3)  * 64;
    const int grp = lane >> 2;
    const int tig = lane & 3;
    const int bn = blockIdx.x * 256;
    const int t  = blockIdx.y;

    const __half* Ab = A  + (size_t)t  * 128 * 512;
    const __half* Bb = Bw + (size_t)bn * 512;

    float acc[4][8][4];
    #pragma unroll
    for (int i = 0; i < 4; i++)
        #pragma unroll
        for (int j = 0; j < 8; j++)
            #pragma unroll
            for (int k = 0; k < 4; k++) acc[i][j][k] = 0.f;

    uint4 ra[2], rb[4];
    #pragma unroll
    for (int p = 0; p < 2; p++) {
        int idx = tid + p * 256;
        int row = idx >> 2, c8 = (idx & 3) * 8;
        ra[p] = *(const uint4*)(Ab + (size_t)row * 512 + c8);
    }
    #pragma unroll
    for (int p = 0; p < 4; p++) {
        int idx = tid + p * 256;
        int row = idx >> 2, c8 = (idx & 3) * 8;
        rb[p] = *(const uint4*)(Bb + (size_t)row * 512 + c8);
    }
    #pragma unroll
    for (int p = 0; p < 2; p++) {
        int idx = tid + p * 256;
        int row = idx >> 2, c8 = (idx & 3) * 8;
        *(uint4*)(As + row*F2_PAD + c8) = ra[p];
    }
    #pragma unroll
    for (int p = 0; p < 4; p++) {
        int idx = tid + p * 256;
        int row = idx >> 2, c8 = (idx & 3) * 8;
        *(uint4*)(Bs + row*F2_PAD + c8) = rb[p];
    }
    __syncthreads();

    #pragma unroll 1
    for (int kt = 0; kt < 16; kt++) {
        const int buf = kt & 1;
        const __half* Asb = As + buf * F2_ASZ;
        const __half* Bsb = Bs + buf * F2_BSZ;

        if (kt < 15) {
            const __half* Aq = Ab + (kt+1)*32;
            const __half* Bq = Bb + (kt+1)*32;
            #pragma unroll
            for (int p = 0; p < 2; p++) {
                int idx = tid + p * 256;
                int row = idx >> 2, c8 = (idx & 3) * 8;
                ra[p] = *(const uint4*)(Aq + (size_t)row * 512 + c8);
            }
            #pragma unroll
            for (int p = 0; p < 4; p++) {
                int idx = tid + p * 256;
                int row = idx >> 2, c8 = (idx & 3) * 8;
                rb[p] = *(const uint4*)(Bq + (size_t)row * 512 + c8);
            }
        }

        #pragma unroll
        for (int k16 = 0; k16 < 2; k16++) {
            const int kb = k16*16 + tig*2;
            uint32_t af[4][4];
            #pragma unroll
            for (int mi = 0; mi < 4; mi++) {
                const __half* ar = Asb + (wm + mi*16 + grp)*F2_PAD;
                af[mi][0] = *(const uint32_t*)(ar + kb);
                af[mi][1] = *(const uint32_t*)(ar + 8*F2_PAD + kb);
                af[mi][2] = *(const uint32_t*)(ar + kb + 8);
                af[mi][3] = *(const uint32_t*)(ar + 8*F2_PAD + kb + 8);
            }
            #pragma unroll
            for (int nj = 0; nj < 8; nj++) {
                const __half* br = Bsb + (wn + nj*8 + grp)*F2_PAD + kb;
                uint32_t b0 = *(const uint32_t*)(br);
                uint32_t b1 = *(const uint32_t*)(br + 8);
                #pragma unroll
                for (int mi = 0; mi < 4; mi++)
                    hmma_fp16(acc[mi][nj][0], acc[mi][nj][1], acc[mi][nj][2], acc[mi][nj][3],
                              af[mi][0], af[mi][1], af[mi][2], af[mi][3], b0, b1);
            }
        }

        if (kt < 15) {
            __half* Asn = As + (buf ^ 1) * F2_ASZ;
            __half* Bsn = Bs + (buf ^ 1) * F2_BSZ;
            #pragma unroll
            for (int p = 0; p < 2; p++) {
                int idx = tid + p * 256;
                int row = idx >> 2, c8 = (idx & 3) * 8;
                *(uint4*)(Asn + row*F2_PAD + c8) = ra[p];
            }
            #pragma unroll
            for (int p = 0; p < 4; p++) {
                int idx = tid + p * 256;
                int row = idx >> 2, c8 = (idx & 3) * 8;
                *(uint4*)(Bsn + row*F2_PAD + c8) = rb[p];
            }
        }
        __syncthreads();
    }

    #pragma unroll
    for (int mi = 0; mi < 4; mi++) {
        const int b0 = wm + mi*16 + grp;
        float* o0 = out + ((size_t)b0       * NSTEP + t) * VOCAB + bn + wn;
        float* o8 = out + ((size_t)(b0 + 8) * NSTEP + t) * VOCAB + bn + wn;
        #pragma unroll
        for (int nj = 0; nj < 8; nj++) {
            const int n = nj*8 + 2*tig;
            float bx = bias[bn + wn + n];
            float by = bias[bn + wn + n + 1];
            *(float2*)(o0 + n) = make_float2(acc[mi][nj][0] + bx, acc[mi][nj][1] + by);
            *(float2*)(o8 + n) = make_float2(acc[mi][nj][2] + bx, acc[mi][nj][3] + by);
        }
    }
}

// ---------------- host launch ----------------
extern "C" void kernel_launch(void* const* d_in, const int* in_sizes, int n_in,
                              void* d_out, int out_size)
{
    const float* features = (const float*)d_in[0];
    const int*   caps     = (const int*)  d_in[1];
    const float* emb      = (const float*)d_in[2];
    const float* fc1_w    = (const float*)d_in[3];
    const float* fc1_b    = (const float*)d_in[4];
    const float* fc0_w    = (const float*)d_in[5];
    const float* fc0_b    = (const float*)d_in[6];
    const float* wq       = (const float*)d_in[7];
    const float* bq       = (const float*)d_in[8];
    const float* wk       = (const float*)d_in[9];
    const float* bk       = (const float*)d_in[10];
    const float* v_w      = (const float*)d_in[11];
    const float* v_b      = (const float*)d_in[12];
    const float* wih0     = (const float*)d_in[13];
    const float* whh0     = (const float*)d_in[14];
    const float* bih0     = (const float*)d_in[15];
    const float* bhh0     = (const float*)d_in[16];
    const float* wihr     = (const float*)d_in[17];
    const float* whhr     = (const float*)d_in[18];
    const float* bihr     = (const float*)d_in[19];
    const float* bhhr     = (const float*)d_in[20];
    const float* fc2_w    = (const float*)d_in[21];
    const float* fc2_b    = (const float*)d_in[22];
    float* out = (float*)d_out;

    float *px, *pkeys;
    __half *phsh, *pw2h, *pwh, *pwl;
    cudaGetSymbolAddress((void**)&px,    g_x);
    cudaGetSymbolAddress((void**)&pkeys, g_keys);
    cudaGetSymbolAddress((void**)&phsh,  g_hsh);
    cudaGetSymbolAddress((void**)&pw2h,  g_w2h);
    cudaGetSymbolAddress((void**)&pwh,   g_wh);
    cudaGetSymbolAddress((void**)&pwl,   g_wl);

    cudaFuncSetAttribute(fc2_mma_fp16, cudaFuncAttributeMaxDynamicSharedMemorySize, F2_SMEM);
    cudaFuncSetAttribute(keys_mma,     cudaFuncAttributeMaxDynamicSharedMemorySize, K_SMEMB);
    cudaFuncSetAttribute(chain_kernel, cudaFuncAttributeMaxDynamicSharedMemorySize, GR_SMEM);

    // persistent grid size: all blocks must be co-resident
    int nsm = 0;
    cudaDeviceGetAttribute(&nsm, cudaDevAttrMultiProcessorCount, 0);
    int occ = 1;
    cudaOccupancyMaxActiveBlocksPerMultiprocessor(&occ, chain_kernel, 256, GR_SMEM);
    if (occ < 1) occ = 1;
    int nb = nsm * occ;
    if (nb > 144) nb = 144;

    init_kernel<<<1024, 256>>>();
    cvt_w2_kernel<<<VOCAB*HID/8/256, 256>>>(fc2_w);

    wsplit_gru<<<(1536*1536/8 + 255)/256, 256>>>(pwh, pwl, wih0, whh0, 1024, 1536);
    for (int l = 1; l < 4; l++) {
        size_t off = (size_t)1536*1536 + (size_t)(l-1)*1536*1024;
        wsplit_gru<<<(1536*1024/8 + 255)/256, 256>>>(
            pwh + off, pwl + off,
            wihr + (size_t)(l-1)*1536*512, whhr + (size_t)(l-1)*1536*512, 512, 1024);
    }

    gemm_big<1><<<dim3(4, 15), 256>>>(emb, fc1_w, fc1_b, px, 512, 512, caps);
    keys_mma<<<dim3(2, 49), 256, K_SMEMB>>>(features, wk, bk, pkeys);

    chain_kernel<<<nb, 256, GR_SMEM>>>(features, wq, bq, v_w, v_b, fc0_w, fc0_b,
                                       bih0, bhh0, bihr, bhhr);

    fc2_mma_fp16<<<dim3(VOCAB/256, NSTEP), 256, F2_SMEM>>>(phsh, pw2h, fc2_b, out);
}

// round 8
// speedup vs baseline: 1.1366x; 1.1366x over previous
#include <cuda_runtime.h>
#include <cuda_fp16.h>
#include <math.h>
#include <cstdint>

#define BATCH 128
#define SEQ   49
#define HID   512
#define VOCAB 32000
#define NSTEP 15
#define BH    (BATCH*HID)

// ---------------- device scratch ----------------
__device__ float  g_x[BATCH*NSTEP*HID];
__device__ float  g_keys[BATCH*SEQ*HID];
__device__ float  g_q[BH];
__device__ float  g_context[BH];
__device__ float  g_ctx[BH];
__device__ float  g_h[2*4*BH];
__device__ __half g_hsh[NSTEP*BH];
__device__ float  g_part[6*3*BH];
__device__ __half g_w2h[VOCAB*HID];
#define WG_TOT (1536*1536 + 3*1536*1024)
__device__ __half g_wh[WG_TOT];
__device__ __half g_wl[WG_TOT];
__device__ __half g_lwh[2*HID*HID];   // [wq | fc0] fp16 hi
__device__ __half g_lwl[2*HID*HID];   // lo
__device__ int    g_cnt[8];
__device__ unsigned g_bcnt = 0;
__device__ unsigned g_bgen = 0;

// ---------------- init ----------------
__global__ void init_kernel() {
    int idx = blockIdx.x * 256 + threadIdx.x;
    if (idx < 4*BH) g_h[idx] = 0.f;
    if (blockIdx.x == 0 && threadIdx.x < 8) g_cnt[threadIdx.x] = 0;
    if (blockIdx.x == 0 && threadIdx.x == 0) { g_bcnt = 0; }
}

// ---------------- fc2 weights -> fp16 ----------------
__global__ void cvt_w2_kernel(const float* __restrict__ w) {
    int i = blockIdx.x * 256 + threadIdx.x;
    const float4* in = (const float4*)w;
    float4 v0 = in[2*i], v1 = in[2*i + 1];
    __half2 h0 = __floats2half2_rn(v0.x, v0.y);
    __half2 h1 = __floats2half2_rn(v0.z, v0.w);
    __half2 h2 = __floats2half2_rn(v1.x, v1.y);
    __half2 h3 = __floats2half2_rn(v1.z, v1.w);
    uint4 o;
    o.x = *(uint32_t*)&h0; o.y = *(uint32_t*)&h1;
    o.z = *(uint32_t*)&h2; o.w = *(uint32_t*)&h3;
    ((uint4*)g_w2h)[i] = o;
}

// ---------------- split 8 floats -> hi/lo fp16 ----------------
__device__ __forceinline__ void split8(const float* sp, uint4& hiv, uint4& lov) {
    uint32_t hi[4], lo[4];
    #pragma unroll
    for (int j = 0; j < 4; j++) {
        float a = sp[2*j], b = sp[2*j + 1];
        __half2 h2 = __floats2half2_rn(a, b);
        float2 bb = __half22float2(h2);
        __half2 l2 = __floats2half2_rn(a - bb.x, b - bb.y);
        hi[j] = *(uint32_t*)&h2; lo[j] = *(uint32_t*)&l2;
    }
    hiv = make_uint4(hi[0], hi[1], hi[2], hi[3]);
    lov = make_uint4(lo[0], lo[1], lo[2], lo[3]);
}

// ---------------- ALL weight splits in ONE kernel (profile positioning) ----
// chunks: L0 294912 | L1-3 3x196608 | wq 32768 | fc0 32768  -> total 950272
__global__ void wsplit_all(const float* __restrict__ wih0, const float* __restrict__ whh0,
                           const float* __restrict__ wihr, const float* __restrict__ whhr,
                           const float* __restrict__ wq,   const float* __restrict__ fc0_w) {
    int i = blockIdx.x * 256 + threadIdx.x;
    const int C0 = 294912, CL = 196608, CW = 32768;
    const float* sp;
    __half *dh, *dl;
    size_t doff;
    if (i < C0) {
        int row = i / 192, c = (i - row*192) * 8;
        sp = (c < 1024) ? (wih0 + (size_t)row*1024 + c) : (whh0 + (size_t)row*512 + (c - 1024));
        dh = g_wh; dl = g_wl; doff = (size_t)row*1536 + c;
    } else if (i < C0 + 3*CL) {
        int j = i - C0;
        int l = j / CL; j -= l*CL;
        int row = j / 128, c = (j - row*128) * 8;
        const float* wih = wihr + (size_t)l*1536*512;
        const float* whh = whhr + (size_t)l*1536*512;
        sp = (c < 512) ? (wih + (size_t)row*512 + c) : (whh + (size_t)row*512 + (c - 512));
        dh = g_wh; dl = g_wl;
        doff = (size_t)1536*1536 + (size_t)l*1536*1024 + (size_t)row*1024 + c;
    } else if (i < C0 + 3*CL + CW) {
        int j = i - C0 - 3*CL;
        int row = j / 64, c = (j - row*64) * 8;
        sp = wq + (size_t)row*512 + c;
        dh = g_lwh; dl = g_lwl; doff = (size_t)row*512 + c;
    } else {
        int j = i - C0 - 3*CL - CW;
        int row = j / 64, c = (j - row*64) * 8;
        sp = fc0_w + (size_t)row*512 + c;
        dh = g_lwh; dl = g_lwl; doff = (size_t)HID*HID + (size_t)row*512 + c;
    }
    uint4 hiv, lov;
    split8(sp, hiv, lov);
    *(uint4*)(dh + doff) = hiv;
    *(uint4*)(dl + doff) = lov;
}

// ---------------- big SIMT GEMM (x precompute, fp32 exact) ----------------
__global__ void gemm_big_gather(const float* __restrict__ A, const float* __restrict__ W,
                                const float* __restrict__ bias, float* __restrict__ C,
                                const int* __restrict__ caps)
{
    __shared__ float As[8][132];
    __shared__ float Bs[8][132];
    const int tid = threadIdx.x;
    const int bm = blockIdx.y * 128;
    const int bn = blockIdx.x * 128;
    const int tx = tid & 15, ty = tid >> 4;
    const int arow = tid >> 1;
    const int acol = (tid & 1) * 4;

    int m = bm + arow;
    int bb = m / NSTEP, tt = m - bb * NSTEP;
    const float* a_row_ptr = A + (size_t)caps[bb * 16 + tt] * 512;
    const float* w_row_ptr = W + (size_t)(bn + arow) * 512;

    float acc[8][8];
    #pragma unroll
    for (int i = 0; i < 8; i++)
        #pragma unroll
        for (int j = 0; j < 8; j++) acc[i][j] = 0.f;

    for (int k0 = 0; k0 < 512; k0 += 8) {
        float4 av = *(const float4*)(a_row_ptr + k0 + acol);
        float4 wv = *(const float4*)(w_row_ptr + k0 + acol);
        As[acol+0][arow] = av.x; As[acol+1][arow] = av.y;
        As[acol+2][arow] = av.z; As[acol+3][arow] = av.w;
        Bs[acol+0][arow] = wv.x; Bs[acol+1][arow] = wv.y;
        Bs[acol+2][arow] = wv.z; Bs[acol+3][arow] = wv.w;
        __syncthreads();
        #pragma unroll
        for (int k = 0; k < 8; k++) {
            float af[8], bf[8];
            *(float4*)&af[0] = *(const float4*)&As[k][ty*8];
            *(float4*)&af[4] = *(const float4*)&As[k][ty*8+4];
            *(float4*)&bf[0] = *(const float4*)&Bs[k][tx*8];
            *(float4*)&bf[4] = *(const float4*)&Bs[k][tx*8+4];
            #pragma unroll
            for (int i = 0; i < 8; i++)
                #pragma unroll
                for (int j = 0; j < 8; j++)
                    acc[i][j] += af[i] * bf[j];
        }
        __syncthreads();
    }
    #pragma unroll
    for (int i = 0; i < 8; i++) {
        int mm = bm + ty*8 + i;
        float* cptr = C + (size_t)mm * 512 + bn + tx*8;
        #pragma unroll
        for (int j = 0; j < 8; j += 4) {
            float4 v;
            v.x = acc[i][j+0] + bias[bn + tx*8 + j+0];
            v.y = acc[i][j+1] + bias[bn + tx*8 + j+1];
            v.z = acc[i][j+2] + bias[bn + tx*8 + j+2];
            v.w = acc[i][j+3] + bias[bn + tx*8 + j+3];
            *(float4*)(cptr + j) = v;
        }
    }
}

// ---------------- MMA helpers ----------------
__device__ __forceinline__ void hmma_tf32(float& c0, float& c1, float& c2, float& c3,
                                          uint32_t a0, uint32_t a1, uint32_t a2, uint32_t a3,
                                          uint32_t b0, uint32_t b1) {
    asm volatile("mma.sync.aligned.m16n8k8.row.col.f32.tf32.tf32.f32 "
                 "{%0,%1,%2,%3}, {%4,%5,%6,%7}, {%8,%9}, {%0,%1,%2,%3};"
                 : "+f"(c0), "+f"(c1), "+f"(c2), "+f"(c3)
                 : "r"(a0), "r"(a1), "r"(a2), "r"(a3), "r"(b0), "r"(b1));
}
__device__ __forceinline__ void hmma_fp16(float& c0, float& c1, float& c2, float& c3,
                                          uint32_t a0, uint32_t a1, uint32_t a2, uint32_t a3,
                                          uint32_t b0, uint32_t b1) {
    asm volatile("mma.sync.aligned.m16n8k16.row.col.f32.f16.f16.f32 "
                 "{%0,%1,%2,%3}, {%4,%5,%6,%7}, {%8,%9}, {%0,%1,%2,%3};"
                 : "+f"(c0), "+f"(c1), "+f"(c2), "+f"(c3)
                 : "r"(a0), "r"(a1), "r"(a2), "r"(a3), "r"(b0), "r"(b1));
}

// ---------------- keys via mma.sync tf32 ----------------
#define KPAD   36
#define K_ASZ  (128*KPAD)
#define K_BSZ  (256*KPAD)
#define K_SMEMB ((2*K_ASZ + 2*K_BSZ)*4)

__global__ void __launch_bounds__(256, 1) keys_mma(
    const float* __restrict__ A, const float* __restrict__ Bw,
    const float* __restrict__ bias, float* __restrict__ C)
{
    extern __shared__ float smf[];
    float* As = smf;
    float* Bs = smf + 2*K_ASZ;

    const int tid  = threadIdx.x;
    const int lane = tid & 31, wid = tid >> 5;
    const int wm = (wid >> 2) * 64;
    const int wn = (wid & 3)  * 64;
    const int grp = lane >> 2;
    const int tig = lane & 3;
    const int bn = blockIdx.x * 256;
    const int bm = blockIdx.y * 128;

    const float* Ab = A  + (size_t)bm * 512;
    const float* Bb = Bw + (size_t)bn * 512;

    const int lrowA = tid >> 3;
    const int lc4   = (tid & 7) * 4;

    float acc[4][8][4];
    #pragma unroll
    for (int i = 0; i < 4; i++)
        #pragma unroll
        for (int j = 0; j < 8; j++)
            #pragma unroll
            for (int k = 0; k < 4; k++) acc[i][j][k] = 0.f;

    float4 ra[4], rb[8];
    #pragma unroll
    for (int p = 0; p < 4; p++)
        ra[p] = *(const float4*)(Ab + (size_t)(p*32 + lrowA) * 512 + lc4);
    #pragma unroll
    for (int p = 0; p < 8; p++)
        rb[p] = *(const float4*)(Bb + (size_t)(p*32 + lrowA) * 512 + lc4);
    #pragma unroll
    for (int p = 0; p < 4; p++)
        *(float4*)(As + (p*32 + lrowA)*KPAD + lc4) = ra[p];
    #pragma unroll
    for (int p = 0; p < 8; p++)
        *(float4*)(Bs + (p*32 + lrowA)*KPAD + lc4) = rb[p];
    __syncthreads();

    #pragma unroll 1
    for (int kt = 0; kt < 16; kt++) {
        const int buf = kt & 1;
        const float* Asb = As + buf * K_ASZ;
        const float* Bsb = Bs + buf * K_BSZ;

        if (kt < 15) {
            const float* Aq = Ab + (kt+1)*32;
            const float* Bq = Bb + (kt+1)*32;
            #pragma unroll
            for (int p = 0; p < 4; p++)
                ra[p] = *(const float4*)(Aq + (size_t)(p*32 + lrowA) * 512 + lc4);
            #pragma unroll
            for (int p = 0; p < 8; p++)
                rb[p] = *(const float4*)(Bq + (size_t)(p*32 + lrowA) * 512 + lc4);
        }

        #pragma unroll
        for (int k8 = 0; k8 < 4; k8++) {
            const int kc = k8*8 + tig;
            uint32_t af[4][4];
            #pragma unroll
            for (int mi = 0; mi < 4; mi++) {
                const float* ar = Asb + (wm + mi*16 + grp)*KPAD;
                af[mi][0] = __float_as_uint(ar[kc]);
                af[mi][1] = __float_as_uint(ar[8*KPAD + kc]);
                af[mi][2] = __float_as_uint(ar[kc + 4]);
                af[mi][3] = __float_as_uint(ar[8*KPAD + kc + 4]);
            }
            #pragma unroll
            for (int nj = 0; nj < 8; nj++) {
                const float* br = Bsb + (wn + nj*8 + grp)*KPAD + k8*8;
                uint32_t b0 = __float_as_uint(br[tig]);
                uint32_t b1 = __float_as_uint(br[tig + 4]);
                #pragma unroll
                for (int mi = 0; mi < 4; mi++)
                    hmma_tf32(acc[mi][nj][0], acc[mi][nj][1], acc[mi][nj][2], acc[mi][nj][3],
                              af[mi][0], af[mi][1], af[mi][2], af[mi][3], b0, b1);
            }
        }

        if (kt < 15) {
            float* Asn = As + (buf ^ 1) * K_ASZ;
            float* Bsn = Bs + (buf ^ 1) * K_BSZ;
            #pragma unroll
            for (int p = 0; p < 4; p++)
                *(float4*)(Asn + (p*32 + lrowA)*KPAD + lc4) = ra[p];
            #pragma unroll
            for (int p = 0; p < 8; p++)
                *(float4*)(Bsn + (p*32 + lrowA)*KPAD + lc4) = rb[p];
        }
        __syncthreads();
    }

    #pragma unroll
    for (int mi = 0; mi < 4; mi++) {
        const int m = bm + wm + mi*16 + grp;
        #pragma unroll
        for (int nj = 0; nj < 8; nj++) {
            const int n = bn + wn + nj*8 + 2*tig;
            float bx = bias[n], by = bias[n + 1];
            *(float2*)(C + (size_t)m * 512 + n) =
                make_float2(acc[mi][nj][0] + bx, acc[mi][nj][1] + by);
            *(float2*)(C + (size_t)(m + 8) * 512 + n) =
                make_float2(acc[mi][nj][2] + bx, acc[mi][nj][3] + by);
        }
    }
}

// =====================================================================
// Persistent chain kernel
// =====================================================================
#define GR_SMEM ((2*5120*2 + 2*2560*2)*2)   // 61440 bytes

__device__ __forceinline__ void grid_bar() {
    __syncthreads();
    if (threadIdx.x == 0) {
        __threadfence();
        unsigned gen = *(volatile unsigned*)&g_bgen;
        if (atomicAdd(&g_bcnt, 1u) == gridDim.x - 1) {
            g_bcnt = 0;
            __threadfence();
            *(volatile unsigned*)&g_bgen = gen + 1;
        } else {
            while (*(volatile unsigned*)&g_bgen == gen) {}
        }
        __threadfence();
    }
    __syncthreads();
}

// ---- generic 128x64 linear tile: C = A[128x512] @ W^T + bias ----
__device__ void lin_tile(int nt, const float* __restrict__ A,
                         const __half* __restrict__ Wh, const __half* __restrict__ Wl,
                         const float* __restrict__ bias, float* __restrict__ Cout,
                         __half* smg)
{
    __half* AHI = smg;
    __half* ALO = AHI + 2*5120;
    __half* BHI = ALO + 2*5120;
    __half* BLO = BHI + 2*2560;

    const int tid = threadIdx.x;
    const int lane = tid & 31, wid = tid >> 5;
    const int wm = (wid & 1) * 64;
    const int wn = (wid >> 1) * 16;
    const int grp = lane >> 2, tig = lane & 3;
    const int bn = nt * 64;

    const int arow = tid >> 1;
    const int acol = (tid & 1) * 16;
    const int brow = tid >> 2;
    const int bcol = (tid & 3) * 8;

    const float*  Arow  = A + (size_t)arow * 512 + acol;
    const __half* Wrowh = Wh + (size_t)(bn + brow) * 512 + bcol;
    const __half* Wrowl = Wl + (size_t)(bn + brow) * 512 + bcol;

    float acc[4][2][4];
    #pragma unroll
    for (int i = 0; i < 4; i++)
        #pragma unroll
        for (int j = 0; j < 2; j++)
            #pragma unroll
            for (int k = 0; k < 4; k++) acc[i][j][k] = 0.f;

    float fa[16];
    uint4 wh4, wl4;

    #pragma unroll
    for (int p = 0; p < 4; p++)
        *(float4*)&fa[p*4] = __ldcg((const float4*)(Arow + p*4));
    wh4 = *(const uint4*)(Wrowh);
    wl4 = *(const uint4*)(Wrowl);

    {
        uint4 hiv0, lov0, hiv1, lov1;
        split8(&fa[0], hiv0, lov0);
        split8(&fa[8], hiv1, lov1);
        __half* ah = AHI + arow*40 + acol;
        __half* al = ALO + arow*40 + acol;
        *(uint4*)ah       = hiv0;
        *(uint4*)(ah + 8) = hiv1;
        *(uint4*)al       = lov0;
        *(uint4*)(al + 8) = lov1;
        *(uint4*)(BHI + brow*40 + bcol) = wh4;
        *(uint4*)(BLO + brow*40 + bcol) = wl4;
    }
    __syncthreads();

    #pragma unroll 1
    for (int kt = 0; kt < 16; kt++) {
        const int buf = kt & 1;
        const __half* Ah = AHI + buf*5120;
        const __half* Al = ALO + buf*5120;
        const __half* Bh = BHI + buf*2560;
        const __half* Bl = BLO + buf*2560;

        if (kt < 15) {
            #pragma unroll
            for (int p = 0; p < 4; p++)
                *(float4*)&fa[p*4] = __ldcg((const float4*)(Arow + (kt+1)*32 + p*4));
            wh4 = *(const uint4*)(Wrowh + (kt+1)*32);
            wl4 = *(const uint4*)(Wrowl + (kt+1)*32);
        }

        #pragma unroll
        for (int k16 = 0; k16 < 2; k16++) {
            const int kb = k16*16 + tig*2;
            uint32_t ah[4][4], al[4][4];
            #pragma unroll
            for (int mi = 0; mi < 4; mi++) {
                const __half* arh = Ah + (wm + mi*16 + grp)*40;
                const __half* arl = Al + (wm + mi*16 + grp)*40;
                ah[mi][0] = *(const uint32_t*)(arh + kb);
                ah[mi][1] = *(const uint32_t*)(arh + 8*40 + kb);
                ah[mi][2] = *(const uint32_t*)(arh + kb + 8);
                ah[mi][3] = *(const uint32_t*)(arh + 8*40 + kb + 8);
                al[mi][0] = *(const uint32_t*)(arl + kb);
                al[mi][1] = *(const uint32_t*)(arl + 8*40 + kb);
                al[mi][2] = *(const uint32_t*)(arl + kb + 8);
                al[mi][3] = *(const uint32_t*)(arl + 8*40 + kb + 8);
            }
            #pragma unroll
            for (int nj = 0; nj < 2; nj++) {
                const __half* brh = Bh + (wn + nj*8 + grp)*40 + kb;
                const __half* brl = Bl + (wn + nj*8 + grp)*40 + kb;
                uint32_t b0h = *(const uint32_t*)(brh);
                uint32_t b1h = *(const uint32_t*)(brh + 8);
                uint32_t b0l = *(const uint32_t*)(brl);
                uint32_t b1l = *(const uint32_t*)(brl + 8);
                #pragma unroll
                for (int mi = 0; mi < 4; mi++) {
                    hmma_fp16(acc[mi][nj][0], acc[mi][nj][1], acc[mi][nj][2], acc[mi][nj][3],
                              ah[mi][0], ah[mi][1], ah[mi][2], ah[mi][3], b0h, b1h);
                    hmma_fp16(acc[mi][nj][0], acc[mi][nj][1], acc[mi][nj][2], acc[mi][nj][3],
                              ah[mi][0], ah[mi][1], ah[mi][2], ah[mi][3], b0l, b1l);
                    hmma_fp16(acc[mi][nj][0], acc[mi][nj][1], acc[mi][nj][2], acc[mi][nj][3],
                              al[mi][0], al[mi][1], al[mi][2], al[mi][3], b0h, b1h);
                }
            }
        }

        if (kt < 15) {
            const int nb = buf ^ 1;
            uint4 hiv0, lov0, hiv1, lov1;
            split8(&fa[0], hiv0, lov0);
            split8(&fa[8], hiv1, lov1);
            __half* ah = AHI + nb*5120 + arow*40 + acol;
            __half* al = ALO + nb*5120 + arow*40 + acol;
            *(uint4*)ah       = hiv0;
            *(uint4*)(ah + 8) = hiv1;
            *(uint4*)al       = lov0;
            *(uint4*)(al + 8) = lov1;
            *(uint4*)(BHI + nb*2560 + brow*40 + bcol) = wh4;
            *(uint4*)(BLO + nb*2560 + brow*40 + bcol) = wl4;
        }
        __syncthreads();
    }

    // epilogue: bias + direct write
    #pragma unroll
    for (int mi = 0; mi < 4; mi++) {
        #pragma unroll
        for (int nj = 0; nj < 2; nj++) {
            int m = wm + mi*16 + grp;
            int nc = wn + nj*8 + tig*2;
            float bx = bias[bn + nc], by = bias[bn + nc + 1];
            *(float2*)(Cout + (size_t)m*512 + bn + nc) =
                make_float2(acc[mi][nj][0] + bx, acc[mi][nj][1] + by);
            *(float2*)(Cout + (size_t)(m+8)*512 + bn + nc) =
                make_float2(acc[mi][nj][2] + bx, acc[mi][nj][3] + by);
        }
    }
    __syncthreads();
}

// ---- softmax + context body (one batch element) ----
__device__ void att_soft(int b, const float* __restrict__ q,
                         const float* __restrict__ keys, const float* __restrict__ features,
                         const float* __restrict__ v_w, const float* __restrict__ v_b,
                         float* __restrict__ ctx_out, float* sm)
{
    const int tid = threadIdx.x;
    float* qs = sm;
    float* vw = sm + 512;
    float* e  = sm + 1024;

    for (int i = tid; i < 512; i += 256) {
        qs[i] = __ldcg(q + b*512 + i);
        vw[i] = v_w[i];
    }
    __syncthreads();

    const int warp = tid >> 5, lane = tid & 31;
    for (int s = warp; s < SEQ; s += 8) {
        const float* kp = keys + ((size_t)b * SEQ + s) * 512;
        float acc = 0.f;
        #pragma unroll
        for (int k = lane; k < 512; k += 32)
            acc += tanhf(qs[k] + kp[k]) * vw[k];
        #pragma unroll
        for (int o = 16; o; o >>= 1) acc += __shfl_xor_sync(0xffffffffu, acc, o);
        if (!lane) e[s] = acc + v_b[0];
    }
    __syncthreads();

    if (warp == 0) {
        float v1 = (lane < SEQ) ? e[lane] : -1e30f;
        float v2 = (lane + 32 < SEQ) ? e[lane + 32] : -1e30f;
        float m = fmaxf(v1, v2);
        #pragma unroll
        for (int o = 16; o; o >>= 1) m = fmaxf(m, __shfl_xor_sync(0xffffffffu, m, o));
        float e1 = (lane < SEQ) ? expf(v1 - m) : 0.f;
        float e2 = (lane + 32 < SEQ) ? expf(v2 - m) : 0.f;
        float s = e1 + e2;
        #pragma unroll
        for (int o = 16; o; o >>= 1) s += __shfl_xor_sync(0xffffffffu, s, o);
        float inv = 1.f / s;
        if (lane < SEQ) e[lane] = e1 * inv;
        if (lane + 32 < SEQ) e[lane + 32] = e2 * inv;
    }
    __syncthreads();

    for (int k = tid; k < 512; k += 256) {
        float acc = 0.f;
        const float* f = features + (size_t)b * SEQ * 512 + k;
        #pragma unroll 7
        for (int s = 0; s < SEQ; s++) acc += e[s] * f[(size_t)s * 512];
        ctx_out[b*512 + k] = acc;
    }
    __syncthreads();
}

// ---- GRU tile body (unchanged from round 6) ----
template<int NK>
__device__ void gru_tile(int nt, int kc,
    const float* __restrict__ srcA, int ldA,
    const float* __restrict__ srcB, const float* __restrict__ srcC,
    const __half* __restrict__ Wh, const __half* __restrict__ Wl, int ldK,
    const float* __restrict__ bih, const float* __restrict__ bhh,
    const float* __restrict__ h_old, float* __restrict__ h_new,
    __half* __restrict__ hs_out, __half* smg)
{
    __half* AHI = smg;
    __half* ALO = AHI + 2*5120;
    __half* BHI = ALO + 2*5120;
    __half* BLO = BHI + 2*2560;

    const int tid = threadIdx.x;
    const int lane = tid & 31, wid = tid >> 5;
    const int wm = (wid & 1) * 64;
    const int wn = (wid >> 1) * 16;
    const int grp = lane >> 2, tig = lane & 3;
    const int bn = nt * 64;

    const float* src; int ld;
    {
        int sel = kc >> 1;
        if (sel == 0)      { src = srcA; ld = ldA; }
        else if (sel == 1) { src = srcB; ld = 512; }
        else               { src = srcC; ld = 512; }
    }
    const int koff = (kc & 1) * 256;

    const int arow = tid >> 1;
    const int acol = (tid & 1) * 16;
    const int brow = tid >> 2;
    const int bcol = (tid & 3) * 8;

    const float*  Arow  = src + (size_t)arow * ld + koff + acol;
    const __half* Wrowh = Wh + (size_t)(bn + brow) * ldK + kc*256 + bcol;
    const __half* Wrowl = Wl + (size_t)(bn + brow) * ldK + kc*256 + bcol;

    float acc[4][2][4];
    #pragma unroll
    for (int i = 0; i < 4; i++)
        #pragma unroll
        for (int j = 0; j < 2; j++)
            #pragma unroll
            for (int k = 0; k < 4; k++) acc[i][j][k] = 0.f;

    float fa[16];
    uint4 wh4, wl4;

    #pragma unroll
    for (int p = 0; p < 4; p++)
        *(float4*)&fa[p*4] = __ldcg((const float4*)(Arow + p*4));
    wh4 = *(const uint4*)(Wrowh);
    wl4 = *(const uint4*)(Wrowl);

    {
        uint4 hiv0, lov0, hiv1, lov1;
        split8(&fa[0], hiv0, lov0);
        split8(&fa[8], hiv1, lov1);
        __half* ah = AHI + arow*40 + acol;
        __half* al = ALO + arow*40 + acol;
        *(uint4*)ah       = hiv0;
        *(uint4*)(ah + 8) = hiv1;
        *(uint4*)al       = lov0;
        *(uint4*)(al + 8) = lov1;
        *(uint4*)(BHI + brow*40 + bcol) = wh4;
        *(uint4*)(BLO + brow*40 + bcol) = wl4;
    }
    __syncthreads();

    #pragma unroll 1
    for (int kt = 0; kt < 8; kt++) {
        const int buf = kt & 1;
        const __half* Ah = AHI + buf*5120;
        const __half* Al = ALO + buf*5120;
        const __half* Bh = BHI + buf*2560;
        const __half* Bl = BLO + buf*2560;

        if (kt < 7) {
            #pragma unroll
            for (int p = 0; p < 4; p++)
                *(float4*)&fa[p*4] = __ldcg((const float4*)(Arow + (kt+1)*32 + p*4));
            wh4 = *(const uint4*)(Wrowh + (kt+1)*32);
            wl4 = *(const uint4*)(Wrowl + (kt+1)*32);
        }

        #pragma unroll
        for (int k16 = 0; k16 < 2; k16++) {
            const int kb = k16*16 + tig*2;
            uint32_t ah[4][4], al[4][4];
            #pragma unroll
            for (int mi = 0; mi < 4; mi++) {
                const __half* arh = Ah + (wm + mi*16 + grp)*40;
                const __half* arl = Al + (wm + mi*16 + grp)*40;
                ah[mi][0] = *(const uint32_t*)(arh + kb);
                ah[mi][1] = *(const uint32_t*)(arh + 8*40 + kb);
                ah[mi][2] = *(const uint32_t*)(arh + kb + 8);
                ah[mi][3] = *(const uint32_t*)(arh + 8*40 + kb + 8);
                al[mi][0] = *(const uint32_t*)(arl + kb);
                al[mi][1] = *(const uint32_t*)(arl + 8*40 + kb);
                al[mi][2] = *(const uint32_t*)(arl + kb + 8);
                al[mi][3] = *(const uint32_t*)(arl + 8*40 + kb + 8);
            }
            #pragma unroll
            for (int nj = 0; nj < 2; nj++) {
                const __half* brh = Bh + (wn + nj*8 + grp)*40 + kb;
                const __half* brl = Bl + (wn + nj*8 + grp)*40 + kb;
                uint32_t b0h = *(const uint32_t*)(brh);
                uint32_t b1h = *(const uint32_t*)(brh + 8);
                uint32_t b0l = *(const uint32_t*)(brl);
                uint32_t b1l = *(const uint32_t*)(brl + 8);
                #pragma unroll
                for (int mi = 0; mi < 4; mi++) {
                    hmma_fp16(acc[mi][nj][0], acc[mi][nj][1], acc[mi][nj][2], acc[mi][nj][3],
                              ah[mi][0], ah[mi][1], ah[mi][2], ah[mi][3], b0h, b1h);
                    hmma_fp16(acc[mi][nj][0], acc[mi][nj][1], acc[mi][nj][2], acc[mi][nj][3],
                              ah[mi][0], ah[mi][1], ah[mi][2], ah[mi][3], b0l, b1l);
                    hmma_fp16(acc[mi][nj][0], acc[mi][nj][1], acc[mi][nj][2], acc[mi][nj][3],
                              al[mi][0], al[mi][1], al[mi][2], al[mi][3], b0h, b1h);
                }
            }
        }

        if (kt < 7) {
            const int nb = buf ^ 1;
            uint4 hiv0, lov0, hiv1, lov1;
            split8(&fa[0], hiv0, lov0);
            split8(&fa[8], hiv1, lov1);
            __half* ah = AHI + nb*5120 + arow*40 + acol;
            __half* al = ALO + nb*5120 + arow*40 + acol;
            *(uint4*)ah       = hiv0;
            *(uint4*)(ah + 8) = hiv1;
            *(uint4*)al       = lov0;
            *(uint4*)(al + 8) = lov1;
            *(uint4*)(BHI + nb*2560 + brow*40 + bcol) = wh4;
            *(uint4*)(BLO + nb*2560 + brow*40 + bcol) = wl4;
        }
        __syncthreads();
    }

    {
        float* P = g_part + ((size_t)(kc*24 + nt)) * 8192;
        #pragma unroll
        for (int mi = 0; mi < 4; mi++) {
            #pragma unroll
            for (int nj = 0; nj < 2; nj++) {
                int m = wm + mi*16 + grp;
                int nc = wn + nj*8 + tig*2;
                *(float2*)(P + m*64 + nc)     = make_float2(acc[mi][nj][0], acc[mi][nj][1]);
                *(float2*)(P + (m+8)*64 + nc) = make_float2(acc[mi][nj][2], acc[mi][nj][3]);
            }
        }
    }

    __threadfence();
    __shared__ int sdone;
    if (tid == 0) {
        int g = nt & 7;
        int v = atomicAdd(&g_cnt[g], 1);
        int done = (v == 3*NK - 1);
        if (done) g_cnt[g] = 0;
        sdone = done;
    }
    __syncthreads();
    if (!sdone) return;
    __threadfence();

    const int g = nt & 7;
    const int cc = (tid & 15) * 4;
    const int c  = g*64 + cc;
    float4 bir = *(const float4*)(bih + c);
    float4 biz = *(const float4*)(bih + 512 + c);
    float4 bin = *(const float4*)(bih + 1024 + c);
    float4 bhr = *(const float4*)(bhh + c);
    float4 bhz = *(const float4*)(bhh + 512 + c);
    float4 bhn = *(const float4*)(bhh + 1024 + c);

    #pragma unroll
    for (int i = 0; i < 8; i++) {
        const int m = (tid >> 4) * 8 + i;
        float4 r4 = make_float4(0,0,0,0), z4 = r4, in4 = r4, hn4 = r4;
        #pragma unroll
        for (int kx = 0; kx < NK; kx++) {
            const float* Pr = g_part + ((size_t)(kx*24 + g))      * 8192 + m*64 + cc;
            const float* Pz = g_part + ((size_t)(kx*24 + 8 + g))  * 8192 + m*64 + cc;
            const float* Pn = g_part + ((size_t)(kx*24 + 16 + g)) * 8192 + m*64 + cc;
            float4 a = __ldcg((const float4*)Pr);
            r4.x += a.x; r4.y += a.y; r4.z += a.z; r4.w += a.w;
            a = __ldcg((const float4*)Pz);
            z4.x += a.x; z4.y += a.y; z4.z += a.z; z4.w += a.w;
            a = __ldcg((const float4*)Pn);
            if (kx < NK-2) { in4.x += a.x; in4.y += a.y; in4.z += a.z; in4.w += a.w; }
            else           { hn4.x += a.x; hn4.y += a.y; hn4.z += a.z; hn4.w += a.w; }
        }
        float4 ho = __ldcg((const float4*)(h_old + (size_t)m*512 + c));
        float hv[4];
        #pragma unroll
        for (int q = 0; q < 4; q++) {
            float rp = ((float*)&r4)[q] + ((float*)&bir)[q] + ((float*)&bhr)[q];
            float zp = ((float*)&z4)[q] + ((float*)&biz)[q] + ((float*)&bhz)[q];
            float ip = ((float*)&in4)[q] + ((float*)&bin)[q];
            float hp = ((float*)&hn4)[q] + ((float*)&bhn)[q];
            float r = 1.f / (1.f + expf(-rp));
            float z = 1.f / (1.f + expf(-zp));
            float n = tanhf(ip + r * hp);
            hv[q] = (1.f - z) * n + z * ((float*)&ho)[q];
        }
        *(float4*)(h_new + (size_t)m*512 + c) = make_float4(hv[0], hv[1], hv[2], hv[3]);
        if (hs_out) {
            __half2 o0 = __floats2half2_rn(hv[0], hv[1]);
            __half2 o1 = __floats2half2_rn(hv[2], hv[3]);
            uint2 ov; ov.x = *(uint32_t*)&o0; ov.y = *(uint32_t*)&o1;
            *(uint2*)(hs_out + (size_t)m*512 + c) = ov;
        }
    }
}

// ---- persistent chain kernel ----
__global__ void __launch_bounds__(256, 1) chain_kernel(
    const float* __restrict__ features,
    const float* __restrict__ bq,
    const float* __restrict__ v_w, const float* __restrict__ v_b,
    const float* __restrict__ fc0_b,
    const float* __restrict__ bih0, const float* __restrict__ bhh0,
    const float* __restrict__ bihr, const float* __restrict__ bhhr)
{
    extern __shared__ __half smg[];
    float* smf = (float*)smg;

    for (int t = 0; t < NSTEP; t++) {
        const float* hold = g_h + (t & 1) * (4 * BH);
        float*       hnew = g_h + ((t & 1) ^ 1) * (4 * BH);

        // Q phase: q = h3 @ wq^T + bq  (8 tensor tiles, weights read once)
        for (int w = blockIdx.x; w < 8; w += gridDim.x)
            lin_tile(w, hold + 3*BH, g_lwh, g_lwl, bq, g_q, smg);
        grid_bar();

        // S phase: softmax + context
        for (int b = blockIdx.x; b < BATCH; b += gridDim.x)
            att_soft(b, g_q, g_keys, features, v_w, v_b, g_context, smf);
        grid_bar();

        // F phase: ctx = context @ fc0^T + fc0_b
        for (int w = blockIdx.x; w < 8; w += gridDim.x)
            lin_tile(w, g_context, g_lwh + (size_t)HID*HID, g_lwl + (size_t)HID*HID,
                     fc0_b, g_ctx, smg);
        grid_bar();

        // L0
        for (int w = blockIdx.x; w < 144; w += gridDim.x)
            gru_tile<6>(w % 24, w / 24,
                        g_x + t*HID, NSTEP*HID, g_ctx, hold,
                        g_wh, g_wl, 1536, bih0, bhh0, hold, hnew, nullptr, smg);
        grid_bar();

        // L1..L3
        for (int l = 1; l < 4; l++) {
            const size_t off = (size_t)1536*1536 + (size_t)(l-1)*1536*1024;
            __half* hs_out = (l == 3) ? (g_hsh + t * BH) : nullptr;
            for (int w = blockIdx.x; w < 96; w += gridDim.x)
                gru_tile<4>(w % 24, w / 24,
                            hnew + (l-1)*BH, 512, hold + l*BH, nullptr,
                            g_wh + off, g_wl + off, 1024,
                            bihr + (l-1)*1536, bhhr + (l-1)*1536,
                            hold + l*BH, hnew + l*BH, hs_out, smg);
            grid_bar();
        }
    }
}

// ---------------- fc2 via mma.sync fp16 ----------------
#define F2_PAD  40
#define F2_ASZ  (128*F2_PAD)
#define F2_BSZ  (256*F2_PAD)
#define F2_SMEM ((2*F2_ASZ + 2*F2_BSZ)*2)

__global__ void __launch_bounds__(256, 1) fc2_mma_fp16(
    const __half* __restrict__ A, const __half* __restrict__ Bw,
    const float* __restrict__ bias, float* __restrict__ out)
{
    extern __shared__ __half smh[];
    __half* As = smh;
    __half* Bs = smh + 2*F2_ASZ;

    const int tid  = threadIdx.x;
    const int lane = tid & 31, wid = tid >> 5;
    const int wm = (wid >> 2) * 64;
    const int wn = (wid & 3)  * 64;
    const int grp = lane >> 2;
    const int tig = lane & 3;
    const int bn = blockIdx.x * 256;
    const int t  = blockIdx.y;

    const __half* Ab = A  + (size_t)t  * 128 * 512;
    const __half* Bb = Bw + (size_t)bn * 512;

    float acc[4][8][4];
    #pragma unroll
    for (int i = 0; i < 4; i++)
        #pragma unroll
        for (int j = 0; j < 8; j++)
            #pragma unroll
            for (int k = 0; k < 4; k++) acc[i][j][k] = 0.f;

    uint4 ra[2], rb[4];
    #pragma unroll
    for (int p = 0; p < 2; p++) {
        int idx = tid + p * 256;
        int row = idx >> 2, c8 = (idx & 3) * 8;
        ra[p] = *(const uint4*)(Ab + (size_t)row * 512 + c8);
    }
    #pragma unroll
    for (int p = 0; p < 4; p++) {
        int idx = tid + p * 256;
        int row = idx >> 2, c8 = (idx & 3) * 8;
        rb[p] = *(const uint4*)(Bb + (size_t)row * 512 + c8);
    }
    #pragma unroll
    for (int p = 0; p < 2; p++) {
        int idx = tid + p * 256;
        int row = idx >> 2, c8 = (idx & 3) * 8;
        *(uint4*)(As + row*F2_PAD + c8) = ra[p];
    }
    #pragma unroll
    for (int p = 0; p < 4; p++) {
        int idx = tid + p * 256;
        int row = idx >> 2, c8 = (idx & 3) * 8;
        *(uint4*)(Bs + row*F2_PAD + c8) = rb[p];
    }
    __syncthreads();

    #pragma unroll 1
    for (int kt = 0; kt < 16; kt++) {
        const int buf = kt & 1;
        const __half* Asb = As + buf * F2_ASZ;
        const __half* Bsb = Bs + buf * F2_BSZ;

        if (kt < 15) {
            const __half* Aq = Ab + (kt+1)*32;
            const __half* Bq = Bb + (kt+1)*32;
            #pragma unroll
            for (int p = 0; p < 2; p++) {
                int idx = tid + p * 256;
                int row = idx >> 2, c8 = (idx & 3) * 8;
                ra[p] = *(const uint4*)(Aq + (size_t)row * 512 + c8);
            }
            #pragma unroll
            for (int p = 0; p < 4; p++) {
                int idx = tid + p * 256;
                int row = idx >> 2, c8 = (idx & 3) * 8;
                rb[p] = *(const uint4*)(Bq + (size_t)row * 512 + c8);
            }
        }

        #pragma unroll
        for (int k16 = 0; k16 < 2; k16++) {
            const int kb = k16*16 + tig*2;
            uint32_t af[4][4];
            #pragma unroll
            for (int mi = 0; mi < 4; mi++) {
                const __half* ar = Asb + (wm + mi*16 + grp)*F2_PAD;
                af[mi][0] = *(const uint32_t*)(ar + kb);
                af[mi][1] = *(const uint32_t*)(ar + 8*F2_PAD + kb);
                af[mi][2] = *(const uint32_t*)(ar + kb + 8);
                af[mi][3] = *(const uint32_t*)(ar + 8*F2_PAD + kb + 8);
            }
            #pragma unroll
            for (int nj = 0; nj < 8; nj++) {
                const __half* br = Bsb + (wn + nj*8 + grp)*F2_PAD + kb;
                uint32_t b0 = *(const uint32_t*)(br);
                uint32_t b1 = *(const uint32_t*)(br + 8);
                #pragma unroll
                for (int mi = 0; mi < 4; mi++)
                    hmma_fp16(acc[mi][nj][0], acc[mi][nj][1], acc[mi][nj][2], acc[mi][nj][3],
                              af[mi][0], af[mi][1], af[mi][2], af[mi][3], b0, b1);
            }
        }

        if (kt < 15) {
            __half* Asn = As + (buf ^ 1) * F2_ASZ;
            __half* Bsn = Bs + (buf ^ 1) * F2_BSZ;
            #pragma unroll
            for (int p = 0; p < 2; p++) {
                int idx = tid + p * 256;
                int row = idx >> 2, c8 = (idx & 3) * 8;
                *(uint4*)(Asn + row*F2_PAD + c8) = ra[p];
            }
            #pragma unroll
            for (int p = 0; p < 4; p++) {
                int idx = tid + p * 256;
                int row = idx >> 2, c8 = (idx & 3) * 8;
                *(uint4*)(Bsn + row*F2_PAD + c8) = rb[p];
            }
        }
        __syncthreads();
    }

    #pragma unroll
    for (int mi = 0; mi < 4; mi++) {
        const int b0 = wm + mi*16 + grp;
        float* o0 = out + ((size_t)b0       * NSTEP + t) * VOCAB + bn + wn;
        float* o8 = out + ((size_t)(b0 + 8) * NSTEP + t) * VOCAB + bn + wn;
        #pragma unroll
        for (int nj = 0; nj < 8; nj++) {
            const int n = nj*8 + 2*tig;
            float bx = bias[bn + wn + n];
            float by = bias[bn + wn + n + 1];
            *(float2*)(o0 + n) = make_float2(acc[mi][nj][0] + bx, acc[mi][nj][1] + by);
            *(float2*)(o8 + n) = make_float2(acc[mi][nj][2] + bx, acc[mi][nj][3] + by);
        }
    }
}

// ---------------- host launch ----------------
extern "C" void kernel_launch(void* const* d_in, const int* in_sizes, int n_in,
                              void* d_out, int out_size)
{
    const float* features = (const float*)d_in[0];
    const int*   caps     = (const int*)  d_in[1];
    const float* emb      = (const float*)d_in[2];
    const float* fc1_w    = (const float*)d_in[3];
    const float* fc1_b    = (const float*)d_in[4];
    const float* fc0_w    = (const float*)d_in[5];
    const float* fc0_b    = (const float*)d_in[6];
    const float* wq       = (const float*)d_in[7];
    const float* bq       = (const float*)d_in[8];
    const float* wk       = (const float*)d_in[9];
    const float* bk       = (const float*)d_in[10];
    const float* v_w      = (const float*)d_in[11];
    const float* v_b      = (const float*)d_in[12];
    const float* wih0     = (const float*)d_in[13];
    const float* whh0     = (const float*)d_in[14];
    const float* bih0     = (const float*)d_in[15];
    const float* bhh0     = (const float*)d_in[16];
    const float* wihr     = (const float*)d_in[17];
    const float* whhr     = (const float*)d_in[18];
    const float* bihr     = (const float*)d_in[19];
    const float* bhhr     = (const float*)d_in[20];
    const float* fc2_w    = (const float*)d_in[21];
    const float* fc2_b    = (const float*)d_in[22];
    float* out = (float*)d_out;

    float *px, *pkeys;
    __half *phsh, *pw2h;
    cudaGetSymbolAddress((void**)&px,    g_x);
    cudaGetSymbolAddress((void**)&pkeys, g_keys);
    cudaGetSymbolAddress((void**)&phsh,  g_hsh);
    cudaGetSymbolAddress((void**)&pw2h,  g_w2h);

    cudaFuncSetAttribute(fc2_mma_fp16, cudaFuncAttributeMaxDynamicSharedMemorySize, F2_SMEM);
    cudaFuncSetAttribute(keys_mma,     cudaFuncAttributeMaxDynamicSharedMemorySize, K_SMEMB);
    cudaFuncSetAttribute(chain_kernel, cudaFuncAttributeMaxDynamicSharedMemorySize, GR_SMEM);

    int nsm = 0;
    cudaDeviceGetAttribute(&nsm, cudaDevAttrMultiProcessorCount, 0);
    int nb = nsm;
    if (nb > 144) nb = 144;

    // launch order matters for ncu (-s 5 -c 1 profiles the 6th launch = chain_kernel)
    init_kernel<<<1024, 256>>>();                                   // 1
    cvt_w2_kernel<<<VOCAB*HID/8/256, 256>>>(fc2_w);                 // 2
    wsplit_all<<<3712, 256>>>(wih0, whh0, wihr, whhr, wq, fc0_w);   // 3
    gemm_big_gather<<<dim3(4, 15), 256>>>(emb, fc1_w, fc1_b, px, caps);  // 4
    keys_mma<<<dim3(2, 49), 256, K_SMEMB>>>(features, wk, bk, pkeys);    // 5

    chain_kernel<<<nb, 256, GR_SMEM>>>(features, bq, v_w, v_b, fc0_b,    // 6 (profiled)
                                       bih0, bhh0, bihr, bhhr);

    fc2_mma_fp16<<<dim3(VOCAB/256, NSTEP), 256, F2_SMEM>>>(phsh, pw2h, fc2_b, out);  // 7
}

// round 9
// speedup vs baseline: 1.1883x; 1.0455x over previous
#include <cuda_runtime.h>
#include <cuda_fp16.h>
#include <math.h>
#include <cstdint>

#define BATCH 128
#define SEQ   49
#define HID   512
#define VOCAB 32000
#define NSTEP 15
#define BH    (BATCH*HID)

// ---------------- device scratch ----------------
__device__ float  g_keys[BATCH*SEQ*HID];
__device__ float  g_q[BH];
__device__ float  g_h[2*4*BH];              // fp32 hidden (gate precision)
__device__ __half g_hh[2*4*BH];             // fp16 hi of hidden
__device__ __half g_hl[2*4*BH];             // fp16 lo
__device__ __half g_xh[BATCH*NSTEP*HID];    // x hi/lo
__device__ __half g_xl[BATCH*NSTEP*HID];
__device__ __half g_coh[BH], g_col[BH];     // context hi/lo
__device__ __half g_ctxh[BH], g_ctxl[BH];   // fc0(context) hi/lo
__device__ __half g_hsh[NSTEP*BH];          // fc2 A operand (fp16)
__device__ float  g_part[6*3*BH];
__device__ __half g_w2h[VOCAB*HID];
#define WG_TOT (1536*1536 + 3*1536*1024)
__device__ __half g_wh[WG_TOT];
__device__ __half g_wl[WG_TOT];
__device__ __half g_lwh[3*HID*HID];         // [wq | fc0 | fc1] hi
__device__ __half g_lwl[3*HID*HID];         // lo
__device__ int    g_cnt[8];
__device__ unsigned g_bcnt = 0;
__device__ unsigned g_bgen = 0;

// ---------------- init ----------------
__global__ void init_kernel() {
    int idx = blockIdx.x * 256 + threadIdx.x;   // < 4*BH (grid 1024)
    if (idx < 4*BH) {
        g_h[idx] = 0.f;
        g_hh[idx] = __float2half(0.f);
        g_hl[idx] = __float2half(0.f);
    }
    if (blockIdx.x == 0 && threadIdx.x < 8) g_cnt[threadIdx.x] = 0;
    if (blockIdx.x == 0 && threadIdx.x == 0) { g_bcnt = 0; }
}

// ---------------- fc2 weights -> fp16 ----------------
__global__ void cvt_w2_kernel(const float* __restrict__ w) {
    int i = blockIdx.x * 256 + threadIdx.x;
    const float4* in = (const float4*)w;
    float4 v0 = in[2*i], v1 = in[2*i + 1];
    __half2 h0 = __floats2half2_rn(v0.x, v0.y);
    __half2 h1 = __floats2half2_rn(v0.z, v0.w);
    __half2 h2 = __floats2half2_rn(v1.x, v1.y);
    __half2 h3 = __floats2half2_rn(v1.z, v1.w);
    uint4 o;
    o.x = *(uint32_t*)&h0; o.y = *(uint32_t*)&h1;
    o.z = *(uint32_t*)&h2; o.w = *(uint32_t*)&h3;
    ((uint4*)g_w2h)[i] = o;
}

// ---------------- split helpers ----------------
__device__ __forceinline__ void split8(const float* sp, uint4& hiv, uint4& lov) {
    uint32_t hi[4], lo[4];
    #pragma unroll
    for (int j = 0; j < 4; j++) {
        float a = sp[2*j], b = sp[2*j + 1];
        __half2 h2 = __floats2half2_rn(a, b);
        float2 bb = __half22float2(h2);
        __half2 l2 = __floats2half2_rn(a - bb.x, b - bb.y);
        hi[j] = *(uint32_t*)&h2; lo[j] = *(uint32_t*)&l2;
    }
    hiv = make_uint4(hi[0], hi[1], hi[2], hi[3]);
    lov = make_uint4(lo[0], lo[1], lo[2], lo[3]);
}
__device__ __forceinline__ void split2(float a, float b, uint32_t& hi, uint32_t& lo) {
    __half2 h2 = __floats2half2_rn(a, b);
    float2 bb = __half22float2(h2);
    __half2 l2 = __floats2half2_rn(a - bb.x, b - bb.y);
    hi = *(uint32_t*)&h2; lo = *(uint32_t*)&l2;
}

// ---------------- ALL weight splits in ONE kernel ----------------
// chunks: L0 294912 | L1-3 3x196608 | wq 32768 | fc0 32768 | fc1 32768
__global__ void wsplit_all(const float* __restrict__ wih0, const float* __restrict__ whh0,
                           const float* __restrict__ wihr, const float* __restrict__ whhr,
                           const float* __restrict__ wq,   const float* __restrict__ fc0_w,
                           const float* __restrict__ fc1_w) {
    int i = blockIdx.x * 256 + threadIdx.x;
    const int C0 = 294912, CL = 196608, CW = 32768;
    const float* sp;
    __half *dh, *dl;
    size_t doff;
    if (i < C0) {
        int row = i / 192, c = (i - row*192) * 8;
        sp = (c < 1024) ? (wih0 + (size_t)row*1024 + c) : (whh0 + (size_t)row*512 + (c - 1024));
        dh = g_wh; dl = g_wl; doff = (size_t)row*1536 + c;
    } else if (i < C0 + 3*CL) {
        int j = i - C0;
        int l = j / CL; j -= l*CL;
        int row = j / 128, c = (j - row*128) * 8;
        const float* wih = wihr + (size_t)l*1536*512;
        const float* whh = whhr + (size_t)l*1536*512;
        sp = (c < 512) ? (wih + (size_t)row*512 + c) : (whh + (size_t)row*512 + (c - 512));
        dh = g_wh; dl = g_wl;
        doff = (size_t)1536*1536 + (size_t)l*1536*1024 + (size_t)row*1024 + c;
    } else {
        int j = i - C0 - 3*CL;
        int seg = j / CW; j -= seg*CW;
        int row = j / 64, c = (j - row*64) * 8;
        const float* w = (seg == 0) ? wq : (seg == 1) ? fc0_w : fc1_w;
        sp = w + (size_t)row*512 + c;
        dh = g_lwh; dl = g_lwl;
        doff = (size_t)seg*HID*HID + (size_t)row*512 + c;
    }
    uint4 hiv, lov;
    split8(sp, hiv, lov);
    *(uint4*)(dh + doff) = hiv;
    *(uint4*)(dl + doff) = lov;
}

// ---------------- MMA helpers ----------------
__device__ __forceinline__ void hmma_tf32(float& c0, float& c1, float& c2, float& c3,
                                          uint32_t a0, uint32_t a1, uint32_t a2, uint32_t a3,
                                          uint32_t b0, uint32_t b1) {
    asm volatile("mma.sync.aligned.m16n8k8.row.col.f32.tf32.tf32.f32 "
                 "{%0,%1,%2,%3}, {%4,%5,%6,%7}, {%8,%9}, {%0,%1,%2,%3};"
                 : "+f"(c0), "+f"(c1), "+f"(c2), "+f"(c3)
                 : "r"(a0), "r"(a1), "r"(a2), "r"(a3), "r"(b0), "r"(b1));
}
__device__ __forceinline__ void hmma_fp16(float& c0, float& c1, float& c2, float& c3,
                                          uint32_t a0, uint32_t a1, uint32_t a2, uint32_t a3,
                                          uint32_t b0, uint32_t b1) {
    asm volatile("mma.sync.aligned.m16n8k16.row.col.f32.f16.f16.f32 "
                 "{%0,%1,%2,%3}, {%4,%5,%6,%7}, {%8,%9}, {%0,%1,%2,%3};"
                 : "+f"(c0), "+f"(c1), "+f"(c2), "+f"(c3)
                 : "r"(a0), "r"(a1), "r"(a2), "r"(a3), "r"(b0), "r"(b1));
}

// ---------------- keys via mma.sync tf32 (unchanged) ----------------
#define KPAD   36
#define K_ASZ  (128*KPAD)
#define K_BSZ  (256*KPAD)
#define K_SMEMB ((2*K_ASZ + 2*K_BSZ)*4)

__global__ void __launch_bounds__(256, 1) keys_mma(
    const float* __restrict__ A, const float* __restrict__ Bw,
    const float* __restrict__ bias, float* __restrict__ C)
{
    extern __shared__ float smf[];
    float* As = smf;
    float* Bs = smf + 2*K_ASZ;

    const int tid  = threadIdx.x;
    const int lane = tid & 31, wid = tid >> 5;
    const int wm = (wid >> 2) * 64;
    const int wn = (wid & 3)  * 64;
    const int grp = lane >> 2;
    const int tig = lane & 3;
    const int bn = blockIdx.x * 256;
    const int bm = blockIdx.y * 128;

    const float* Ab = A  + (size_t)bm * 512;
    const float* Bb = Bw + (size_t)bn * 512;

    const int lrowA = tid >> 3;
    const int lc4   = (tid & 7) * 4;

    float acc[4][8][4];
    #pragma unroll
    for (int i = 0; i < 4; i++)
        #pragma unroll
        for (int j = 0; j < 8; j++)
            #pragma unroll
            for (int k = 0; k < 4; k++) acc[i][j][k] = 0.f;

    float4 ra[4], rb[8];
    #pragma unroll
    for (int p = 0; p < 4; p++)
        ra[p] = *(const float4*)(Ab + (size_t)(p*32 + lrowA) * 512 + lc4);
    #pragma unroll
    for (int p = 0; p < 8; p++)
        rb[p] = *(const float4*)(Bb + (size_t)(p*32 + lrowA) * 512 + lc4);
    #pragma unroll
    for (int p = 0; p < 4; p++)
        *(float4*)(As + (p*32 + lrowA)*KPAD + lc4) = ra[p];
    #pragma unroll
    for (int p = 0; p < 8; p++)
        *(float4*)(Bs + (p*32 + lrowA)*KPAD + lc4) = rb[p];
    __syncthreads();

    #pragma unroll 1
    for (int kt = 0; kt < 16; kt++) {
        const int buf = kt & 1;
        const float* Asb = As + buf * K_ASZ;
        const float* Bsb = Bs + buf * K_BSZ;

        if (kt < 15) {
            const float* Aq = Ab + (kt+1)*32;
            const float* Bq = Bb + (kt+1)*32;
            #pragma unroll
            for (int p = 0; p < 4; p++)
                ra[p] = *(const float4*)(Aq + (size_t)(p*32 + lrowA) * 512 + lc4);
            #pragma unroll
            for (int p = 0; p < 8; p++)
                rb[p] = *(const float4*)(Bq + (size_t)(p*32 + lrowA) * 512 + lc4);
        }

        #pragma unroll
        for (int k8 = 0; k8 < 4; k8++) {
            const int kc = k8*8 + tig;
            uint32_t af[4][4];
            #pragma unroll
            for (int mi = 0; mi < 4; mi++) {
                const float* ar = Asb + (wm + mi*16 + grp)*KPAD;
                af[mi][0] = __float_as_uint(ar[kc]);
                af[mi][1] = __float_as_uint(ar[8*KPAD + kc]);
                af[mi][2] = __float_as_uint(ar[kc + 4]);
                af[mi][3] = __float_as_uint(ar[8*KPAD + kc + 4]);
            }
            #pragma unroll
            for (int nj = 0; nj < 8; nj++) {
                const float* br = Bsb + (wn + nj*8 + grp)*KPAD + k8*8;
                uint32_t b0 = __float_as_uint(br[tig]);
                uint32_t b1 = __float_as_uint(br[tig + 4]);
                #pragma unroll
                for (int mi = 0; mi < 4; mi++)
                    hmma_tf32(acc[mi][nj][0], acc[mi][nj][1], acc[mi][nj][2], acc[mi][nj][3],
                              af[mi][0], af[mi][1], af[mi][2], af[mi][3], b0, b1);
            }
        }

        if (kt < 15) {
            float* Asn = As + (buf ^ 1) * K_ASZ;
            float* Bsn = Bs + (buf ^ 1) * K_BSZ;
            #pragma unroll
            for (int p = 0; p < 4; p++)
                *(float4*)(Asn + (p*32 + lrowA)*KPAD + lc4) = ra[p];
            #pragma unroll
            for (int p = 0; p < 8; p++)
                *(float4*)(Bsn + (p*32 + lrowA)*KPAD + lc4) = rb[p];
        }
        __syncthreads();
    }

    #pragma unroll
    for (int mi = 0; mi < 4; mi++) {
        const int m = bm + wm + mi*16 + grp;
        #pragma unroll
        for (int nj = 0; nj < 8; nj++) {
            const int n = bn + wn + nj*8 + 2*tig;
            float bx = bias[n], by = bias[n + 1];
            *(float2*)(C + (size_t)m * 512 + n) =
                make_float2(acc[mi][nj][0] + bx, acc[mi][nj][1] + by);
            *(float2*)(C + (size_t)(m + 8) * 512 + n) =
                make_float2(acc[mi][nj][2] + bx, acc[mi][nj][3] + by);
        }
    }
}

#define GR_SMEM ((2*5120*2 + 2*2560*2)*2)   // 61440 bytes

// ---------------- x precompute: fp16-compensated, gathered A ----------------
// x[b][t] = emb[caps[b][t]] @ fc1^T + fc1_b -> g_xh/g_xl.  grid (8, 15).
__global__ void __launch_bounds__(256, 1) xgemm_mma(
    const float* __restrict__ emb, const int* __restrict__ caps,
    const float* __restrict__ bias)
{
    extern __shared__ __half smg[];
    __half* AHI = smg;
    __half* ALO = AHI + 2*5120;
    __half* BHI = ALO + 2*5120;
    __half* BLO = BHI + 2*2560;

    const int tid = threadIdx.x;
    const int lane = tid & 31, wid = tid >> 5;
    const int wm = (wid & 1) * 64;
    const int wn = (wid >> 1) * 16;
    const int grp = lane >> 2, tig = lane & 3;
    const int bn = blockIdx.x * 64;
    const int t  = blockIdx.y;

    const int arow = tid >> 1;
    const int acol = (tid & 1) * 16;
    const int brow = tid >> 2;
    const int bcol = (tid & 3) * 8;

    const float*  Arow  = emb + (size_t)caps[arow*16 + t] * 512 + acol;
    const __half* Wh = g_lwh + (size_t)2*HID*HID;
    const __half* Wl = g_lwl + (size_t)2*HID*HID;
    const __half* Wrowh = Wh + (size_t)(bn + brow) * 512 + bcol;
    const __half* Wrowl = Wl + (size_t)(bn + brow) * 512 + bcol;

    float acc[4][2][4];
    #pragma unroll
    for (int i = 0; i < 4; i++)
        #pragma unroll
        for (int j = 0; j < 2; j++)
            #pragma unroll
            for (int k = 0; k < 4; k++) acc[i][j][k] = 0.f;

    float fa[16];
    uint4 wh4, wl4;
    #pragma unroll
    for (int p = 0; p < 4; p++)
        *(float4*)&fa[p*4] = *(const float4*)(Arow + p*4);
    wh4 = *(const uint4*)(Wrowh);
    wl4 = *(const uint4*)(Wrowl);
    {
        uint4 h0, l0, h1, l1;
        split8(&fa[0], h0, l0); split8(&fa[8], h1, l1);
        __half* ah = AHI + arow*40 + acol;
        __half* al = ALO + arow*40 + acol;
        *(uint4*)ah = h0; *(uint4*)(ah+8) = h1;
        *(uint4*)al = l0; *(uint4*)(al+8) = l1;
        *(uint4*)(BHI + brow*40 + bcol) = wh4;
        *(uint4*)(BLO + brow*40 + bcol) = wl4;
    }
    __syncthreads();

    #pragma unroll 1
    for (int kt = 0; kt < 16; kt++) {
        const int buf = kt & 1;
        const __half* Ah = AHI + buf*5120;
        const __half* Al = ALO + buf*5120;
        const __half* Bh = BHI + buf*2560;
        const __half* Bl = BLO + buf*2560;

        if (kt < 15) {
            #pragma unroll
            for (int p = 0; p < 4; p++)
                *(float4*)&fa[p*4] = *(const float4*)(Arow + (kt+1)*32 + p*4);
            wh4 = *(const uint4*)(Wrowh + (kt+1)*32);
            wl4 = *(const uint4*)(Wrowl + (kt+1)*32);
        }

        #pragma unroll
        for (int k16 = 0; k16 < 2; k16++) {
            const int kb = k16*16 + tig*2;
            uint32_t ah[4][4], al[4][4];
            #pragma unroll
            for (int mi = 0; mi < 4; mi++) {
                const __half* arh = Ah + (wm + mi*16 + grp)*40;
                const __half* arl = Al + (wm + mi*16 + grp)*40;
                ah[mi][0] = *(const uint32_t*)(arh + kb);
                ah[mi][1] = *(const uint32_t*)(arh + 8*40 + kb);
                ah[mi][2] = *(const uint32_t*)(arh + kb + 8);
                ah[mi][3] = *(const uint32_t*)(arh + 8*40 + kb + 8);
                al[mi][0] = *(const uint32_t*)(arl + kb);
                al[mi][1] = *(const uint32_t*)(arl + 8*40 + kb);
                al[mi][2] = *(const uint32_t*)(arl + kb + 8);
                al[mi][3] = *(const uint32_t*)(arl + 8*40 + kb + 8);
            }
            #pragma unroll
            for (int nj = 0; nj < 2; nj++) {
                const __half* brh = Bh + (wn + nj*8 + grp)*40 + kb;
                const __half* brl = Bl + (wn + nj*8 + grp)*40 + kb;
                uint32_t b0h = *(const uint32_t*)(brh);
                uint32_t b1h = *(const uint32_t*)(brh + 8);
                uint32_t b0l = *(const uint32_t*)(brl);
                uint32_t b1l = *(const uint32_t*)(brl + 8);
                #pragma unroll
                for (int mi = 0; mi < 4; mi++) {
                    hmma_fp16(acc[mi][nj][0], acc[mi][nj][1], acc[mi][nj][2], acc[mi][nj][3],
                              ah[mi][0], ah[mi][1], ah[mi][2], ah[mi][3], b0h, b1h);
                    hmma_fp16(acc[mi][nj][0], acc[mi][nj][1], acc[mi][nj][2], acc[mi][nj][3],
                              ah[mi][0], ah[mi][1], ah[mi][2], ah[mi][3], b0l, b1l);
                    hmma_fp16(acc[mi][nj][0], acc[mi][nj][1], acc[mi][nj][2], acc[mi][nj][3],
                              al[mi][0], al[mi][1], al[mi][2], al[mi][3], b0h, b1h);
                }
            }
        }

        if (kt < 15) {
            const int nb = buf ^ 1;
            uint4 h0, l0, h1, l1;
            split8(&fa[0], h0, l0); split8(&fa[8], h1, l1);
            __half* ah = AHI + nb*5120 + arow*40 + acol;
            __half* al = ALO + nb*5120 + arow*40 + acol;
            *(uint4*)ah = h0; *(uint4*)(ah+8) = h1;
            *(uint4*)al = l0; *(uint4*)(al+8) = l1;
            *(uint4*)(BHI + nb*2560 + brow*40 + bcol) = wh4;
            *(uint4*)(BLO + nb*2560 + brow*40 + bcol) = wl4;
        }
        __syncthreads();
    }

    #pragma unroll
    for (int mi = 0; mi < 4; mi++) {
        #pragma unroll
        for (int nj = 0; nj < 2; nj++) {
            int m = wm + mi*16 + grp;
            int nc = wn + nj*8 + tig*2;
            float bx = bias[bn + nc], by = bias[bn + nc + 1];
            uint32_t hi0, lo0, hi1, lo1;
            split2(acc[mi][nj][0] + bx, acc[mi][nj][1] + by, hi0, lo0);
            split2(acc[mi][nj][2] + bx, acc[mi][nj][3] + by, hi1, lo1);
            size_t o0 = (size_t)m * (NSTEP*HID) + (size_t)t*HID + bn + nc;
            size_t o8 = (size_t)(m+8) * (NSTEP*HID) + (size_t)t*HID + bn + nc;
            *(uint32_t*)(g_xh + o0) = hi0;
            *(uint32_t*)(g_xl + o0) = lo0;
            *(uint32_t*)(g_xh + o8) = hi1;
            *(uint32_t*)(g_xl + o8) = lo1;
        }
    }
}

// =====================================================================
// Persistent chain kernel
// =====================================================================
__device__ __forceinline__ void grid_bar() {
    __syncthreads();
    if (threadIdx.x == 0) {
        __threadfence();
        unsigned gen = *(volatile unsigned*)&g_bgen;
        if (atomicAdd(&g_bcnt, 1u) == gridDim.x - 1) {
            g_bcnt = 0;
            __threadfence();
            *(volatile unsigned*)&g_bgen = gen + 1;
        } else {
            while (*(volatile unsigned*)&g_bgen == gen) {}
        }
        __threadfence();
    }
    __syncthreads();
}

// ---- linear tile: C = A(fp16 hi/lo)[128x512] @ W^T + bias; OUT 0=fp32, 1=hi/lo ----
template<int OUT>
__device__ void lin_tile(int nt,
                         const __half* __restrict__ Ahg, const __half* __restrict__ Alg,
                         const __half* __restrict__ Wh, const __half* __restrict__ Wl,
                         const float* __restrict__ bias,
                         float* __restrict__ Cout, __half* __restrict__ Ch,
                         __half* __restrict__ Cl, __half* smg)
{
    __half* AHI = smg;
    __half* ALO = AHI + 2*5120;
    __half* BHI = ALO + 2*5120;
    __half* BLO = BHI + 2*2560;

    const int tid = threadIdx.x;
    const int lane = tid & 31, wid = tid >> 5;
    const int wm = (wid & 1) * 64;
    const int wn = (wid >> 1) * 16;
    const int grp = lane >> 2, tig = lane & 3;
    const int bn = nt * 64;

    const int arow = tid >> 1;
    const int acol = (tid & 1) * 16;
    const int brow = tid >> 2;
    const int bcol = (tid & 3) * 8;

    const __half* Arh = Ahg + (size_t)arow * 512 + acol;
    const __half* Arl = Alg + (size_t)arow * 512 + acol;
    const __half* Wrowh = Wh + (size_t)(bn + brow) * 512 + bcol;
    const __half* Wrowl = Wl + (size_t)(bn + brow) * 512 + bcol;

    float acc[4][2][4];
    #pragma unroll
    for (int i = 0; i < 4; i++)
        #pragma unroll
        for (int j = 0; j < 2; j++)
            #pragma unroll
            for (int k = 0; k < 4; k++) acc[i][j][k] = 0.f;

    uint4 a_h0, a_h1, a_l0, a_l1, wh4, wl4;
    a_h0 = __ldcg((const uint4*)(Arh));
    a_h1 = __ldcg((const uint4*)(Arh + 8));
    a_l0 = __ldcg((const uint4*)(Arl));
    a_l1 = __ldcg((const uint4*)(Arl + 8));
    wh4 = *(const uint4*)(Wrowh);
    wl4 = *(const uint4*)(Wrowl);
    {
        __half* ah = AHI + arow*40 + acol;
        __half* al = ALO + arow*40 + acol;
        *(uint4*)ah = a_h0; *(uint4*)(ah+8) = a_h1;
        *(uint4*)al = a_l0; *(uint4*)(al+8) = a_l1;
        *(uint4*)(BHI + brow*40 + bcol) = wh4;
        *(uint4*)(BLO + brow*40 + bcol) = wl4;
    }
    __syncthreads();

    #pragma unroll 1
    for (int kt = 0; kt < 16; kt++) {
        const int buf = kt & 1;
        const __half* Ah = AHI + buf*5120;
        const __half* Al = ALO + buf*5120;
        const __half* Bh = BHI + buf*2560;
        const __half* Bl = BLO + buf*2560;

        if (kt < 15) {
            a_h0 = __ldcg((const uint4*)(Arh + (kt+1)*32));
            a_h1 = __ldcg((const uint4*)(Arh + (kt+1)*32 + 8));
            a_l0 = __ldcg((const uint4*)(Arl + (kt+1)*32));
            a_l1 = __ldcg((const uint4*)(Arl + (kt+1)*32 + 8));
            wh4 = *(const uint4*)(Wrowh + (kt+1)*32);
            wl4 = *(const uint4*)(Wrowl + (kt+1)*32);
        }

        #pragma unroll
        for (int k16 = 0; k16 < 2; k16++) {
            const int kb = k16*16 + tig*2;
            uint32_t ah[4][4], al[4][4];
            #pragma unroll
            for (int mi = 0; mi < 4; mi++) {
                const __half* arh = Ah + (wm + mi*16 + grp)*40;
                const __half* arl = Al + (wm + mi*16 + grp)*40;
                ah[mi][0] = *(const uint32_t*)(arh + kb);
                ah[mi][1] = *(const uint32_t*)(arh + 8*40 + kb);
                ah[mi][2] = *(const uint32_t*)(arh + kb + 8);
                ah[mi][3] = *(const uint32_t*)(arh + 8*40 + kb + 8);
                al[mi][0] = *(const uint32_t*)(arl + kb);
                al[mi][1] = *(const uint32_t*)(arl + 8*40 + kb);
                al[mi][2] = *(const uint32_t*)(arl + kb + 8);
                al[mi][3] = *(const uint32_t*)(arl + 8*40 + kb + 8);
            }
            #pragma unroll
            for (int nj = 0; nj < 2; nj++) {
                const __half* brh = Bh + (wn + nj*8 + grp)*40 + kb;
                const __half* brl = Bl + (wn + nj*8 + grp)*40 + kb;
                uint32_t b0h = *(const uint32_t*)(brh);
                uint32_t b1h = *(const uint32_t*)(brh + 8);
                uint32_t b0l = *(const uint32_t*)(brl);
                uint32_t b1l = *(const uint32_t*)(brl + 8);
                #pragma unroll
                for (int mi = 0; mi < 4; mi++) {
                    hmma_fp16(acc[mi][nj][0], acc[mi][nj][1], acc[mi][nj][2], acc[mi][nj][3],
                              ah[mi][0], ah[mi][1], ah[mi][2], ah[mi][3], b0h, b1h);
                    hmma_fp16(acc[mi][nj][0], acc[mi][nj][1], acc[mi][nj][2], acc[mi][nj][3],
                              ah[mi][0], ah[mi][1], ah[mi][2], ah[mi][3], b0l, b1l);
                    hmma_fp16(acc[mi][nj][0], acc[mi][nj][1], acc[mi][nj][2], acc[mi][nj][3],
                              al[mi][0], al[mi][1], al[mi][2], al[mi][3], b0h, b1h);
                }
            }
        }

        if (kt < 15) {
            const int nb = buf ^ 1;
            __half* ah = AHI + nb*5120 + arow*40 + acol;
            __half* al = ALO + nb*5120 + arow*40 + acol;
            *(uint4*)ah = a_h0; *(uint4*)(ah+8) = a_h1;
            *(uint4*)al = a_l0; *(uint4*)(al+8) = a_l1;
            *(uint4*)(BHI + nb*2560 + brow*40 + bcol) = wh4;
            *(uint4*)(BLO + nb*2560 + brow*40 + bcol) = wl4;
        }
        __syncthreads();
    }

    #pragma unroll
    for (int mi = 0; mi < 4; mi++) {
        #pragma unroll
        for (int nj = 0; nj < 2; nj++) {
            int m = wm + mi*16 + grp;
            int nc = wn + nj*8 + tig*2;
            float bx = bias[bn + nc], by = bias[bn + nc + 1];
            float v00 = acc[mi][nj][0] + bx, v01 = acc[mi][nj][1] + by;
            float v10 = acc[mi][nj][2] + bx, v11 = acc[mi][nj][3] + by;
            if (OUT == 0) {
                *(float2*)(Cout + (size_t)m*512 + bn + nc)     = make_float2(v00, v01);
                *(float2*)(Cout + (size_t)(m+8)*512 + bn + nc) = make_float2(v10, v11);
            } else {
                uint32_t hi0, lo0, hi1, lo1;
                split2(v00, v01, hi0, lo0);
                split2(v10, v11, hi1, lo1);
                *(uint32_t*)(Ch + (size_t)m*512 + bn + nc)     = hi0;
                *(uint32_t*)(Cl + (size_t)m*512 + bn + nc)     = lo0;
                *(uint32_t*)(Ch + (size_t)(m+8)*512 + bn + nc) = hi1;
                *(uint32_t*)(Cl + (size_t)(m+8)*512 + bn + nc) = lo1;
            }
        }
    }
    __syncthreads();
}

// ---- softmax + context (one batch element); writes context hi/lo fp16 ----
__device__ void att_soft(int b, const float* __restrict__ q,
                         const float* __restrict__ keys, const float* __restrict__ features,
                         const float* __restrict__ v_w, const float* __restrict__ v_b,
                         __half* __restrict__ coh, __half* __restrict__ col, float* sm)
{
    const int tid = threadIdx.x;
    float* qs = sm;
    float* vw = sm + 512;
    float* e  = sm + 1024;

    for (int i = tid; i < 512; i += 256) {
        qs[i] = __ldcg(q + b*512 + i);
        vw[i] = v_w[i];
    }
    __syncthreads();

    const int warp = tid >> 5, lane = tid & 31;
    for (int s = warp; s < SEQ; s += 8) {
        const float* kp = keys + ((size_t)b * SEQ + s) * 512;
        float acc = 0.f;
        #pragma unroll
        for (int k = lane; k < 512; k += 32)
            acc += tanhf(qs[k] + kp[k]) * vw[k];
        #pragma unroll
        for (int o = 16; o; o >>= 1) acc += __shfl_xor_sync(0xffffffffu, acc, o);
        if (!lane) e[s] = acc + v_b[0];
    }
    __syncthreads();

    if (warp == 0) {
        float v1 = (lane < SEQ) ? e[lane] : -1e30f;
        float v2 = (lane + 32 < SEQ) ? e[lane + 32] : -1e30f;
        float m = fmaxf(v1, v2);
        #pragma unroll
        for (int o = 16; o; o >>= 1) m = fmaxf(m, __shfl_xor_sync(0xffffffffu, m, o));
        float e1 = (lane < SEQ) ? expf(v1 - m) : 0.f;
        float e2 = (lane + 32 < SEQ) ? expf(v2 - m) : 0.f;
        float s = e1 + e2;
        #pragma unroll
        for (int o = 16; o; o >>= 1) s += __shfl_xor_sync(0xffffffffu, s, o);
        float inv = 1.f / s;
        if (lane < SEQ) e[lane] = e1 * inv;
        if (lane + 32 < SEQ) e[lane + 32] = e2 * inv;
    }
    __syncthreads();

    for (int k = tid; k < 512; k += 256) {
        float acc = 0.f;
        const float* f = features + (size_t)b * SEQ * 512 + k;
        #pragma unroll 7
        for (int s = 0; s < SEQ; s++) acc += e[s] * f[(size_t)s * 512];
        __half hi = __float2half_rn(acc);
        __half lo = __float2half_rn(acc - __half2float(hi));
        coh[b*512 + k] = hi;
        col[b*512 + k] = lo;
    }
    __syncthreads();
}

// ---- GRU tile: A operands pre-split fp16 hi/lo ----
template<int NK>
__device__ void gru_tile(int nt, int kc,
    const __half* __restrict__ sAh, const __half* __restrict__ sAl, int ldA,
    const __half* __restrict__ sBh, const __half* __restrict__ sBl,
    const __half* __restrict__ sCh, const __half* __restrict__ sCl,
    const __half* __restrict__ Wh, const __half* __restrict__ Wl, int ldK,
    const float* __restrict__ bih, const float* __restrict__ bhh,
    const float* __restrict__ h_old, float* __restrict__ h_new,
    __half* __restrict__ hnh, __half* __restrict__ hnl,
    __half* __restrict__ hs_out, __half* smg)
{
    __half* AHI = smg;
    __half* ALO = AHI + 2*5120;
    __half* BHI = ALO + 2*5120;
    __half* BLO = BHI + 2*2560;

    const int tid = threadIdx.x;
    const int lane = tid & 31, wid = tid >> 5;
    const int wm = (wid & 1) * 64;
    const int wn = (wid >> 1) * 16;
    const int grp = lane >> 2, tig = lane & 3;
    const int bn = nt * 64;

    const __half *Ahg, *Alg; int ld;
    {
        int sel = kc >> 1;
        if (sel == 0)      { Ahg = sAh; Alg = sAl; ld = ldA; }
        else if (sel == 1) { Ahg = sBh; Alg = sBl; ld = 512; }
        else               { Ahg = sCh; Alg = sCl; ld = 512; }
    }
    const int koff = (kc & 1) * 256;

    const int arow = tid >> 1;
    const int acol = (tid & 1) * 16;
    const int brow = tid >> 2;
    const int bcol = (tid & 3) * 8;

    const __half* Arh = Ahg + (size_t)arow * ld + koff + acol;
    const __half* Arl = Alg + (size_t)arow * ld + koff + acol;
    const __half* Wrowh = Wh + (size_t)(bn + brow) * ldK + kc*256 + bcol;
    const __half* Wrowl = Wl + (size_t)(bn + brow) * ldK + kc*256 + bcol;

    float acc[4][2][4];
    #pragma unroll
    for (int i = 0; i < 4; i++)
        #pragma unroll
        for (int j = 0; j < 2; j++)
            #pragma unroll
            for (int k = 0; k < 4; k++) acc[i][j][k] = 0.f;

    uint4 a_h0, a_h1, a_l0, a_l1, wh4, wl4;
    a_h0 = __ldcg((const uint4*)(Arh));
    a_h1 = __ldcg((const uint4*)(Arh + 8));
    a_l0 = __ldcg((const uint4*)(Arl));
    a_l1 = __ldcg((const uint4*)(Arl + 8));
    wh4 = *(const uint4*)(Wrowh);
    wl4 = *(const uint4*)(Wrowl);
    {
        __half* ah = AHI + arow*40 + acol;
        __half* al = ALO + arow*40 + acol;
        *(uint4*)ah = a_h0; *(uint4*)(ah+8) = a_h1;
        *(uint4*)al = a_l0; *(uint4*)(al+8) = a_l1;
        *(uint4*)(BHI + brow*40 + bcol) = wh4;
        *(uint4*)(BLO + brow*40 + bcol) = wl4;
    }
    __syncthreads();

    #pragma unroll 1
    for (int kt = 0; kt < 8; kt++) {
        const int buf = kt & 1;
        const __half* Ah = AHI + buf*5120;
        const __half* Al = ALO + buf*5120;
        const __half* Bh = BHI + buf*2560;
        const __half* Bl = BLO + buf*2560;

        if (kt < 7) {
            a_h0 = __ldcg((const uint4*)(Arh + (kt+1)*32));
            a_h1 = __ldcg((const uint4*)(Arh + (kt+1)*32 + 8));
            a_l0 = __ldcg((const uint4*)(Arl + (kt+1)*32));
            a_l1 = __ldcg((const uint4*)(Arl + (kt+1)*32 + 8));
            wh4 = *(const uint4*)(Wrowh + (kt+1)*32);
            wl4 = *(const uint4*)(Wrowl + (kt+1)*32);
        }

        #pragma unroll
        for (int k16 = 0; k16 < 2; k16++) {
            const int kb = k16*16 + tig*2;
            uint32_t ah[4][4], al[4][4];
            #pragma unroll
            for (int mi = 0; mi < 4; mi++) {
                const __half* arh = Ah + (wm + mi*16 + grp)*40;
                const __half* arl = Al + (wm + mi*16 + grp)*40;
                ah[mi][0] = *(const uint32_t*)(arh + kb);
                ah[mi][1] = *(const uint32_t*)(arh + 8*40 + kb);
                ah[mi][2] = *(const uint32_t*)(arh + kb + 8);
                ah[mi][3] = *(const uint32_t*)(arh + 8*40 + kb + 8);
                al[mi][0] = *(const uint32_t*)(arl + kb);
                al[mi][1] = *(const uint32_t*)(arl + 8*40 + kb);
                al[mi][2] = *(const uint32_t*)(arl + kb + 8);
                al[mi][3] = *(const uint32_t*)(arl + 8*40 + kb + 8);
            }
            #pragma unroll
            for (int nj = 0; nj < 2; nj++) {
                const __half* brh = Bh + (wn + nj*8 + grp)*40 + kb;
                const __half* brl = Bl + (wn + nj*8 + grp)*40 + kb;
                uint32_t b0h = *(const uint32_t*)(brh);
                uint32_t b1h = *(const uint32_t*)(brh + 8);
                uint32_t b0l = *(const uint32_t*)(brl);
                uint32_t b1l = *(const uint32_t*)(brl + 8);
                #pragma unroll
                for (int mi = 0; mi < 4; mi++) {
                    hmma_fp16(acc[mi][nj][0], acc[mi][nj][1], acc[mi][nj][2], acc[mi][nj][3],
                              ah[mi][0], ah[mi][1], ah[mi][2], ah[mi][3], b0h, b1h);
                    hmma_fp16(acc[mi][nj][0], acc[mi][nj][1], acc[mi][nj][2], acc[mi][nj][3],
                              ah[mi][0], ah[mi][1], ah[mi][2], ah[mi][3], b0l, b1l);
                    hmma_fp16(acc[mi][nj][0], acc[mi][nj][1], acc[mi][nj][2], acc[mi][nj][3],
                              al[mi][0], al[mi][1], al[mi][2], al[mi][3], b0h, b1h);
                }
            }
        }

        if (kt < 7) {
            const int nb = buf ^ 1;
            __half* ah = AHI + nb*5120 + arow*40 + acol;
            __half* al = ALO + nb*5120 + arow*40 + acol;
            *(uint4*)ah = a_h0; *(uint4*)(ah+8) = a_h1;
            *(uint4*)al = a_l0; *(uint4*)(al+8) = a_l1;
            *(uint4*)(BHI + nb*2560 + brow*40 + bcol) = wh4;
            *(uint4*)(BLO + nb*2560 + brow*40 + bcol) = wl4;
        }
        __syncthreads();
    }

    {
        float* P = g_part + ((size_t)(kc*24 + nt)) * 8192;
        #pragma unroll
        for (int mi = 0; mi < 4; mi++) {
            #pragma unroll
            for (int nj = 0; nj < 2; nj++) {
                int m = wm + mi*16 + grp;
                int nc = wn + nj*8 + tig*2;
                *(float2*)(P + m*64 + nc)     = make_float2(acc[mi][nj][0], acc[mi][nj][1]);
                *(float2*)(P + (m+8)*64 + nc) = make_float2(acc[mi][nj][2], acc[mi][nj][3]);
            }
        }
    }

    __threadfence();
    __shared__ int sdone;
    if (tid == 0) {
        int g = nt & 7;
        int v = atomicAdd(&g_cnt[g], 1);
        int done = (v == 3*NK - 1);
        if (done) g_cnt[g] = 0;
        sdone = done;
    }
    __syncthreads();
    if (!sdone) return;
    __threadfence();

    const int g = nt & 7;
    const int cc = (tid & 15) * 4;
    const int c  = g*64 + cc;
    float4 bir = *(const float4*)(bih + c);
    float4 biz = *(const float4*)(bih + 512 + c);
    float4 bin = *(const float4*)(bih + 1024 + c);
    float4 bhr = *(const float4*)(bhh + c);
    float4 bhz = *(const float4*)(bhh + 512 + c);
    float4 bhn = *(const float4*)(bhh + 1024 + c);

    #pragma unroll
    for (int i = 0; i < 8; i++) {
        const int m = (tid >> 4) * 8 + i;
        float4 r4 = make_float4(0,0,0,0), z4 = r4, in4 = r4, hn4 = r4;
        #pragma unroll
        for (int kx = 0; kx < NK; kx++) {
            const float* Pr = g_part + ((size_t)(kx*24 + g))      * 8192 + m*64 + cc;
            const float* Pz = g_part + ((size_t)(kx*24 + 8 + g))  * 8192 + m*64 + cc;
            const float* Pn = g_part + ((size_t)(kx*24 + 16 + g)) * 8192 + m*64 + cc;
            float4 a = __ldcg((const float4*)Pr);
            r4.x += a.x; r4.y += a.y; r4.z += a.z; r4.w += a.w;
            a = __ldcg((const float4*)Pz);
            z4.x += a.x; z4.y += a.y; z4.z += a.z; z4.w += a.w;
            a = __ldcg((const float4*)Pn);
            if (kx < NK-2) { in4.x += a.x; in4.y += a.y; in4.z += a.z; in4.w += a.w; }
            else           { hn4.x += a.x; hn4.y += a.y; hn4.z += a.z; hn4.w += a.w; }
        }
        float4 ho = __ldcg((const float4*)(h_old + (size_t)m*512 + c));
        float hv[4];
        #pragma unroll
        for (int q = 0; q < 4; q++) {
            float rp = ((float*)&r4)[q] + ((float*)&bir)[q] + ((float*)&bhr)[q];
            float zp = ((float*)&z4)[q] + ((float*)&biz)[q] + ((float*)&bhz)[q];
            float ip = ((float*)&in4)[q] + ((float*)&bin)[q];
            float hp = ((float*)&hn4)[q] + ((float*)&bhn)[q];
            float r = 1.f / (1.f + expf(-rp));
            float z = 1.f / (1.f + expf(-zp));
            float n = tanhf(ip + r * hp);
            hv[q] = (1.f - z) * n + z * ((float*)&ho)[q];
        }
        *(float4*)(h_new + (size_t)m*512 + c) = make_float4(hv[0], hv[1], hv[2], hv[3]);
        uint32_t hi0, lo0, hi1, lo1;
        split2(hv[0], hv[1], hi0, lo0);
        split2(hv[2], hv[3], hi1, lo1);
        *(uint32_t*)(hnh + (size_t)m*512 + c)     = hi0;
        *(uint32_t*)(hnh + (size_t)m*512 + c + 2) = hi1;
        *(uint32_t*)(hnl + (size_t)m*512 + c)     = lo0;
        *(uint32_t*)(hnl + (size_t)m*512 + c + 2) = lo1;
        if (hs_out) {
            uint2 ov; ov.x = hi0; ov.y = hi1;
            *(uint2*)(hs_out + (size_t)m*512 + c) = ov;
        }
    }
}

// ---- persistent chain kernel ----
__global__ void __launch_bounds__(256, 1) chain_kernel(
    const float* __restrict__ features,
    const float* __restrict__ bq,
    const float* __restrict__ v_w, const float* __restrict__ v_b,
    const float* __restrict__ fc0_b,
    const float* __restrict__ bih0, const float* __restrict__ bhh0,
    const float* __restrict__ bihr, const float* __restrict__ bhhr)
{
    extern __shared__ __half smg[];
    float* smf = (float*)smg;

    for (int t = 0; t < NSTEP; t++) {
        const int ho = (t & 1) * (4 * BH);
        const int no = ((t & 1) ^ 1) * (4 * BH);
        const float* hold = g_h + ho;
        float*       hnew = g_h + no;

        // Q: q = h3 @ wq^T + bq
        for (int w = blockIdx.x; w < 8; w += gridDim.x)
            lin_tile<0>(w, g_hh + ho + 3*BH, g_hl + ho + 3*BH,
                        g_lwh, g_lwl, bq, g_q, nullptr, nullptr, smg);
        grid_bar();

        // S: softmax + context -> hi/lo
        for (int b = blockIdx.x; b < BATCH; b += gridDim.x)
            att_soft(b, g_q, g_keys, features, v_w, v_b, g_coh, g_col, smf);
        grid_bar();

        // F: ctx = context @ fc0^T + fc0_b -> hi/lo
        for (int w = blockIdx.x; w < 8; w += gridDim.x)
            lin_tile<1>(w, g_coh, g_col,
                        g_lwh + (size_t)HID*HID, g_lwl + (size_t)HID*HID,
                        fc0_b, nullptr, g_ctxh, g_ctxl, smg);
        grid_bar();

        // L0
        for (int w = blockIdx.x; w < 144; w += gridDim.x)
            gru_tile<6>(w % 24, w / 24,
                        g_xh + t*HID, g_xl + t*HID, NSTEP*HID,
                        g_ctxh, g_ctxl,
                        g_hh + ho, g_hl + ho,
                        g_wh, g_wl, 1536, bih0, bhh0, hold, hnew,
                        g_hh + no, g_hl + no, nullptr, smg);
        grid_bar();

        // L1..L3
        for (int l = 1; l < 4; l++) {
            const size_t off = (size_t)1536*1536 + (size_t)(l-1)*1536*1024;
            __half* hs_out = (l == 3) ? (g_hsh + t * BH) : nullptr;
            for (int w = blockIdx.x; w < 96; w += gridDim.x)
                gru_tile<4>(w % 24, w / 24,
                            g_hh + no + (l-1)*BH, g_hl + no + (l-1)*BH, 512,
                            g_hh + ho + l*BH, g_hl + ho + l*BH,
                            nullptr, nullptr,
                            g_wh + off, g_wl + off, 1024,
                            bihr + (l-1)*1536, bhhr + (l-1)*1536,
                            hold + l*BH, hnew + l*BH,
                            g_hh + no + l*BH, g_hl + no + l*BH, hs_out, smg);
            grid_bar();
        }
    }
}

// ---------------- fc2 via mma.sync fp16 (unchanged) ----------------
#define F2_PAD  40
#define F2_ASZ  (128*F2_PAD)
#define F2_BSZ  (256*F2_PAD)
#define F2_SMEM ((2*F2_ASZ + 2*F2_BSZ)*2)

__global__ void __launch_bounds__(256, 1) fc2_mma_fp16(
    const __half* __restrict__ A, const __half* __restrict__ Bw,
    const float* __restrict__ bias, float* __restrict__ out)
{
    extern __shared__ __half smh[];
    __half* As = smh;
    __half* Bs = smh + 2*F2_ASZ;

    const int tid  = threadIdx.x;
    const int lane = tid & 31, wid = tid >> 5;
    const int wm = (wid >> 2) * 64;
    const int wn = (wid & 3)  * 64;
    const int grp = lane >> 2;
    const int tig = lane & 3;
    const int bn = blockIdx.x * 256;
    const int t  = blockIdx.y;

    const __half* Ab = A  + (size_t)t  * 128 * 512;
    const __half* Bb = Bw + (size_t)bn * 512;

    float acc[4][8][4];
    #pragma unroll
    for (int i = 0; i < 4; i++)
        #pragma unroll
        for (int j = 0; j < 8; j++)
            #pragma unroll
            for (int k = 0; k < 4; k++) acc[i][j][k] = 0.f;

    uint4 ra[2], rb[4];
    #pragma unroll
    for (int p = 0; p < 2; p++) {
        int idx = tid + p * 256;
        int row = idx >> 2, c8 = (idx & 3) * 8;
        ra[p] = *(const uint4*)(Ab + (size_t)row * 512 + c8);
    }
    #pragma unroll
    for (int p = 0; p < 4; p++) {
        int idx = tid + p * 256;
        int row = idx >> 2, c8 = (idx & 3) * 8;
        rb[p] = *(const uint4*)(Bb + (size_t)row * 512 + c8);
    }
    #pragma unroll
    for (int p = 0; p < 2; p++) {
        int idx = tid + p * 256;
        int row = idx >> 2, c8 = (idx & 3) * 8;
        *(uint4*)(As + row*F2_PAD + c8) = ra[p];
    }
    #pragma unroll
    for (int p = 0; p < 4; p++) {
        int idx = tid + p * 256;
        int row = idx >> 2, c8 = (idx & 3) * 8;
        *(uint4*)(Bs + row*F2_PAD + c8) = rb[p];
    }
    __syncthreads();

    #pragma unroll 1
    for (int kt = 0; kt < 16; kt++) {
        const int buf = kt & 1;
        const __half* Asb = As + buf * F2_ASZ;
        const __half* Bsb = Bs + buf * F2_BSZ;

        if (kt < 15) {
            const __half* Aq = Ab + (kt+1)*32;
            const __half* Bq = Bb + (kt+1)*32;
            #pragma unroll
            for (int p = 0; p < 2; p++) {
                int idx = tid + p * 256;
                int row = idx >> 2, c8 = (idx & 3) * 8;
                ra[p] = *(const uint4*)(Aq + (size_t)row * 512 + c8);
            }
            #pragma unroll
            for (int p = 0; p < 4; p++) {
                int idx = tid + p * 256;
                int row = idx >> 2, c8 = (idx & 3) * 8;
                rb[p] = *(const uint4*)(Bq + (size_t)row * 512 + c8);
            }
        }

        #pragma unroll
        for (int k16 = 0; k16 < 2; k16++) {
            const int kb = k16*16 + tig*2;
            uint32_t af[4][4];
            #pragma unroll
            for (int mi = 0; mi < 4; mi++) {
                const __half* ar = Asb + (wm + mi*16 + grp)*F2_PAD;
                af[mi][0] = *(const uint32_t*)(ar + kb);
                af[mi][1] = *(const uint32_t*)(ar + 8*F2_PAD + kb);
                af[mi][2] = *(const uint32_t*)(ar + kb + 8);
                af[mi][3] = *(const uint32_t*)(ar + 8*F2_PAD + kb + 8);
            }
            #pragma unroll
            for (int nj = 0; nj < 8; nj++) {
                const __half* br = Bsb + (wn + nj*8 + grp)*F2_PAD + kb;
                uint32_t b0 = *(const uint32_t*)(br);
                uint32_t b1 = *(const uint32_t*)(br + 8);
                #pragma unroll
                for (int mi = 0; mi < 4; mi++)
                    hmma_fp16(acc[mi][nj][0], acc[mi][nj][1], acc[mi][nj][2], acc[mi][nj][3],
                              af[mi][0], af[mi][1], af[mi][2], af[mi][3], b0, b1);
            }
        }

        if (kt < 15) {
            __half* Asn = As + (buf ^ 1) * F2_ASZ;
            __half* Bsn = Bs + (buf ^ 1) * F2_BSZ;
            #pragma unroll
            for (int p = 0; p < 2; p++) {
                int idx = tid + p * 256;
                int row = idx >> 2, c8 = (idx & 3) * 8;
                *(uint4*)(Asn + row*F2_PAD + c8) = ra[p];
            }
            #pragma unroll
            for (int p = 0; p < 4; p++) {
                int idx = tid + p * 256;
                int row = idx >> 2, c8 = (idx & 3) * 8;
                *(uint4*)(Bsn + row*F2_PAD + c8) = rb[p];
            }
        }
        __syncthreads();
    }

    #pragma unroll
    for (int mi = 0; mi < 4; mi++) {
        const int b0 = wm + mi*16 + grp;
        float* o0 = out + ((size_t)b0       * NSTEP + t) * VOCAB + bn + wn;
        float* o8 = out + ((size_t)(b0 + 8) * NSTEP + t) * VOCAB + bn + wn;
        #pragma unroll
        for (int nj = 0; nj < 8; nj++) {
            const int n = nj*8 + 2*tig;
            float bx = bias[bn + wn + n];
            float by = bias[bn + wn + n + 1];
            *(float2*)(o0 + n) = make_float2(acc[mi][nj][0] + bx, acc[mi][nj][1] + by);
            *(float2*)(o8 + n) = make_float2(acc[mi][nj][2] + bx, acc[mi][nj][3] + by);
        }
    }
}

// ---------------- host launch ----------------
extern "C" void kernel_launch(void* const* d_in, const int* in_sizes, int n_in,
                              void* d_out, int out_size)
{
    const float* features = (const float*)d_in[0];
    const int*   caps     = (const int*)  d_in[1];
    const float* emb      = (const float*)d_in[2];
    const float* fc1_w    = (const float*)d_in[3];
    const float* fc1_b    = (const float*)d_in[4];
    const float* fc0_w    = (const float*)d_in[5];
    const float* fc0_b    = (const float*)d_in[6];
    const float* wq       = (const float*)d_in[7];
    const float* bq       = (const float*)d_in[8];
    const float* wk       = (const float*)d_in[9];
    const float* bk       = (const float*)d_in[10];
    const float* v_w      = (const float*)d_in[11];
    const float* v_b      = (const float*)d_in[12];
    const float* wih0     = (const float*)d_in[13];
    const float* whh0     = (const float*)d_in[14];
    const float* bih0     = (const float*)d_in[15];
    const float* bhh0     = (const float*)d_in[16];
    const float* wihr     = (const float*)d_in[17];
    const float* whhr     = (const float*)d_in[18];
    const float* bihr     = (const float*)d_in[19];
    const float* bhhr     = (const float*)d_in[20];
    const float* fc2_w    = (const float*)d_in[21];
    const float* fc2_b    = (const float*)d_in[22];
    float* out = (float*)d_out;

    float* pkeys;
    __half *phsh, *pw2h;
    cudaGetSymbolAddress((void**)&pkeys, g_keys);
    cudaGetSymbolAddress((void**)&phsh,  g_hsh);
    cudaGetSymbolAddress((void**)&pw2h,  g_w2h);

    cudaFuncSetAttribute(fc2_mma_fp16, cudaFuncAttributeMaxDynamicSharedMemorySize, F2_SMEM);
    cudaFuncSetAttribute(keys_mma,     cudaFuncAttributeMaxDynamicSharedMemorySize, K_SMEMB);
    cudaFuncSetAttribute(chain_kernel, cudaFuncAttributeMaxDynamicSharedMemorySize, GR_SMEM);
    cudaFuncSetAttribute(xgemm_mma,    cudaFuncAttributeMaxDynamicSharedMemorySize, GR_SMEM);

    int nsm = 0;
    cudaDeviceGetAttribute(&nsm, cudaDevAttrMultiProcessorCount, 0);
    int nb = nsm;
    if (nb > 144) nb = 144;

    // launch order matters for ncu (-s 5 -c 1 profiles the 6th launch = chain_kernel)
    init_kernel<<<1024, 256>>>();                                        // 1
    cvt_w2_kernel<<<VOCAB*HID/8/256, 256>>>(fc2_w);                      // 2
    wsplit_all<<<3840, 256>>>(wih0, whh0, wihr, whhr, wq, fc0_w, fc1_w); // 3
    xgemm_mma<<<dim3(8, 15), 256, GR_SMEM>>>(emb, caps, fc1_b);          // 4
    keys_mma<<<dim3(2, 49), 256, K_SMEMB>>>(features, wk, bk, pkeys);    // 5

    chain_kernel<<<nb, 256, GR_SMEM>>>(features, bq, v_w, v_b, fc0_b,    // 6 (profiled)
                                       bih0, bhh0, bihr, bhhr);

    fc2_mma_fp16<<<dim3(VOCAB/256, NSTEP), 256, F2_SMEM>>>(phsh, pw2h, fc2_b, out);  // 7
}

// round 11
// speedup vs baseline: 1.3206x; 1.1114x over previous
#include <cuda_runtime.h>
#include <cuda_fp16.h>
#include <math.h>
#include <cstdint>

#define BATCH 128
#define SEQ   49
#define HID   512
#define VOCAB 32000
#define NSTEP 15
#define BH    (BATCH*HID)

// ---------------- device scratch ----------------
__device__ float  g_keys[BATCH*SEQ*HID];
__device__ float  g_q[BH];
__device__ float  g_h[2*4*BH];
__device__ __half g_hh[2*4*BH];
__device__ __half g_hl[2*4*BH];
__device__ __half g_xh[BATCH*NSTEP*HID];
__device__ __half g_xl[BATCH*NSTEP*HID];
__device__ __half g_coh[BH], g_col[BH];     // context hi/lo
__device__ __half g_hsh[NSTEP*BH];
__device__ float  g_part[6*3*BH];
__device__ __half g_w2h[VOCAB*HID];
#define WG_TOT (1536*1536 + 3*1536*1024)
__device__ __half g_wh[WG_TOT];
__device__ __half g_wl[WG_TOT];
__device__ __half g_lwh[3*HID*HID];         // [wq | fc0^T | fc1] hi
__device__ __half g_lwl[3*HID*HID];
__device__ float  g_bihe[1536];             // bih0 + wih0_mid @ fc0_b
__device__ int    g_cnt[8];
__device__ unsigned g_bcnt = 0;
__device__ unsigned g_bgen = 0;

// ---------------- init (+ folded bias) ----------------
__global__ void init_kernel(const float* __restrict__ wih0,
                            const float* __restrict__ fc0_b,
                            const float* __restrict__ bih0) {
    if (blockIdx.x < 1024) {
        int idx = blockIdx.x * 256 + threadIdx.x;
        if (idx < 4*BH) {
            g_h[idx] = 0.f;
            g_hh[idx] = __float2half(0.f);
            g_hl[idx] = __float2half(0.f);
        }
        if (blockIdx.x == 0 && threadIdx.x < 8) g_cnt[threadIdx.x] = 0;
        if (blockIdx.x == 0 && threadIdx.x == 0) { g_bcnt = 0; }
    } else {
        int i = (blockIdx.x - 1024) * 256 + threadIdx.x;
        if (i < 1536) {
            const float* wr = wih0 + (size_t)i * 1024 + 512;
            float s = 0.f;
            #pragma unroll 8
            for (int j = 0; j < 512; j += 4) {
                float4 w = *(const float4*)(wr + j);
                float4 b = *(const float4*)(fc0_b + j);
                s += w.x*b.x + w.y*b.y + w.z*b.z + w.w*b.w;
            }
            g_bihe[i] = bih0[i] + s;
        }
    }
}

// ---------------- split helpers ----------------
__device__ __forceinline__ void split8(const float* sp, uint4& hiv, uint4& lov) {
    uint32_t hi[4], lo[4];
    #pragma unroll
    for (int j = 0; j < 4; j++) {
        float a = sp[2*j], b = sp[2*j + 1];
        __half2 h2 = __floats2half2_rn(a, b);
        float2 bb = __half22float2(h2);
        __half2 l2 = __floats2half2_rn(a - bb.x, b - bb.y);
        hi[j] = *(uint32_t*)&h2; lo[j] = *(uint32_t*)&l2;
    }
    hiv = make_uint4(hi[0], hi[1], hi[2], hi[3]);
    lov = make_uint4(lo[0], lo[1], lo[2], lo[3]);
}
__device__ __forceinline__ void split2(float a, float b, uint32_t& hi, uint32_t& lo) {
    __half2 h2 = __floats2half2_rn(a, b);
    float2 bb = __half22float2(h2);
    __half2 l2 = __floats2half2_rn(a - bb.x, b - bb.y);
    hi = *(uint32_t*)&h2; lo = *(uint32_t*)&l2;
}

// ---------------- ALL weight prep in ONE kernel ----------------
// segs: L0 294912 | L1-3 3x196608 | wq/fc0T/fc1 3x32768 | w2 2048000
__global__ void wsplit_all(const float* __restrict__ wih0, const float* __restrict__ whh0,
                           const float* __restrict__ wihr, const float* __restrict__ whhr,
                           const float* __restrict__ wq,   const float* __restrict__ fc0_w,
                           const float* __restrict__ fc1_w, const float* __restrict__ fc2_w) {
    int i = blockIdx.x * 256 + threadIdx.x;
    const int C0 = 294912, CL = 196608, CW = 32768;
    const int B1 = C0 + 3*CL, B2 = B1 + 3*CW, B3 = B2 + VOCAB*HID/8;
    if (i >= B3) return;
    if (i >= B2) {
        int j = i - B2;
        int row = j >> 6, c = (j & 63) * 8;
        const float* sp = fc2_w + (size_t)row*512 + c;
        float4 v0 = *(const float4*)sp, v1 = *(const float4*)(sp + 4);
        __half2 h0 = __floats2half2_rn(v0.x, v0.y);
        __half2 h1 = __floats2half2_rn(v0.z, v0.w);
        __half2 h2 = __floats2half2_rn(v1.x, v1.y);
        __half2 h3 = __floats2half2_rn(v1.z, v1.w);
        uint4 o;
        o.x = *(uint32_t*)&h0; o.y = *(uint32_t*)&h1;
        o.z = *(uint32_t*)&h2; o.w = *(uint32_t*)&h3;
        *(uint4*)(g_w2h + (size_t)row*512 + c) = o;
        return;
    }
    const float* sp;
    __half *dh, *dl;
    size_t doff;
    if (i < C0) {
        int row = i / 192, c = (i - row*192) * 8;
        sp = (c < 1024) ? (wih0 + (size_t)row*1024 + c) : (whh0 + (size_t)row*512 + (c - 1024));
        dh = g_wh; dl = g_wl; doff = (size_t)row*1536 + c;
    } else if (i < B1) {
        int j = i - C0;
        int l = j / CL; j -= l*CL;
        int row = j / 128, c = (j - row*128) * 8;
        const float* wih = wihr + (size_t)l*1536*512;
        const float* whh = whhr + (size_t)l*1536*512;
        sp = (c < 512) ? (wih + (size_t)row*512 + c) : (whh + (size_t)row*512 + (c - 512));
        dh = g_wh; dl = g_wl;
        doff = (size_t)1536*1536 + (size_t)l*1536*1024 + (size_t)row*1024 + c;
    } else {
        int j = i - B1;
        int seg = j / CW; j -= seg*CW;
        int row = j / 64, c = (j - row*64) * 8;
        if (seg == 1) {
            // fc0 TRANSPOSED: dest[n][j] = fc0_w[j][n]  (scalar stores, one-time)
            const float* s0 = fc0_w + (size_t)row*512 + c;   // fc0_w[row][c..c+7]
            #pragma unroll
            for (int u = 0; u < 8; u++) {
                float v = s0[u];
                __half h = __float2half_rn(v);
                __half l = __float2half_rn(v - __half2float(h));
                size_t d = (size_t)HID*HID + (size_t)(c + u)*512 + row;
                g_lwh[d] = h;
                g_lwl[d] = l;
            }
            return;
        }
        const float* w = (seg == 0) ? wq : fc1_w;
        sp = w + (size_t)row*512 + c;
        dh = g_lwh; dl = g_lwl;
        doff = (size_t)seg*HID*HID + (size_t)row*512 + c;
    }
    uint4 hiv, lov;
    split8(sp, hiv, lov);
    *(uint4*)(dh + doff) = hiv;
    *(uint4*)(dl + doff) = lov;
}

// ---------------- MMA helpers ----------------
__device__ __forceinline__ void hmma_tf32(float& c0, float& c1, float& c2, float& c3,
                                          uint32_t a0, uint32_t a1, uint32_t a2, uint32_t a3,
                                          uint32_t b0, uint32_t b1) {
    asm volatile("mma.sync.aligned.m16n8k8.row.col.f32.tf32.tf32.f32 "
                 "{%0,%1,%2,%3}, {%4,%5,%6,%7}, {%8,%9}, {%0,%1,%2,%3};"
                 : "+f"(c0), "+f"(c1), "+f"(c2), "+f"(c3)
                 : "r"(a0), "r"(a1), "r"(a2), "r"(a3), "r"(b0), "r"(b1));
}
__device__ __forceinline__ void hmma_fp16(float& c0, float& c1, float& c2, float& c3,
                                          uint32_t a0, uint32_t a1, uint32_t a2, uint32_t a3,
                                          uint32_t b0, uint32_t b1) {
    asm volatile("mma.sync.aligned.m16n8k16.row.col.f32.f16.f16.f32 "
                 "{%0,%1,%2,%3}, {%4,%5,%6,%7}, {%8,%9}, {%0,%1,%2,%3};"
                 : "+f"(c0), "+f"(c1), "+f"(c2), "+f"(c3)
                 : "r"(a0), "r"(a1), "r"(a2), "r"(a3), "r"(b0), "r"(b1));
}

#define GR_SMEM ((2*5120*2 + 2*2560*2)*2)   // 61440 bytes

// ---------------- W0c fold: g_wh[:,512:1024] = wih0_mid @ fc0 (compensated) ----
// A[m][j] = wih0[m][512+j]; B[n][j] = fc0^T stored row-major = fc0_w[j][n].
__global__ void __launch_bounds__(256, 1) w0c_mma(const float* __restrict__ wih0)
{
    extern __shared__ __half smg[];
    __half* AHI = smg;
    __half* ALO = AHI + 2*5120;
    __half* BHI = ALO + 2*5120;
    __half* BLO = BHI + 2*2560;

    const int tid = threadIdx.x;
    const int lane = tid & 31, wid = tid >> 5;
    const int wm = (wid & 1) * 64;
    const int wn = (wid >> 1) * 16;
    const int grp = lane >> 2, tig = lane & 3;
    const int bn = blockIdx.x * 64;
    const int bm = blockIdx.y * 128;

    const int arow = tid >> 1;
    const int acol = (tid & 1) * 16;
    const int brow = tid >> 2;
    const int bcol = (tid & 3) * 8;

    const float*  Arow  = wih0 + (size_t)(bm + arow) * 1024 + 512 + acol;
    const __half* Wrowh = g_lwh + (size_t)HID*HID + (size_t)(bn + brow) * 512 + bcol;
    const __half* Wrowl = g_lwl + (size_t)HID*HID + (size_t)(bn + brow) * 512 + bcol;

    float acc[4][2][4];
    #pragma unroll
    for (int i = 0; i < 4; i++)
        #pragma unroll
        for (int j = 0; j < 2; j++)
            #pragma unroll
            for (int k = 0; k < 4; k++) acc[i][j][k] = 0.f;

    float fa[16];
    uint4 wh4, wl4;
    #pragma unroll
    for (int p = 0; p < 4; p++)
        *(float4*)&fa[p*4] = *(const float4*)(Arow + p*4);
    wh4 = *(const uint4*)(Wrowh);
    wl4 = *(const uint4*)(Wrowl);
    {
        uint4 h0, l0, h1, l1;
        split8(&fa[0], h0, l0); split8(&fa[8], h1, l1);
        __half* ah = AHI + arow*40 + acol;
        __half* al = ALO + arow*40 + acol;
        *(uint4*)ah = h0; *(uint4*)(ah+8) = h1;
        *(uint4*)al = l0; *(uint4*)(al+8) = l1;
        *(uint4*)(BHI + brow*40 + bcol) = wh4;
        *(uint4*)(BLO + brow*40 + bcol) = wl4;
    }
    __syncthreads();

    #pragma unroll 1
    for (int kt = 0; kt < 16; kt++) {
        const int buf = kt & 1;
        const __half* Ah = AHI + buf*5120;
        const __half* Al = ALO + buf*5120;
        const __half* Bh = BHI + buf*2560;
        const __half* Bl = BLO + buf*2560;

        if (kt < 15) {
            #pragma unroll
            for (int p = 0; p < 4; p++)
                *(float4*)&fa[p*4] = *(const float4*)(Arow + (kt+1)*32 + p*4);
            wh4 = *(const uint4*)(Wrowh + (kt+1)*32);
            wl4 = *(const uint4*)(Wrowl + (kt+1)*32);
        }

        #pragma unroll
        for (int k16 = 0; k16 < 2; k16++) {
            const int kb = k16*16 + tig*2;
            uint32_t ah[4][4], al[4][4];
            #pragma unroll
            for (int mi = 0; mi < 4; mi++) {
                const __half* arh = Ah + (wm + mi*16 + grp)*40;
                const __half* arl = Al + (wm + mi*16 + grp)*40;
                ah[mi][0] = *(const uint32_t*)(arh + kb);
                ah[mi][1] = *(const uint32_t*)(arh + 8*40 + kb);
                ah[mi][2] = *(const uint32_t*)(arh + kb + 8);
                ah[mi][3] = *(const uint32_t*)(arh + 8*40 + kb + 8);
                al[mi][0] = *(const uint32_t*)(arl + kb);
                al[mi][1] = *(const uint32_t*)(arl + 8*40 + kb);
                al[mi][2] = *(const uint32_t*)(arl + kb + 8);
                al[mi][3] = *(const uint32_t*)(arl + 8*40 + kb + 8);
            }
            #pragma unroll
            for (int nj = 0; nj < 2; nj++) {
                const __half* brh = Bh + (wn + nj*8 + grp)*40 + kb;
                const __half* brl = Bl + (wn + nj*8 + grp)*40 + kb;
                uint32_t b0h = *(const uint32_t*)(brh);
                uint32_t b1h = *(const uint32_t*)(brh + 8);
                uint32_t b0l = *(const uint32_t*)(brl);
                uint32_t b1l = *(const uint32_t*)(brl + 8);
                #pragma unroll
                for (int mi = 0; mi < 4; mi++) {
                    hmma_fp16(acc[mi][nj][0], acc[mi][nj][1], acc[mi][nj][2], acc[mi][nj][3],
                              ah[mi][0], ah[mi][1], ah[mi][2], ah[mi][3], b0h, b1h);
                    hmma_fp16(acc[mi][nj][0], acc[mi][nj][1], acc[mi][nj][2], acc[mi][nj][3],
                              ah[mi][0], ah[mi][1], ah[mi][2], ah[mi][3], b0l, b1l);
                    hmma_fp16(acc[mi][nj][0], acc[mi][nj][1], acc[mi][nj][2], acc[mi][nj][3],
                              al[mi][0], al[mi][1], al[mi][2], al[mi][3], b0h, b1h);
                }
            }
        }

        if (kt < 15) {
            const int nb = buf ^ 1;
            uint4 h0, l0, h1, l1;
            split8(&fa[0], h0, l0); split8(&fa[8], h1, l1);
            __half* ah = AHI + nb*5120 + arow*40 + acol;
            __half* al = ALO + nb*5120 + arow*40 + acol;
            *(uint4*)ah = h0; *(uint4*)(ah+8) = h1;
            *(uint4*)al = l0; *(uint4*)(al+8) = l1;
            *(uint4*)(BHI + nb*2560 + brow*40 + bcol) = wh4;
            *(uint4*)(BLO + nb*2560 + brow*40 + bcol) = wl4;
        }
        __syncthreads();
    }

    #pragma unroll
    for (int mi = 0; mi < 4; mi++) {
        #pragma unroll
        for (int nj = 0; nj < 2; nj++) {
            int m = wm + mi*16 + grp;
            int k = bn + wn + nj*8 + tig*2;
            uint32_t hi0, lo0, hi1, lo1;
            split2(acc[mi][nj][0], acc[mi][nj][1], hi0, lo0);
            split2(acc[mi][nj][2], acc[mi][nj][3], hi1, lo1);
            size_t o0 = (size_t)(bm + m) * 1536 + 512 + k;
            size_t o8 = (size_t)(bm + m + 8) * 1536 + 512 + k;
            *(uint32_t*)(g_wh + o0) = hi0;
            *(uint32_t*)(g_wl + o0) = lo0;
            *(uint32_t*)(g_wh + o8) = hi1;
            *(uint32_t*)(g_wl + o8) = lo1;
        }
    }
}

// ---------------- keys via mma.sync tf32 ----------------
#define KPAD   36
#define K_ASZ  (128*KPAD)
#define K_BSZ  (256*KPAD)
#define K_SMEMB ((2*K_ASZ + 2*K_BSZ)*4)

__global__ void __launch_bounds__(256, 1) keys_mma(
    const float* __restrict__ A, const float* __restrict__ Bw,
    const float* __restrict__ bias, float* __restrict__ C)
{
    extern __shared__ float smf[];
    float* As = smf;
    float* Bs = smf + 2*K_ASZ;

    const int tid  = threadIdx.x;
    const int lane = tid & 31, wid = tid >> 5;
    const int wm = (wid >> 2) * 64;
    const int wn = (wid & 3)  * 64;
    const int grp = lane >> 2;
    const int tig = lane & 3;
    const int bn = blockIdx.x * 256;
    const int bm = blockIdx.y * 128;

    const float* Ab = A  + (size_t)bm * 512;
    const float* Bb = Bw + (size_t)bn * 512;

    const int lrowA = tid >> 3;
    const int lc4   = (tid & 7) * 4;

    float acc[4][8][4];
    #pragma unroll
    for (int i = 0; i < 4; i++)
        #pragma unroll
        for (int j = 0; j < 8; j++)
            #pragma unroll
            for (int k = 0; k < 4; k++) acc[i][j][k] = 0.f;

    float4 ra[4], rb[8];
    #pragma unroll
    for (int p = 0; p < 4; p++)
        ra[p] = *(const float4*)(Ab + (size_t)(p*32 + lrowA) * 512 + lc4);
    #pragma unroll
    for (int p = 0; p < 8; p++)
        rb[p] = *(const float4*)(Bb + (size_t)(p*32 + lrowA) * 512 + lc4);
    #pragma unroll
    for (int p = 0; p < 4; p++)
        *(float4*)(As + (p*32 + lrowA)*KPAD + lc4) = ra[p];
    #pragma unroll
    for (int p = 0; p < 8; p++)
        *(float4*)(Bs + (p*32 + lrowA)*KPAD + lc4) = rb[p];
    __syncthreads();

    #pragma unroll 1
    for (int kt = 0; kt < 16; kt++) {
        const int buf = kt & 1;
        const float* Asb = As + buf * K_ASZ;
        const float* Bsb = Bs + buf * K_BSZ;

        if (kt < 15) {
            const float* Aq = Ab + (kt+1)*32;
            const float* Bq = Bb + (kt+1)*32;
            #pragma unroll
            for (int p = 0; p < 4; p++)
                ra[p] = *(const float4*)(Aq + (size_t)(p*32 + lrowA) * 512 + lc4);
            #pragma unroll
            for (int p = 0; p < 8; p++)
                rb[p] = *(const float4*)(Bq + (size_t)(p*32 + lrowA) * 512 + lc4);
        }

        #pragma unroll
        for (int k8 = 0; k8 < 4; k8++) {
            const int kc = k8*8 + tig;
            uint32_t af[4][4];
            #pragma unroll
            for (int mi = 0; mi < 4; mi++) {
                const float* ar = Asb + (wm + mi*16 + grp)*KPAD;
                af[mi][0] = __float_as_uint(ar[kc]);
                af[mi][1] = __float_as_uint(ar[8*KPAD + kc]);
                af[mi][2] = __float_as_uint(ar[kc + 4]);
                af[mi][3] = __float_as_uint(ar[8*KPAD + kc + 4]);
            }
            #pragma unroll
            for (int nj = 0; nj < 8; nj++) {
                const float* br = Bsb + (wn + nj*8 + grp)*KPAD + k8*8;
                uint32_t b0 = __float_as_uint(br[tig]);
                uint32_t b1 = __float_as_uint(br[tig + 4]);
                #pragma unroll
                for (int mi = 0; mi < 4; mi++)
                    hmma_tf32(acc[mi][nj][0], acc[mi][nj][1], acc[mi][nj][2], acc[mi][nj][3],
                              af[mi][0], af[mi][1], af[mi][2], af[mi][3], b0, b1);
            }
        }

        if (kt < 15) {
            float* Asn = As + (buf ^ 1) * K_ASZ;
            float* Bsn = Bs + (buf ^ 1) * K_BSZ;
            #pragma unroll
            for (int p = 0; p < 4; p++)
                *(float4*)(Asn + (p*32 + lrowA)*KPAD + lc4) = ra[p];
            #pragma unroll
            for (int p = 0; p < 8; p++)
                *(float4*)(Bsn + (p*32 + lrowA)*KPAD + lc4) = rb[p];
        }
        __syncthreads();
    }

    #pragma unroll
    for (int mi = 0; mi < 4; mi++) {
        const int m = bm + wm + mi*16 + grp;
        #pragma unroll
        for (int nj = 0; nj < 8; nj++) {
            const int n = bn + wn + nj*8 + 2*tig;
            float bx = bias[n], by = bias[n + 1];
            *(float2*)(C + (size_t)m * 512 + n) =
                make_float2(acc[mi][nj][0] + bx, acc[mi][nj][1] + by);
            *(float2*)(C + (size_t)(m + 8) * 512 + n) =
                make_float2(acc[mi][nj][2] + bx, acc[mi][nj][3] + by);
        }
    }
}

// ---------------- x precompute ----------------
__global__ void __launch_bounds__(256, 1) xgemm_mma(
    const float* __restrict__ emb, const int* __restrict__ caps,
    const float* __restrict__ bias)
{
    extern __shared__ __half smg[];
    __half* AHI = smg;
    __half* ALO = AHI + 2*5120;
    __half* BHI = ALO + 2*5120;
    __half* BLO = BHI + 2*2560;

    const int tid = threadIdx.x;
    const int lane = tid & 31, wid = tid >> 5;
    const int wm = (wid & 1) * 64;
    const int wn = (wid >> 1) * 16;
    const int grp = lane >> 2, tig = lane & 3;
    const int bn = blockIdx.x * 64;
    const int t  = blockIdx.y;

    const int arow = tid >> 1;
    const int acol = (tid & 1) * 16;
    const int brow = tid >> 2;
    const int bcol = (tid & 3) * 8;

    const float*  Arow  = emb + (size_t)caps[arow*16 + t] * 512 + acol;
    const __half* Wh = g_lwh + (size_t)2*HID*HID;
    const __half* Wl = g_lwl + (size_t)2*HID*HID;
    const __half* Wrowh = Wh + (size_t)(bn + brow) * 512 + bcol;
    const __half* Wrowl = Wl + (size_t)(bn + brow) * 512 + bcol;

    float acc[4][2][4];
    #pragma unroll
    for (int i = 0; i < 4; i++)
        #pragma unroll
        for (int j = 0; j < 2; j++)
            #pragma unroll
            for (int k = 0; k < 4; k++) acc[i][j][k] = 0.f;

    float fa[16];
    uint4 wh4, wl4;
    #pragma unroll
    for (int p = 0; p < 4; p++)
        *(float4*)&fa[p*4] = *(const float4*)(Arow + p*4);
    wh4 = *(const uint4*)(Wrowh);
    wl4 = *(const uint4*)(Wrowl);
    {
        uint4 h0, l0, h1, l1;
        split8(&fa[0], h0, l0); split8(&fa[8], h1, l1);
        __half* ah = AHI + arow*40 + acol;
        __half* al = ALO + arow*40 + acol;
        *(uint4*)ah = h0; *(uint4*)(ah+8) = h1;
        *(uint4*)al = l0; *(uint4*)(al+8) = l1;
        *(uint4*)(BHI + brow*40 + bcol) = wh4;
        *(uint4*)(BLO + brow*40 + bcol) = wl4;
    }
    __syncthreads();

    #pragma unroll 1
    for (int kt = 0; kt < 16; kt++) {
        const int buf = kt & 1;
        const __half* Ah = AHI + buf*5120;
        const __half* Al = ALO + buf*5120;
        const __half* Bh = BHI + buf*2560;
        const __half* Bl = BLO + buf*2560;

        if (kt < 15) {
            #pragma unroll
            for (int p = 0; p < 4; p++)
                *(float4*)&fa[p*4] = *(const float4*)(Arow + (kt+1)*32 + p*4);
            wh4 = *(const uint4*)(Wrowh + (kt+1)*32);
            wl4 = *(const uint4*)(Wrowl + (kt+1)*32);
        }

        #pragma unroll
        for (int k16 = 0; k16 < 2; k16++) {
            const int kb = k16*16 + tig*2;
            uint32_t ah[4][4], al[4][4];
            #pragma unroll
            for (int mi = 0; mi < 4; mi++) {
                const __half* arh = Ah + (wm + mi*16 + grp)*40;
                const __half* arl = Al + (wm + mi*16 + grp)*40;
                ah[mi][0] = *(const uint32_t*)(arh + kb);
                ah[mi][1] = *(const uint32_t*)(arh + 8*40 + kb);
                ah[mi][2] = *(const uint32_t*)(arh + kb + 8);
                ah[mi][3] = *(const uint32_t*)(arh + 8*40 + kb + 8);
                al[mi][0] = *(const uint32_t*)(arl + kb);
                al[mi][1] = *(const uint32_t*)(arl + 8*40 + kb);
                al[mi][2] = *(const uint32_t*)(arl + kb + 8);
                al[mi][3] = *(const uint32_t*)(arl + 8*40 + kb + 8);
            }
            #pragma unroll
            for (int nj = 0; nj < 2; nj++) {
                const __half* brh = Bh + (wn + nj*8 + grp)*40 + kb;
                const __half* brl = Bl + (wn + nj*8 + grp)*40 + kb;
                uint32_t b0h = *(const uint32_t*)(brh);
                uint32_t b1h = *(const uint32_t*)(brh + 8);
                uint32_t b0l = *(const uint32_t*)(brl);
                uint32_t b1l = *(const uint32_t*)(brl + 8);
                #pragma unroll
                for (int mi = 0; mi < 4; mi++) {
                    hmma_fp16(acc[mi][nj][0], acc[mi][nj][1], acc[mi][nj][2], acc[mi][nj][3],
                              ah[mi][0], ah[mi][1], ah[mi][2], ah[mi][3], b0h, b1h);
                    hmma_fp16(acc[mi][nj][0], acc[mi][nj][1], acc[mi][nj][2], acc[mi][nj][3],
                              ah[mi][0], ah[mi][1], ah[mi][2], ah[mi][3], b0l, b1l);
                    hmma_fp16(acc[mi][nj][0], acc[mi][nj][1], acc[mi][nj][2], acc[mi][nj][3],
                              al[mi][0], al[mi][1], al[mi][2], al[mi][3], b0h, b1h);
                }
            }
        }

        if (kt < 15) {
            const int nb = buf ^ 1;
            uint4 h0, l0, h1, l1;
            split8(&fa[0], h0, l0); split8(&fa[8], h1, l1);
            __half* ah = AHI + nb*5120 + arow*40 + acol;
            __half* al = ALO + nb*5120 + arow*40 + acol;
            *(uint4*)ah = h0; *(uint4*)(ah+8) = h1;
            *(uint4*)al = l0; *(uint4*)(al+8) = l1;
            *(uint4*)(BHI + nb*2560 + brow*40 + bcol) = wh4;
            *(uint4*)(BLO + nb*2560 + brow*40 + bcol) = wl4;
        }
        __syncthreads();
    }

    #pragma unroll
    for (int mi = 0; mi < 4; mi++) {
        #pragma unroll
        for (int nj = 0; nj < 2; nj++) {
            int m = wm + mi*16 + grp;
            int nc = wn + nj*8 + tig*2;
            float bx = bias[bn + nc], by = bias[bn + nc + 1];
            uint32_t hi0, lo0, hi1, lo1;
            split2(acc[mi][nj][0] + bx, acc[mi][nj][1] + by, hi0, lo0);
            split2(acc[mi][nj][2] + bx, acc[mi][nj][3] + by, hi1, lo1);
            size_t o0 = (size_t)m * (NSTEP*HID) + (size_t)t*HID + bn + nc;
            size_t o8 = (size_t)(m+8) * (NSTEP*HID) + (size_t)t*HID + bn + nc;
            *(uint32_t*)(g_xh + o0) = hi0;
            *(uint32_t*)(g_xl + o0) = lo0;
            *(uint32_t*)(g_xh + o8) = hi1;
            *(uint32_t*)(g_xl + o8) = lo1;
        }
    }
}

// =====================================================================
// Persistent chain kernel
// =====================================================================
__device__ __forceinline__ void grid_bar() {
    __syncthreads();
    if (threadIdx.x == 0) {
        __threadfence();
        unsigned gen = *(volatile unsigned*)&g_bgen;
        if (atomicAdd(&g_bcnt, 1u) == gridDim.x - 1) {
            g_bcnt = 0;
            __threadfence();
            *(volatile unsigned*)&g_bgen = gen + 1;
        } else {
            while (*(volatile unsigned*)&g_bgen == gen) {}
        }
        __threadfence();
    }
    __syncthreads();
}

// ---- Q tile ----
__device__ void lin_tile(int nt,
                         const __half* __restrict__ Ahg, const __half* __restrict__ Alg,
                         const __half* __restrict__ Wh, const __half* __restrict__ Wl,
                         const float* __restrict__ bias, float* __restrict__ Cout,
                         __half* smg)
{
    __half* AHI = smg;
    __half* ALO = AHI + 2*5120;
    __half* BHI = ALO + 2*5120;
    __half* BLO = BHI + 2*2560;

    const int tid = threadIdx.x;
    const int lane = tid & 31, wid = tid >> 5;
    const int wm = (wid & 1) * 64;
    const int wn = (wid >> 1) * 16;
    const int grp = lane >> 2, tig = lane & 3;
    const int bn = nt * 64;

    const int arow = tid >> 1;
    const int acol = (tid & 1) * 16;
    const int brow = tid >> 2;
    const int bcol = (tid & 3) * 8;

    const __half* Arh = Ahg + (size_t)arow * 512 + acol;
    const __half* Arl = Alg + (size_t)arow * 512 + acol;
    const __half* Wrowh = Wh + (size_t)(bn + brow) * 512 + bcol;
    const __half* Wrowl = Wl + (size_t)(bn + brow) * 512 + bcol;

    float acc[4][2][4];
    #pragma unroll
    for (int i = 0; i < 4; i++)
        #pragma unroll
        for (int j = 0; j < 2; j++)
            #pragma unroll
            for (int k = 0; k < 4; k++) acc[i][j][k] = 0.f;

    uint4 a_h0, a_h1, a_l0, a_l1, wh4, wl4;
    a_h0 = __ldcg((const uint4*)(Arh));
    a_h1 = __ldcg((const uint4*)(Arh + 8));
    a_l0 = __ldcg((const uint4*)(Arl));
    a_l1 = __ldcg((const uint4*)(Arl + 8));
    wh4 = *(const uint4*)(Wrowh);
    wl4 = *(const uint4*)(Wrowl);
    {
        __half* ah = AHI + arow*40 + acol;
        __half* al = ALO + arow*40 + acol;
        *(uint4*)ah = a_h0; *(uint4*)(ah+8) = a_h1;
        *(uint4*)al = a_l0; *(uint4*)(al+8) = a_l1;
        *(uint4*)(BHI + brow*40 + bcol) = wh4;
        *(uint4*)(BLO + brow*40 + bcol) = wl4;
    }
    __syncthreads();

    #pragma unroll 1
    for (int kt = 0; kt < 16; kt++) {
        const int buf = kt & 1;
        const __half* Ah = AHI + buf*5120;
        const __half* Al = ALO + buf*5120;
        const __half* Bh = BHI + buf*2560;
        const __half* Bl = BLO + buf*2560;

        if (kt < 15) {
            a_h0 = __ldcg((const uint4*)(Arh + (kt+1)*32));
            a_h1 = __ldcg((const uint4*)(Arh + (kt+1)*32 + 8));
            a_l0 = __ldcg((const uint4*)(Arl + (kt+1)*32));
            a_l1 = __ldcg((const uint4*)(Arl + (kt+1)*32 + 8));
            wh4 = *(const uint4*)(Wrowh + (kt+1)*32);
            wl4 = *(const uint4*)(Wrowl + (kt+1)*32);
        }

        #pragma unroll
        for (int k16 = 0; k16 < 2; k16++) {
            const int kb = k16*16 + tig*2;
            uint32_t ah[4][4], al[4][4];
            #pragma unroll
            for (int mi = 0; mi < 4; mi++) {
                const __half* arh = Ah + (wm + mi*16 + grp)*40;
                const __half* arl = Al + (wm + mi*16 + grp)*40;
                ah[mi][0] = *(const uint32_t*)(arh + kb);
                ah[mi][1] = *(const uint32_t*)(arh + 8*40 + kb);
                ah[mi][2] = *(const uint32_t*)(arh + kb + 8);
                ah[mi][3] = *(const uint32_t*)(arh + 8*40 + kb + 8);
                al[mi][0] = *(const uint32_t*)(arl + kb);
                al[mi][1] = *(const uint32_t*)(arl + 8*40 + kb);
                al[mi][2] = *(const uint32_t*)(arl + kb + 8);
                al[mi][3] = *(const uint32_t*)(arl + 8*40 + kb + 8);
            }
            #pragma unroll
            for (int nj = 0; nj < 2; nj++) {
                const __half* brh = Bh + (wn + nj*8 + grp)*40 + kb;
                const __half* brl = Bl + (wn + nj*8 + grp)*40 + kb;
                uint32_t b0h = *(const uint32_t*)(brh);
                uint32_t b1h = *(const uint32_t*)(brh + 8);
                uint32_t b0l = *(const uint32_t*)(brl);
                uint32_t b1l = *(const uint32_t*)(brl + 8);
                #pragma unroll
                for (int mi = 0; mi < 4; mi++) {
                    hmma_fp16(acc[mi][nj][0], acc[mi][nj][1], acc[mi][nj][2], acc[mi][nj][3],
                              ah[mi][0], ah[mi][1], ah[mi][2], ah[mi][3], b0h, b1h);
                    hmma_fp16(acc[mi][nj][0], acc[mi][nj][1], acc[mi][nj][2], acc[mi][nj][3],
                              ah[mi][0], ah[mi][1], ah[mi][2], ah[mi][3], b0l, b1l);
                    hmma_fp16(acc[mi][nj][0], acc[mi][nj][1], acc[mi][nj][2], acc[mi][nj][3],
                              al[mi][0], al[mi][1], al[mi][2], al[mi][3], b0h, b1h);
                }
            }
        }

        if (kt < 15) {
            const int nb = buf ^ 1;
            __half* ah = AHI + nb*5120 + arow*40 + acol;
            __half* al = ALO + nb*5120 + arow*40 + acol;
            *(uint4*)ah = a_h0; *(uint4*)(ah+8) = a_h1;
            *(uint4*)al = a_l0; *(uint4*)(al+8) = a_l1;
            *(uint4*)(BHI + nb*2560 + brow*40 + bcol) = wh4;
            *(uint4*)(BLO + nb*2560 + brow*40 + bcol) = wl4;
        }
        __syncthreads();
    }

    #pragma unroll
    for (int mi = 0; mi < 4; mi++) {
        #pragma unroll
        for (int nj = 0; nj < 2; nj++) {
            int m = wm + mi*16 + grp;
            int nc = wn + nj*8 + tig*2;
            float bx = bias[bn + nc], by = bias[bn + nc + 1];
            *(float2*)(Cout + (size_t)m*512 + bn + nc) =
                make_float2(acc[mi][nj][0] + bx, acc[mi][nj][1] + by);
            *(float2*)(Cout + (size_t)(m+8)*512 + bn + nc) =
                make_float2(acc[mi][nj][2] + bx, acc[mi][nj][3] + by);
        }
    }
    __syncthreads();
}

// ---- softmax + context (writes context hi/lo) ----
__device__ void att_soft(int b, const float* __restrict__ q,
                         const float* __restrict__ keys, const float* __restrict__ features,
                         const float* __restrict__ v_w, const float* __restrict__ v_b,
                         __half* __restrict__ coh, __half* __restrict__ col, float* sm)
{
    const int tid = threadIdx.x;
    float* qs = sm;
    float* vw = sm + 512;
    float* e  = sm + 1024;

    for (int i = tid; i < 512; i += 256) {
        qs[i] = __ldcg(q + b*512 + i);
        vw[i] = v_w[i];
    }
    __syncthreads();

    const int warp = tid >> 5, lane = tid & 31;
    for (int s = warp; s < SEQ; s += 8) {
        const float* kp = keys + ((size_t)b * SEQ + s) * 512;
        float acc = 0.f;
        #pragma unroll
        for (int k = lane; k < 512; k += 32)
            acc += tanhf(qs[k] + kp[k]) * vw[k];
        #pragma unroll
        for (int o = 16; o; o >>= 1) acc += __shfl_xor_sync(0xffffffffu, acc, o);
        if (!lane) e[s] = acc + v_b[0];
    }
    __syncthreads();

    if (warp == 0) {
        float v1 = (lane < SEQ) ? e[lane] : -1e30f;
        float v2 = (lane + 32 < SEQ) ? e[lane + 32] : -1e30f;
        float m = fmaxf(v1, v2);
        #pragma unroll
        for (int o = 16; o; o >>= 1) m = fmaxf(m, __shfl_xor_sync(0xffffffffu, m, o));
        float e1 = (lane < SEQ) ? expf(v1 - m) : 0.f;
        float e2 = (lane + 32 < SEQ) ? expf(v2 - m) : 0.f;
        float s = e1 + e2;
        #pragma unroll
        for (int o = 16; o; o >>= 1) s += __shfl_xor_sync(0xffffffffu, s, o);
        float inv = 1.f / s;
        if (lane < SEQ) e[lane] = e1 * inv;
        if (lane + 32 < SEQ) e[lane + 32] = e2 * inv;
    }
    __syncthreads();

    for (int k = tid; k < 512; k += 256) {
        float acc = 0.f;
        const float* f = features + (size_t)b * SEQ * 512 + k;
        #pragma unroll 7
        for (int s = 0; s < SEQ; s++) acc += e[s] * f[(size_t)s * 512];
        __half hi = __float2half_rn(acc);
        __half lo = __float2half_rn(acc - __half2float(hi));
        coh[b*512 + k] = hi;
        col[b*512 + k] = lo;
    }
    __syncthreads();
}

// ---- GRU tile ----
template<int NK>
__device__ void gru_tile(int nt, int kc,
    const __half* __restrict__ sAh, const __half* __restrict__ sAl, int ldA,
    const __half* __restrict__ sBh, const __half* __restrict__ sBl,
    const __half* __restrict__ sCh, const __half* __restrict__ sCl,
    const __half* __restrict__ Wh, const __half* __restrict__ Wl, int ldK,
    const float* __restrict__ bih, const float* __restrict__ bhh,
    const float* __restrict__ h_old, float* __restrict__ h_new,
    __half* __restrict__ hnh, __half* __restrict__ hnl,
    __half* __restrict__ hs_out, __half* smg)
{
    __half* AHI = smg;
    __half* ALO = AHI + 2*5120;
    __half* BHI = ALO + 2*5120;
    __half* BLO = BHI + 2*2560;

    const int tid = threadIdx.x;
    const int lane = tid & 31, wid = tid >> 5;
    const int wm = (wid & 1) * 64;
    const int wn = (wid >> 1) * 16;
    const int grp = lane >> 2, tig = lane & 3;
    const int bn = nt * 64;

    const __half *Ahg, *Alg; int ld;
    {
        int sel = kc >> 1;
        if (sel == 0)      { Ahg = sAh; Alg = sAl; ld = ldA; }
        else if (sel == 1) { Ahg = sBh; Alg = sBl; ld = 512; }
        else               { Ahg = sCh; Alg = sCl; ld = 512; }
    }
    const int koff = (kc & 1) * 256;

    const int arow = tid >> 1;
    const int acol = (tid & 1) * 16;
    const int brow = tid >> 2;
    const int bcol = (tid & 3) * 8;

    const __half* Arh = Ahg + (size_t)arow * ld + koff + acol;
    const __half* Arl = Alg + (size_t)arow * ld + koff + acol;
    const __half* Wrowh = Wh + (size_t)(bn + brow) * ldK + kc*256 + bcol;
    const __half* Wrowl = Wl + (size_t)(bn + brow) * ldK + kc*256 + bcol;

    float acc[4][2][4];
    #pragma unroll
    for (int i = 0; i < 4; i++)
        #pragma unroll
        for (int j = 0; j < 2; j++)
            #pragma unroll
            for (int k = 0; k < 4; k++) acc[i][j][k] = 0.f;

    uint4 a_h0, a_h1, a_l0, a_l1, wh4, wl4;
    a_h0 = __ldcg((const uint4*)(Arh));
    a_h1 = __ldcg((const uint4*)(Arh + 8));
    a_l0 = __ldcg((const uint4*)(Arl));
    a_l1 = __ldcg((const uint4*)(Arl + 8));
    wh4 = *(const uint4*)(Wrowh);
    wl4 = *(const uint4*)(Wrowl);
    {
        __half* ah = AHI + arow*40 + acol;
        __half* al = ALO + arow*40 + acol;
        *(uint4*)ah = a_h0; *(uint4*)(ah+8) = a_h1;
        *(uint4*)al = a_l0; *(uint4*)(al+8) = a_l1;
        *(uint4*)(BHI + brow*40 + bcol) = wh4;
        *(uint4*)(BLO + brow*40 + bcol) = wl4;
    }
    __syncthreads();

    #pragma unroll 1
    for (int kt = 0; kt < 8; kt++) {
        const int buf = kt & 1;
        const __half* Ah = AHI + buf*5120;
        const __half* Al = ALO + buf*5120;
        const __half* Bh = BHI + buf*2560;
        const __half* Bl = BLO + buf*2560;

        if (kt < 7) {
            a_h0 = __ldcg((const uint4*)(Arh + (kt+1)*32));
            a_h1 = __ldcg((const uint4*)(Arh + (kt+1)*32 + 8));
            a_l0 = __ldcg((const uint4*)(Arl + (kt+1)*32));
            a_l1 = __ldcg((const uint4*)(Arl + (kt+1)*32 + 8));
            wh4 = *(const uint4*)(Wrowh + (kt+1)*32);
            wl4 = *(const uint4*)(Wrowl + (kt+1)*32);
        }

        #pragma unroll
        for (int k16 = 0; k16 < 2; k16++) {
            const int kb = k16*16 + tig*2;
            uint32_t ah[4][4], al[4][4];
            #pragma unroll
            for (int mi = 0; mi < 4; mi++) {
                const __half* arh = Ah + (wm + mi*16 + grp)*40;
                const __half* arl = Al + (wm + mi*16 + grp)*40;
                ah[mi][0] = *(const uint32_t*)(arh + kb);
                ah[mi][1] = *(const uint32_t*)(arh + 8*40 + kb);
                ah[mi][2] = *(const uint32_t*)(arh + kb + 8);
                ah[mi][3] = *(const uint32_t*)(arh + 8*40 + kb + 8);
                al[mi][0] = *(const uint32_t*)(arl + kb);
                al[mi][1] = *(const uint32_t*)(arl + 8*40 + kb);
                al[mi][2] = *(const uint32_t*)(arl + kb + 8);
                al[mi][3] = *(const uint32_t*)(arl + 8*40 + kb + 8);
            }
            #pragma unroll
            for (int nj = 0; nj < 2; nj++) {
                const __half* brh = Bh + (wn + nj*8 + grp)*40 + kb;
                const __half* brl = Bl + (wn + nj*8 + grp)*40 + kb;
                uint32_t b0h = *(const uint32_t*)(brh);
                uint32_t b1h = *(const uint32_t*)(brh + 8);
                uint32_t b0l = *(const uint32_t*)(brl);
                uint32_t b1l = *(const uint32_t*)(brl + 8);
                #pragma unroll
                for (int mi = 0; mi < 4; mi++) {
                    hmma_fp16(acc[mi][nj][0], acc[mi][nj][1], acc[mi][nj][2], acc[mi][nj][3],
                              ah[mi][0], ah[mi][1], ah[mi][2], ah[mi][3], b0h, b1h);
                    hmma_fp16(acc[mi][nj][0], acc[mi][nj][1], acc[mi][nj][2], acc[mi][nj][3],
                              ah[mi][0], ah[mi][1], ah[mi][2], ah[mi][3], b0l, b1l);
                    hmma_fp16(acc[mi][nj][0], acc[mi][nj][1], acc[mi][nj][2], acc[mi][nj][3],
                              al[mi][0], al[mi][1], al[mi][2], al[mi][3], b0h, b1h);
                }
            }
        }

        if (kt < 7) {
            const int nb = buf ^ 1;
            __half* ah = AHI + nb*5120 + arow*40 + acol;
            __half* al = ALO + nb*5120 + arow*40 + acol;
            *(uint4*)ah = a_h0; *(uint4*)(ah+8) = a_h1;
            *(uint4*)al = a_l0; *(uint4*)(al+8) = a_l1;
            *(uint4*)(BHI + nb*2560 + brow*40 + bcol) = wh4;
            *(uint4*)(BLO + nb*2560 + brow*40 + bcol) = wl4;
        }
        __syncthreads();
    }

    {
        float* P = g_part + ((size_t)(kc*24 + nt)) * 8192;
        #pragma unroll
        for (int mi = 0; mi < 4; mi++) {
            #pragma unroll
            for (int nj = 0; nj < 2; nj++) {
                int m = wm + mi*16 + grp;
                int nc = wn + nj*8 + tig*2;
                *(float2*)(P + m*64 + nc)     = make_float2(acc[mi][nj][0], acc[mi][nj][1]);
                *(float2*)(P + (m+8)*64 + nc) = make_float2(acc[mi][nj][2], acc[mi][nj][3]);
            }
        }
    }

    __threadfence();
    __shared__ int sdone;
    if (tid == 0) {
        int g = nt & 7;
        int v = atomicAdd(&g_cnt[g], 1);
        int done = (v == 3*NK - 1);
        if (done) g_cnt[g] = 0;
        sdone = done;
    }
    __syncthreads();
    if (!sdone) return;
    __threadfence();

    const int g = nt & 7;
    const int cc = (tid & 15) * 4;
    const int c  = g*64 + cc;
    float4 bir = *(const float4*)(bih + c);
    float4 biz = *(const float4*)(bih + 512 + c);
    float4 bin = *(const float4*)(bih + 1024 + c);
    float4 bhr = *(const float4*)(bhh + c);
    float4 bhz = *(const float4*)(bhh + 512 + c);
    float4 bhn = *(const float4*)(bhh + 1024 + c);

    #pragma unroll
    for (int i = 0; i < 8; i++) {
        const int m = (tid >> 4) * 8 + i;
        float4 r4 = make_float4(0,0,0,0), z4 = r4, in4 = r4, hn4 = r4;
        #pragma unroll
        for (int kx = 0; kx < NK; kx++) {
            const float* Pr = g_part + ((size_t)(kx*24 + g))      * 8192 + m*64 + cc;
            const float* Pz = g_part + ((size_t)(kx*24 + 8 + g))  * 8192 + m*64 + cc;
            const float* Pn = g_part + ((size_t)(kx*24 + 16 + g)) * 8192 + m*64 + cc;
            float4 a = __ldcg((const float4*)Pr);
            r4.x += a.x; r4.y += a.y; r4.z += a.z; r4.w += a.w;
            a = __ldcg((const float4*)Pz);
            z4.x += a.x; z4.y += a.y; z4.z += a.z; z4.w += a.w;
            a = __ldcg((const float4*)Pn);
            if (kx < NK-2) { in4.x += a.x; in4.y += a.y; in4.z += a.z; in4.w += a.w; }
            else           { hn4.x += a.x; hn4.y += a.y; hn4.z += a.z; hn4.w += a.w; }
        }
        float4 ho = __ldcg((const float4*)(h_old + (size_t)m*512 + c));
        float hv[4];
        #pragma unroll
        for (int q = 0; q < 4; q++) {
            float rp = ((float*)&r4)[q] + ((float*)&bir)[q] + ((float*)&bhr)[q];
            float zp = ((float*)&z4)[q] + ((float*)&biz)[q] + ((float*)&bhz)[q];
            float ip = ((float*)&in4)[q] + ((float*)&bin)[q];
            float hp = ((float*)&hn4)[q] + ((float*)&bhn)[q];
            float r = 1.f / (1.f + expf(-rp));
            float z = 1.f / (1.f + expf(-zp));
            float n = tanhf(ip + r * hp);
            hv[q] = (1.f - z) * n + z * ((float*)&ho)[q];
        }
        *(float4*)(h_new + (size_t)m*512 + c) = make_float4(hv[0], hv[1], hv[2], hv[3]);
        uint32_t hi0, lo0, hi1, lo1;
        split2(hv[0], hv[1], hi0, lo0);
        split2(hv[2], hv[3], hi1, lo1);
        *(uint32_t*)(hnh + (size_t)m*512 + c)     = hi0;
        *(uint32_t*)(hnh + (size_t)m*512 + c + 2) = hi1;
        *(uint32_t*)(hnl + (size_t)m*512 + c)     = lo0;
        *(uint32_t*)(hnl + (size_t)m*512 + c + 2) = lo1;
        if (hs_out) {
            uint2 ov; ov.x = hi0; ov.y = hi1;
            *(uint2*)(hs_out + (size_t)m*512 + c) = ov;
        }
    }
}

// ---- persistent chain kernel (6 phases/step) ----
__global__ void __launch_bounds__(256, 1) chain_kernel(
    const float* __restrict__ features,
    const float* __restrict__ bq,
    const float* __restrict__ v_w, const float* __restrict__ v_b,
    const float* __restrict__ bhh0,
    const float* __restrict__ bihr, const float* __restrict__ bhhr)
{
    extern __shared__ __half smg[];
    float* smf = (float*)smg;

    for (int t = 0; t < NSTEP; t++) {
        const int ho = (t & 1) * (4 * BH);
        const int no = ((t & 1) ^ 1) * (4 * BH);
        const float* hold = g_h + ho;
        float*       hnew = g_h + no;

        // Q
        for (int w = blockIdx.x; w < 8; w += gridDim.x)
            lin_tile(w, g_hh + ho + 3*BH, g_hl + ho + 3*BH,
                     g_lwh, g_lwl, bq, g_q, smg);
        grid_bar();

        // S: softmax + context -> hi/lo
        for (int b = blockIdx.x; b < BATCH; b += gridDim.x)
            att_soft(b, g_q, g_keys, features, v_w, v_b, g_coh, g_col, smf);
        grid_bar();

        // L0 (fc0 folded into W0c; srcB = raw context)
        for (int w = blockIdx.x; w < 144; w += gridDim.x)
            gru_tile<6>(w % 24, w / 24,
                        g_xh + t*HID, g_xl + t*HID, NSTEP*HID,
                        g_coh, g_col,
                        g_hh + ho, g_hl + ho,
                        g_wh, g_wl, 1536, g_bihe, bhh0, hold, hnew,
                        g_hh + no, g_hl + no, nullptr, smg);
        grid_bar();

        // L1..L3
        for (int l = 1; l < 4; l++) {
            const size_t off = (size_t)1536*1536 + (size_t)(l-1)*1536*1024;
            __half* hs_out = (l == 3) ? (g_hsh + t * BH) : nullptr;
            for (int w = blockIdx.x; w < 96; w += gridDim.x)
                gru_tile<4>(w % 24, w / 24,
                            g_hh + no + (l-1)*BH, g_hl + no + (l-1)*BH, 512,
                            g_hh + ho + l*BH, g_hl + ho + l*BH,
                            nullptr, nullptr,
                            g_wh + off, g_wl + off, 1024,
                            bihr + (l-1)*1536, bhhr + (l-1)*1536,
                            hold + l*BH, hnew + l*BH,
                            g_hh + no + l*BH, g_hl + no + l*BH, hs_out, smg);
            grid_bar();
        }
    }
}

// ---------------- fc2 via mma.sync fp16 ----------------
#define F2_PAD  40
#define F2_ASZ  (128*F2_PAD)
#define F2_BSZ  (256*F2_PAD)
#define F2_SMEM ((2*F2_ASZ + 2*F2_BSZ)*2)

__global__ void __launch_bounds__(256, 1) fc2_mma_fp16(
    const __half* __restrict__ A, const __half* __restrict__ Bw,
    const float* __restrict__ bias, float* __restrict__ out)
{
    extern __shared__ __half smh[];
    __half* As = smh;
    __half* Bs = smh + 2*F2_ASZ;

    const int tid  = threadIdx.x;
    const int lane = tid & 31, wid = tid >> 5;
    const int wm = (wid >> 2) * 64;
    const int wn = (wid & 3)  * 64;
    const int grp = lane >> 2;
    const int tig = lane & 3;
    const int bn = blockIdx.x * 256;
    const int t  = blockIdx.y;

    const __half* Ab = A  + (size_t)t  * 128 * 512;
    const __half* Bb = Bw + (size_t)bn * 512;

    float acc[4][8][4];
    #pragma unroll
    for (int i = 0; i < 4; i++)
        #pragma unroll
        for (int j = 0; j < 8; j++)
            #pragma unroll
            for (int k = 0; k < 4; k++) acc[i][j][k] = 0.f;

    uint4 ra[2], rb[4];
    #pragma unroll
    for (int p = 0; p < 2; p++) {
        int idx = tid + p * 256;
        int row = idx >> 2, c8 = (idx & 3) * 8;
        ra[p] = *(const uint4*)(Ab + (size_t)row * 512 + c8);
    }
    #pragma unroll
    for (int p = 0; p < 4; p++) {
        int idx = tid + p * 256;
        int row = idx >> 2, c8 = (idx & 3) * 8;
        rb[p] = *(const uint4*)(Bb + (size_t)row * 512 + c8);
    }
    #pragma unroll
    for (int p = 0; p < 2; p++) {
        int idx = tid + p * 256;
        int row = idx >> 2, c8 = (idx & 3) * 8;
        *(uint4*)(As + row*F2_PAD + c8) = ra[p];
    }
    #pragma unroll
    for (int p = 0; p < 4; p++) {
        int idx = tid + p * 256;
        int row = idx >> 2, c8 = (idx & 3) * 8;
        *(uint4*)(Bs + row*F2_PAD + c8) = rb[p];
    }
    __syncthreads();

    #pragma unroll 1
    for (int kt = 0; kt < 16; kt++) {
        const int buf = kt & 1;
        const __half* Asb = As + buf * F2_ASZ;
        const __half* Bsb = Bs + buf * F2_BSZ;

        if (kt < 15) {
            const __half* Aq = Ab + (kt+1)*32;
            const __half* Bq = Bb + (kt+1)*32;
            #pragma unroll
            for (int p = 0; p < 2; p++) {
                int idx = tid + p * 256;
                int row = idx >> 2, c8 = (idx & 3) * 8;
                ra[p] = *(const uint4*)(Aq + (size_t)row * 512 + c8);
            }
            #pragma unroll
            for (int p = 0; p < 4; p++) {
                int idx = tid + p * 256;
                int row = idx >> 2, c8 = (idx & 3) * 8;
                rb[p] = *(const uint4*)(Bq + (size_t)row * 512 + c8);
            }
        }

        #pragma unroll
        for (int k16 = 0; k16 < 2; k16++) {
            const int kb = k16*16 + tig*2;
            uint32_t af[4][4];
            #pragma unroll
            for (int mi = 0; mi < 4; mi++) {
                const __half* ar = Asb + (wm + mi*16 + grp)*F2_PAD;
                af[mi][0] = *(const uint32_t*)(ar + kb);
                af[mi][1] = *(const uint32_t*)(ar + 8*F2_PAD + kb);
                af[mi][2] = *(const uint32_t*)(ar + kb + 8);
                af[mi][3] = *(const uint32_t*)(ar + 8*F2_PAD + kb + 8);
            }
            #pragma unroll
            for (int nj = 0; nj < 8; nj++) {
                const __half* br = Bsb + (wn + nj*8 + grp)*F2_PAD + kb;
                uint32_t b0 = *(const uint32_t*)(br);
                uint32_t b1 = *(const uint32_t*)(br + 8);
                #pragma unroll
                for (int mi = 0; mi < 4; mi++)
                    hmma_fp16(acc[mi][nj][0], acc[mi][nj][1], acc[mi][nj][2], acc[mi][nj][3],
                              af[mi][0], af[mi][1], af[mi][2], af[mi][3], b0, b1);
            }
        }

        if (kt < 15) {
            __half* Asn = As + (buf ^ 1) * F2_ASZ;
            __half* Bsn = Bs + (buf ^ 1) * F2_BSZ;
            #pragma unroll
            for (int p = 0; p < 2; p++) {
                int idx = tid + p * 256;
                int row = idx >> 2, c8 = (idx & 3) * 8;
                *(uint4*)(Asn + row*F2_PAD + c8) = ra[p];
            }
            #pragma unroll
            for (int p = 0; p < 4; p++) {
                int idx = tid + p * 256;
                int row = idx >> 2, c8 = (idx & 3) * 8;
                *(uint4*)(Bsn + row*F2_PAD + c8) = rb[p];
            }
        }
        __syncthreads();
    }

    #pragma unroll
    for (int mi = 0; mi < 4; mi++) {
        const int b0 = wm + mi*16 + grp;
        float* o0 = out + ((size_t)b0       * NSTEP + t) * VOCAB + bn + wn;
        float* o8 = out + ((size_t)(b0 + 8) * NSTEP + t) * VOCAB + bn + wn;
        #pragma unroll
        for (int nj = 0; nj < 8; nj++) {
            const int n = nj*8 + 2*tig;
            float bx = bias[bn + wn + n];
            float by = bias[bn + wn + n + 1];
            *(float2*)(o0 + n) = make_float2(acc[mi][nj][0] + bx, acc[mi][nj][1] + by);
            *(float2*)(o8 + n) = make_float2(acc[mi][nj][2] + bx, acc[mi][nj][3] + by);
        }
    }
}

// ---------------- host launch ----------------
extern "C" void kernel_launch(void* const* d_in, const int* in_sizes, int n_in,
                              void* d_out, int out_size)
{
    const float* features = (const float*)d_in[0];
    const int*   caps     = (const int*)  d_in[1];
    const float* emb      = (const float*)d_in[2];
    const float* fc1_w    = (const float*)d_in[3];
    const float* fc1_b    = (const float*)d_in[4];
    const float* fc0_w    = (const float*)d_in[5];
    const float* fc0_b    = (const float*)d_in[6];
    const float* wq       = (const float*)d_in[7];
    const float* bq       = (const float*)d_in[8];
    const float* wk       = (const float*)d_in[9];
    const float* bk       = (const float*)d_in[10];
    const float* v_w      = (const float*)d_in[11];
    const float* v_b      = (const float*)d_in[12];
    const float* wih0     = (const float*)d_in[13];
    const float* whh0     = (const float*)d_in[14];
    const float* bih0     = (const float*)d_in[15];
    const float* bhh0     = (const float*)d_in[16];
    const float* wihr     = (const float*)d_in[17];
    const float* whhr     = (const float*)d_in[18];
    const float* bihr     = (const float*)d_in[19];
    const float* bhhr     = (const float*)d_in[20];
    const float* fc2_w    = (const float*)d_in[21];
    const float* fc2_b    = (const float*)d_in[22];
    float* out = (float*)d_out;

    float* pkeys;
    __half *phsh, *pw2h;
    cudaGetSymbolAddress((void**)&pkeys, g_keys);
    cudaGetSymbolAddress((void**)&phsh,  g_hsh);
    cudaGetSymbolAddress((void**)&pw2h,  g_w2h);

    cudaFuncSetAttribute(fc2_mma_fp16, cudaFuncAttributeMaxDynamicSharedMemorySize, F2_SMEM);
    cudaFuncSetAttribute(keys_mma,     cudaFuncAttributeMaxDynamicSharedMemorySize, K_SMEMB);
    cudaFuncSetAttribute(chain_kernel, cudaFuncAttributeMaxDynamicSharedMemorySize, GR_SMEM);
    cudaFuncSetAttribute(xgemm_mma,    cudaFuncAttributeMaxDynamicSharedMemorySize, GR_SMEM);
    cudaFuncSetAttribute(w0c_mma,      cudaFuncAttributeMaxDynamicSharedMemorySize, GR_SMEM);

    int nsm = 0;
    cudaDeviceGetAttribute(&nsm, cudaDevAttrMultiProcessorCount, 0);
    int nb = nsm;
    if (nb > 144) nb = 144;

    // chain is 6th launch (ncu -s 5 -c 1)
    init_kernel<<<1030, 256>>>(wih0, fc0_b, bih0);                                // 1
    wsplit_all<<<11840, 256>>>(wih0, whh0, wihr, whhr, wq, fc0_w, fc1_w, fc2_w);  // 2
    w0c_mma<<<dim3(8, 12), 256, GR_SMEM>>>(wih0);                                 // 3
    xgemm_mma<<<dim3(8, 15), 256, GR_SMEM>>>(emb, caps, fc1_b);                   // 4
    keys_mma<<<dim3(2, 49), 256, K_SMEMB>>>(features, wk, bk, pkeys);             // 5

    chain_kernel<<<nb, 256, GR_SMEM>>>(features, bq, v_w, v_b,                    // 6
                                       bhh0, bihr, bhhr);

    fc2_mma_fp16<<<dim3(VOCAB/256, NSTEP), 256, F2_SMEM>>>(phsh, pw2h, fc2_b, out);  // 7
}

// round 12
// speedup vs baseline: 1.4034x; 1.0626x over previous
#include <cuda_runtime.h>
#include <cuda_fp16.h>
#include <math.h>
#include <cstdint>

#define BATCH 128
#define SEQ   49
#define HID   512
#define VOCAB 32000
#define NSTEP 15
#define BH    (BATCH*HID)

// ---------------- device scratch ----------------
__device__ float  g_keys[BATCH*SEQ*HID];
__device__ float  g_qp[2*BH];               // Q K-split partials
__device__ float  g_h[2*4*BH];
__device__ __half g_hh[2*4*BH];
__device__ __half g_hl[2*4*BH];
__device__ __half g_xh[BATCH*NSTEP*HID];
__device__ __half g_xl[BATCH*NSTEP*HID];
__device__ __half g_coh[BH], g_col[BH];
__device__ __half g_hsh[NSTEP*BH];
__device__ float  g_part[6*3*BH];
__device__ __half g_w2h[VOCAB*HID];
#define WG_TOT (1536*1536 + 3*1536*1024)
__device__ __half g_wh[WG_TOT];
__device__ __half g_wl[WG_TOT];
__device__ __half g_lwh[3*HID*HID];         // [wq | fc0^T | fc1] hi
__device__ __half g_lwl[3*HID*HID];
__device__ float  g_bihe[1536];
__device__ int    g_cnt[8];
__device__ unsigned g_bcnt = 0;
__device__ unsigned g_bgen = 0;

// ---------------- init (+ folded bias) ----------------
__global__ void init_kernel(const float* __restrict__ wih0,
                            const float* __restrict__ fc0_b,
                            const float* __restrict__ bih0) {
    if (blockIdx.x < 1024) {
        int idx = blockIdx.x * 256 + threadIdx.x;
        if (idx < 4*BH) {
            g_h[idx] = 0.f;
            g_hh[idx] = __float2half(0.f);
            g_hl[idx] = __float2half(0.f);
        }
        if (blockIdx.x == 0 && threadIdx.x < 8) g_cnt[threadIdx.x] = 0;
        if (blockIdx.x == 0 && threadIdx.x == 0) { g_bcnt = 0; }
    } else {
        int i = (blockIdx.x - 1024) * 256 + threadIdx.x;
        if (i < 1536) {
            const float* wr = wih0 + (size_t)i * 1024 + 512;
            float s = 0.f;
            #pragma unroll 8
            for (int j = 0; j < 512; j += 4) {
                float4 w = *(const float4*)(wr + j);
                float4 b = *(const float4*)(fc0_b + j);
                s += w.x*b.x + w.y*b.y + w.z*b.z + w.w*b.w;
            }
            g_bihe[i] = bih0[i] + s;
        }
    }
}

// ---------------- split helpers ----------------
__device__ __forceinline__ void split8(const float* sp, uint4& hiv, uint4& lov) {
    uint32_t hi[4], lo[4];
    #pragma unroll
    for (int j = 0; j < 4; j++) {
        float a = sp[2*j], b = sp[2*j + 1];
        __half2 h2 = __floats2half2_rn(a, b);
        float2 bb = __half22float2(h2);
        __half2 l2 = __floats2half2_rn(a - bb.x, b - bb.y);
        hi[j] = *(uint32_t*)&h2; lo[j] = *(uint32_t*)&l2;
    }
    hiv = make_uint4(hi[0], hi[1], hi[2], hi[3]);
    lov = make_uint4(lo[0], lo[1], lo[2], lo[3]);
}
__device__ __forceinline__ void split2(float a, float b, uint32_t& hi, uint32_t& lo) {
    __half2 h2 = __floats2half2_rn(a, b);
    float2 bb = __half22float2(h2);
    __half2 l2 = __floats2half2_rn(a - bb.x, b - bb.y);
    hi = *(uint32_t*)&h2; lo = *(uint32_t*)&l2;
}

// ---------------- ALL weight prep in ONE kernel ----------------
__global__ void wsplit_all(const float* __restrict__ wih0, const float* __restrict__ whh0,
                           const float* __restrict__ wihr, const float* __restrict__ whhr,
                           const float* __restrict__ wq,   const float* __restrict__ fc0_w,
                           const float* __restrict__ fc1_w, const float* __restrict__ fc2_w) {
    int i = blockIdx.x * 256 + threadIdx.x;
    const int C0 = 294912, CL = 196608, CW = 32768;
    const int B1 = C0 + 3*CL, B2 = B1 + 3*CW, B3 = B2 + VOCAB*HID/8;
    if (i >= B3) return;
    if (i >= B2) {
        int j = i - B2;
        int row = j >> 6, c = (j & 63) * 8;
        const float* sp = fc2_w + (size_t)row*512 + c;
        float4 v0 = *(const float4*)sp, v1 = *(const float4*)(sp + 4);
        __half2 h0 = __floats2half2_rn(v0.x, v0.y);
        __half2 h1 = __floats2half2_rn(v0.z, v0.w);
        __half2 h2 = __floats2half2_rn(v1.x, v1.y);
        __half2 h3 = __floats2half2_rn(v1.z, v1.w);
        uint4 o;
        o.x = *(uint32_t*)&h0; o.y = *(uint32_t*)&h1;
        o.z = *(uint32_t*)&h2; o.w = *(uint32_t*)&h3;
        *(uint4*)(g_w2h + (size_t)row*512 + c) = o;
        return;
    }
    const float* sp;
    __half *dh, *dl;
    size_t doff;
    if (i < C0) {
        int row = i / 192, c = (i - row*192) * 8;
        sp = (c < 1024) ? (wih0 + (size_t)row*1024 + c) : (whh0 + (size_t)row*512 + (c - 1024));
        dh = g_wh; dl = g_wl; doff = (size_t)row*1536 + c;
    } else if (i < B1) {
        int j = i - C0;
        int l = j / CL; j -= l*CL;
        int row = j / 128, c = (j - row*128) * 8;
        const float* wih = wihr + (size_t)l*1536*512;
        const float* whh = whhr + (size_t)l*1536*512;
        sp = (c < 512) ? (wih + (size_t)row*512 + c) : (whh + (size_t)row*512 + (c - 512));
        dh = g_wh; dl = g_wl;
        doff = (size_t)1536*1536 + (size_t)l*1536*1024 + (size_t)row*1024 + c;
    } else {
        int j = i - B1;
        int seg = j / CW; j -= seg*CW;
        int row = j / 64, c = (j - row*64) * 8;
        if (seg == 1) {
            const float* s0 = fc0_w + (size_t)row*512 + c;
            #pragma unroll
            for (int u = 0; u < 8; u++) {
                float v = s0[u];
                __half h = __float2half_rn(v);
                __half l = __float2half_rn(v - __half2float(h));
                size_t d = (size_t)HID*HID + (size_t)(c + u)*512 + row;
                g_lwh[d] = h;
                g_lwl[d] = l;
            }
            return;
        }
        const float* w = (seg == 0) ? wq : fc1_w;
        sp = w + (size_t)row*512 + c;
        dh = g_lwh; dl = g_lwl;
        doff = (size_t)seg*HID*HID + (size_t)row*512 + c;
    }
    uint4 hiv, lov;
    split8(sp, hiv, lov);
    *(uint4*)(dh + doff) = hiv;
    *(uint4*)(dl + doff) = lov;
}

// ---------------- MMA helpers ----------------
__device__ __forceinline__ void hmma_tf32(float& c0, float& c1, float& c2, float& c3,
                                          uint32_t a0, uint32_t a1, uint32_t a2, uint32_t a3,
                                          uint32_t b0, uint32_t b1) {
    asm volatile("mma.sync.aligned.m16n8k8.row.col.f32.tf32.tf32.f32 "
                 "{%0,%1,%2,%3}, {%4,%5,%6,%7}, {%8,%9}, {%0,%1,%2,%3};"
                 : "+f"(c0), "+f"(c1), "+f"(c2), "+f"(c3)
                 : "r"(a0), "r"(a1), "r"(a2), "r"(a3), "r"(b0), "r"(b1));
}
__device__ __forceinline__ void hmma_fp16(float& c0, float& c1, float& c2, float& c3,
                                          uint32_t a0, uint32_t a1, uint32_t a2, uint32_t a3,
                                          uint32_t b0, uint32_t b1) {
    asm volatile("mma.sync.aligned.m16n8k16.row.col.f32.f16.f16.f32 "
                 "{%0,%1,%2,%3}, {%4,%5,%6,%7}, {%8,%9}, {%0,%1,%2,%3};"
                 : "+f"(c0), "+f"(c1), "+f"(c2), "+f"(c3)
                 : "r"(a0), "r"(a1), "r"(a2), "r"(a3), "r"(b0), "r"(b1));
}

#define GR_SMEM ((2*5120*2 + 2*2560*2)*2)   // 61440 bytes

// ---------------- W0c fold ----------------
__global__ void __launch_bounds__(256, 1) w0c_mma(const float* __restrict__ wih0)
{
    extern __shared__ __half smg[];
    __half* AHI = smg;
    __half* ALO = AHI + 2*5120;
    __half* BHI = ALO + 2*5120;
    __half* BLO = BHI + 2*2560;

    const int tid = threadIdx.x;
    const int lane = tid & 31, wid = tid >> 5;
    const int wm = (wid & 1) * 64;
    const int wn = (wid >> 1) * 16;
    const int grp = lane >> 2, tig = lane & 3;
    const int bn = blockIdx.x * 64;
    const int bm = blockIdx.y * 128;

    const int arow = tid >> 1;
    const int acol = (tid & 1) * 16;
    const int brow = tid >> 2;
    const int bcol = (tid & 3) * 8;

    const float*  Arow  = wih0 + (size_t)(bm + arow) * 1024 + 512 + acol;
    const __half* Wrowh = g_lwh + (size_t)HID*HID + (size_t)(bn + brow) * 512 + bcol;
    const __half* Wrowl = g_lwl + (size_t)HID*HID + (size_t)(bn + brow) * 512 + bcol;

    float acc[4][2][4];
    #pragma unroll
    for (int i = 0; i < 4; i++)
        #pragma unroll
        for (int j = 0; j < 2; j++)
            #pragma unroll
            for (int k = 0; k < 4; k++) acc[i][j][k] = 0.f;

    float fa[16];
    uint4 wh4, wl4;
    #pragma unroll
    for (int p = 0; p < 4; p++)
        *(float4*)&fa[p*4] = *(const float4*)(Arow + p*4);
    wh4 = *(const uint4*)(Wrowh);
    wl4 = *(const uint4*)(Wrowl);
    {
        uint4 h0, l0, h1, l1;
        split8(&fa[0], h0, l0); split8(&fa[8], h1, l1);
        __half* ah = AHI + arow*40 + acol;
        __half* al = ALO + arow*40 + acol;
        *(uint4*)ah = h0; *(uint4*)(ah+8) = h1;
        *(uint4*)al = l0; *(uint4*)(al+8) = l1;
        *(uint4*)(BHI + brow*40 + bcol) = wh4;
        *(uint4*)(BLO + brow*40 + bcol) = wl4;
    }
    __syncthreads();

    #pragma unroll 1
    for (int kt = 0; kt < 16; kt++) {
        const int buf = kt & 1;
        const __half* Ah = AHI + buf*5120;
        const __half* Al = ALO + buf*5120;
        const __half* Bh = BHI + buf*2560;
        const __half* Bl = BLO + buf*2560;

        if (kt < 15) {
            #pragma unroll
            for (int p = 0; p < 4; p++)
                *(float4*)&fa[p*4] = *(const float4*)(Arow + (kt+1)*32 + p*4);
            wh4 = *(const uint4*)(Wrowh + (kt+1)*32);
            wl4 = *(const uint4*)(Wrowl + (kt+1)*32);
        }

        #pragma unroll
        for (int k16 = 0; k16 < 2; k16++) {
            const int kb = k16*16 + tig*2;
            uint32_t ah[4][4], al[4][4];
            #pragma unroll
            for (int mi = 0; mi < 4; mi++) {
                const __half* arh = Ah + (wm + mi*16 + grp)*40;
                const __half* arl = Al + (wm + mi*16 + grp)*40;
                ah[mi][0] = *(const uint32_t*)(arh + kb);
                ah[mi][1] = *(const uint32_t*)(arh + 8*40 + kb);
                ah[mi][2] = *(const uint32_t*)(arh + kb + 8);
                ah[mi][3] = *(const uint32_t*)(arh + 8*40 + kb + 8);
                al[mi][0] = *(const uint32_t*)(arl + kb);
                al[mi][1] = *(const uint32_t*)(arl + 8*40 + kb);
                al[mi][2] = *(const uint32_t*)(arl + kb + 8);
                al[mi][3] = *(const uint32_t*)(arl + 8*40 + kb + 8);
            }
            #pragma unroll
            for (int nj = 0; nj < 2; nj++) {
                const __half* brh = Bh + (wn + nj*8 + grp)*40 + kb;
                const __half* brl = Bl + (wn + nj*8 + grp)*40 + kb;
                uint32_t b0h = *(const uint32_t*)(brh);
                uint32_t b1h = *(const uint32_t*)(brh + 8);
                uint32_t b0l = *(const uint32_t*)(brl);
                uint32_t b1l = *(const uint32_t*)(brl + 8);
                #pragma unroll
                for (int mi = 0; mi < 4; mi++) {
                    hmma_fp16(acc[mi][nj][0], acc[mi][nj][1], acc[mi][nj][2], acc[mi][nj][3],
                              ah[mi][0], ah[mi][1], ah[mi][2], ah[mi][3], b0h, b1h);
                    hmma_fp16(acc[mi][nj][0], acc[mi][nj][1], acc[mi][nj][2], acc[mi][nj][3],
                              ah[mi][0], ah[mi][1], ah[mi][2], ah[mi][3], b0l, b1l);
                    hmma_fp16(acc[mi][nj][0], acc[mi][nj][1], acc[mi][nj][2], acc[mi][nj][3],
                              al[mi][0], al[mi][1], al[mi][2], al[mi][3], b0h, b1h);
                }
            }
        }

        if (kt < 15) {
            const int nb = buf ^ 1;
            uint4 h0, l0, h1, l1;
            split8(&fa[0], h0, l0); split8(&fa[8], h1, l1);
            __half* ah = AHI + nb*5120 + arow*40 + acol;
            __half* al = ALO + nb*5120 + arow*40 + acol;
            *(uint4*)ah = h0; *(uint4*)(ah+8) = h1;
            *(uint4*)al = l0; *(uint4*)(al+8) = l1;
            *(uint4*)(BHI + nb*2560 + brow*40 + bcol) = wh4;
            *(uint4*)(BLO + nb*2560 + brow*40 + bcol) = wl4;
        }
        __syncthreads();
    }

    #pragma unroll
    for (int mi = 0; mi < 4; mi++) {
        #pragma unroll
        for (int nj = 0; nj < 2; nj++) {
            int m = wm + mi*16 + grp;
            int k = bn + wn + nj*8 + tig*2;
            uint32_t hi0, lo0, hi1, lo1;
            split2(acc[mi][nj][0], acc[mi][nj][1], hi0, lo0);
            split2(acc[mi][nj][2], acc[mi][nj][3], hi1, lo1);
            size_t o0 = (size_t)(bm + m) * 1536 + 512 + k;
            size_t o8 = (size_t)(bm + m + 8) * 1536 + 512 + k;
            *(uint32_t*)(g_wh + o0) = hi0;
            *(uint32_t*)(g_wl + o0) = lo0;
            *(uint32_t*)(g_wh + o8) = hi1;
            *(uint32_t*)(g_wl + o8) = lo1;
        }
    }
}

// ---------------- keys via mma.sync tf32 ----------------
#define KPAD   36
#define K_ASZ  (128*KPAD)
#define K_BSZ  (256*KPAD)
#define K_SMEMB ((2*K_ASZ + 2*K_BSZ)*4)

__global__ void __launch_bounds__(256, 1) keys_mma(
    const float* __restrict__ A, const float* __restrict__ Bw,
    const float* __restrict__ bias, float* __restrict__ C)
{
    extern __shared__ float smf[];
    float* As = smf;
    float* Bs = smf + 2*K_ASZ;

    const int tid  = threadIdx.x;
    const int lane = tid & 31, wid = tid >> 5;
    const int wm = (wid >> 2) * 64;
    const int wn = (wid & 3)  * 64;
    const int grp = lane >> 2;
    const int tig = lane & 3;
    const int bn = blockIdx.x * 256;
    const int bm = blockIdx.y * 128;

    const float* Ab = A  + (size_t)bm * 512;
    const float* Bb = Bw + (size_t)bn * 512;

    const int lrowA = tid >> 3;
    const int lc4   = (tid & 7) * 4;

    float acc[4][8][4];
    #pragma unroll
    for (int i = 0; i < 4; i++)
        #pragma unroll
        for (int j = 0; j < 8; j++)
            #pragma unroll
            for (int k = 0; k < 4; k++) acc[i][j][k] = 0.f;

    float4 ra[4], rb[8];
    #pragma unroll
    for (int p = 0; p < 4; p++)
        ra[p] = *(const float4*)(Ab + (size_t)(p*32 + lrowA) * 512 + lc4);
    #pragma unroll
    for (int p = 0; p < 8; p++)
        rb[p] = *(const float4*)(Bb + (size_t)(p*32 + lrowA) * 512 + lc4);
    #pragma unroll
    for (int p = 0; p < 4; p++)
        *(float4*)(As + (p*32 + lrowA)*KPAD + lc4) = ra[p];
    #pragma unroll
    for (int p = 0; p < 8; p++)
        *(float4*)(Bs + (p*32 + lrowA)*KPAD + lc4) = rb[p];
    __syncthreads();

    #pragma unroll 1
    for (int kt = 0; kt < 16; kt++) {
        const int buf = kt & 1;
        const float* Asb = As + buf * K_ASZ;
        const float* Bsb = Bs + buf * K_BSZ;

        if (kt < 15) {
            const float* Aq = Ab + (kt+1)*32;
            const float* Bq = Bb + (kt+1)*32;
            #pragma unroll
            for (int p = 0; p < 4; p++)
                ra[p] = *(const float4*)(Aq + (size_t)(p*32 + lrowA) * 512 + lc4);
            #pragma unroll
            for (int p = 0; p < 8; p++)
                rb[p] = *(const float4*)(Bq + (size_t)(p*32 + lrowA) * 512 + lc4);
        }

        #pragma unroll
        for (int k8 = 0; k8 < 4; k8++) {
            const int kc = k8*8 + tig;
            uint32_t af[4][4];
            #pragma unroll
            for (int mi = 0; mi < 4; mi++) {
                const float* ar = Asb + (wm + mi*16 + grp)*KPAD;
                af[mi][0] = __float_as_uint(ar[kc]);
                af[mi][1] = __float_as_uint(ar[8*KPAD + kc]);
                af[mi][2] = __float_as_uint(ar[kc + 4]);
                af[mi][3] = __float_as_uint(ar[8*KPAD + kc + 4]);
            }
            #pragma unroll
            for (int nj = 0; nj < 8; nj++) {
                const float* br = Bsb + (wn + nj*8 + grp)*KPAD + k8*8;
                uint32_t b0 = __float_as_uint(br[tig]);
                uint32_t b1 = __float_as_uint(br[tig + 4]);
                #pragma unroll
                for (int mi = 0; mi < 4; mi++)
                    hmma_tf32(acc[mi][nj][0], acc[mi][nj][1], acc[mi][nj][2], acc[mi][nj][3],
                              af[mi][0], af[mi][1], af[mi][2], af[mi][3], b0, b1);
            }
        }

        if (kt < 15) {
            float* Asn = As + (buf ^ 1) * K_ASZ;
            float* Bsn = Bs + (buf ^ 1) * K_BSZ;
            #pragma unroll
            for (int p = 0; p < 4; p++)
                *(float4*)(Asn + (p*32 + lrowA)*KPAD + lc4) = ra[p];
            #pragma unroll
            for (int p = 0; p < 8; p++)
                *(float4*)(Bsn + (p*32 + lrowA)*KPAD + lc4) = rb[p];
        }
        __syncthreads();
    }

    #pragma unroll
    for (int mi = 0; mi < 4; mi++) {
        const int m = bm + wm + mi*16 + grp;
        #pragma unroll
        for (int nj = 0; nj < 8; nj++) {
            const int n = bn + wn + nj*8 + 2*tig;
            float bx = bias[n], by = bias[n + 1];
            *(float2*)(C + (size_t)m * 512 + n) =
                make_float2(acc[mi][nj][0] + bx, acc[mi][nj][1] + by);
            *(float2*)(C + (size_t)(m + 8) * 512 + n) =
                make_float2(acc[mi][nj][2] + bx, acc[mi][nj][3] + by);
        }
    }
}

// ---------------- x precompute ----------------
__global__ void __launch_bounds__(256, 1) xgemm_mma(
    const float* __restrict__ emb, const int* __restrict__ caps,
    const float* __restrict__ bias)
{
    extern __shared__ __half smg[];
    __half* AHI = smg;
    __half* ALO = AHI + 2*5120;
    __half* BHI = ALO + 2*5120;
    __half* BLO = BHI + 2*2560;

    const int tid = threadIdx.x;
    const int lane = tid & 31, wid = tid >> 5;
    const int wm = (wid & 1) * 64;
    const int wn = (wid >> 1) * 16;
    const int grp = lane >> 2, tig = lane & 3;
    const int bn = blockIdx.x * 64;
    const int t  = blockIdx.y;

    const int arow = tid >> 1;
    const int acol = (tid & 1) * 16;
    const int brow = tid >> 2;
    const int bcol = (tid & 3) * 8;

    const float*  Arow  = emb + (size_t)caps[arow*16 + t] * 512 + acol;
    const __half* Wh = g_lwh + (size_t)2*HID*HID;
    const __half* Wl = g_lwl + (size_t)2*HID*HID;
    const __half* Wrowh = Wh + (size_t)(bn + brow) * 512 + bcol;
    const __half* Wrowl = Wl + (size_t)(bn + brow) * 512 + bcol;

    float acc[4][2][4];
    #pragma unroll
    for (int i = 0; i < 4; i++)
        #pragma unroll
        for (int j = 0; j < 2; j++)
            #pragma unroll
            for (int k = 0; k < 4; k++) acc[i][j][k] = 0.f;

    float fa[16];
    uint4 wh4, wl4;
    #pragma unroll
    for (int p = 0; p < 4; p++)
        *(float4*)&fa[p*4] = *(const float4*)(Arow + p*4);
    wh4 = *(const uint4*)(Wrowh);
    wl4 = *(const uint4*)(Wrowl);
    {
        uint4 h0, l0, h1, l1;
        split8(&fa[0], h0, l0); split8(&fa[8], h1, l1);
        __half* ah = AHI + arow*40 + acol;
        __half* al = ALO + arow*40 + acol;
        *(uint4*)ah = h0; *(uint4*)(ah+8) = h1;
        *(uint4*)al = l0; *(uint4*)(al+8) = l1;
        *(uint4*)(BHI + brow*40 + bcol) = wh4;
        *(uint4*)(BLO + brow*40 + bcol) = wl4;
    }
    __syncthreads();

    #pragma unroll 1
    for (int kt = 0; kt < 16; kt++) {
        const int buf = kt & 1;
        const __half* Ah = AHI + buf*5120;
        const __half* Al = ALO + buf*5120;
        const __half* Bh = BHI + buf*2560;
        const __half* Bl = BLO + buf*2560;

        if (kt < 15) {
            #pragma unroll
            for (int p = 0; p < 4; p++)
                *(float4*)&fa[p*4] = *(const float4*)(Arow + (kt+1)*32 + p*4);
            wh4 = *(const uint4*)(Wrowh + (kt+1)*32);
            wl4 = *(const uint4*)(Wrowl + (kt+1)*32);
        }

        #pragma unroll
        for (int k16 = 0; k16 < 2; k16++) {
            const int kb = k16*16 + tig*2;
            uint32_t ah[4][4], al[4][4];
            #pragma unroll
            for (int mi = 0; mi < 4; mi++) {
                const __half* arh = Ah + (wm + mi*16 + grp)*40;
                const __half* arl = Al + (wm + mi*16 + grp)*40;
                ah[mi][0] = *(const uint32_t*)(arh + kb);
                ah[mi][1] = *(const uint32_t*)(arh + 8*40 + kb);
                ah[mi][2] = *(const uint32_t*)(arh + kb + 8);
                ah[mi][3] = *(const uint32_t*)(arh + 8*40 + kb + 8);
                al[mi][0] = *(const uint32_t*)(arl + kb);
                al[mi][1] = *(const uint32_t*)(arl + 8*40 + kb);
                al[mi][2] = *(const uint32_t*)(arl + kb + 8);
                al[mi][3] = *(const uint32_t*)(arl + 8*40 + kb + 8);
            }
            #pragma unroll
            for (int nj = 0; nj < 2; nj++) {
                const __half* brh = Bh + (wn + nj*8 + grp)*40 + kb;
                const __half* brl = Bl + (wn + nj*8 + grp)*40 + kb;
                uint32_t b0h = *(const uint32_t*)(brh);
                uint32_t b1h = *(const uint32_t*)(brh + 8);
                uint32_t b0l = *(const uint32_t*)(brl);
                uint32_t b1l = *(const uint32_t*)(brl + 8);
                #pragma unroll
                for (int mi = 0; mi < 4; mi++) {
                    hmma_fp16(acc[mi][nj][0], acc[mi][nj][1], acc[mi][nj][2], acc[mi][nj][3],
                              ah[mi][0], ah[mi][1], ah[mi][2], ah[mi][3], b0h, b1h);
                    hmma_fp16(acc[mi][nj][0], acc[mi][nj][1], acc[mi][nj][2], acc[mi][nj][3],
                              ah[mi][0], ah[mi][1], ah[mi][2], ah[mi][3], b0l, b1l);
                    hmma_fp16(acc[mi][nj][0], acc[mi][nj][1], acc[mi][nj][2], acc[mi][nj][3],
                              al[mi][0], al[mi][1], al[mi][2], al[mi][3], b0h, b1h);
                }
            }
        }

        if (kt < 15) {
            const int nb = buf ^ 1;
            uint4 h0, l0, h1, l1;
            split8(&fa[0], h0, l0); split8(&fa[8], h1, l1);
            __half* ah = AHI + nb*5120 + arow*40 + acol;
            __half* al = ALO + nb*5120 + arow*40 + acol;
            *(uint4*)ah = h0; *(uint4*)(ah+8) = h1;
            *(uint4*)al = l0; *(uint4*)(al+8) = l1;
            *(uint4*)(BHI + nb*2560 + brow*40 + bcol) = wh4;
            *(uint4*)(BLO + nb*2560 + brow*40 + bcol) = wl4;
        }
        __syncthreads();
    }

    #pragma unroll
    for (int mi = 0; mi < 4; mi++) {
        #pragma unroll
        for (int nj = 0; nj < 2; nj++) {
            int m = wm + mi*16 + grp;
            int nc = wn + nj*8 + tig*2;
            float bx = bias[bn + nc], by = bias[bn + nc + 1];
            uint32_t hi0, lo0, hi1, lo1;
            split2(acc[mi][nj][0] + bx, acc[mi][nj][1] + by, hi0, lo0);
            split2(acc[mi][nj][2] + bx, acc[mi][nj][3] + by, hi1, lo1);
            size_t o0 = (size_t)m * (NSTEP*HID) + (size_t)t*HID + bn + nc;
            size_t o8 = (size_t)(m+8) * (NSTEP*HID) + (size_t)t*HID + bn + nc;
            *(uint32_t*)(g_xh + o0) = hi0;
            *(uint32_t*)(g_xl + o0) = lo0;
            *(uint32_t*)(g_xh + o8) = hi1;
            *(uint32_t*)(g_xl + o8) = lo1;
        }
    }
}

// =====================================================================
// Persistent chain kernel
// =====================================================================
__device__ __forceinline__ void grid_bar() {
    __syncthreads();
    if (threadIdx.x == 0) {
        __threadfence();
        unsigned gen = *(volatile unsigned*)&g_bgen;
        if (atomicAdd(&g_bcnt, 1u) == gridDim.x - 1) {
            g_bcnt = 0;
            __threadfence();
            *(volatile unsigned*)&g_bgen = gen + 1;
        } else {
            while (*(volatile unsigned*)&g_bgen == gen) {}
        }
        __threadfence();
    }
    __syncthreads();
}

// ---- Q K-split tile (8 kt over a 256-col chunk): writes fp32 partial ----
__device__ void q_ktile(int nt, int kc,
                        const __half* __restrict__ Ahg, const __half* __restrict__ Alg,
                        __half* smg)
{
    __half* AHI = smg;
    __half* ALO = AHI + 2*5120;
    __half* BHI = ALO + 2*5120;
    __half* BLO = BHI + 2*2560;

    const int tid = threadIdx.x;
    const int lane = tid & 31, wid = tid >> 5;
    const int wm = (wid & 1) * 64;
    const int wn = (wid >> 1) * 16;
    const int grp = lane >> 2, tig = lane & 3;
    const int bn = nt * 64;
    const int koff = kc * 256;

    const int arow = tid >> 1;
    const int acol = (tid & 1) * 16;
    const int brow = tid >> 2;
    const int bcol = (tid & 3) * 8;

    const __half* Arh = Ahg + (size_t)arow * 512 + koff + acol;
    const __half* Arl = Alg + (size_t)arow * 512 + koff + acol;
    const __half* Wrowh = g_lwh + (size_t)(bn + brow) * 512 + koff + bcol;
    const __half* Wrowl = g_lwl + (size_t)(bn + brow) * 512 + koff + bcol;

    float acc[4][2][4];
    #pragma unroll
    for (int i = 0; i < 4; i++)
        #pragma unroll
        for (int j = 0; j < 2; j++)
            #pragma unroll
            for (int k = 0; k < 4; k++) acc[i][j][k] = 0.f;

    uint4 a_h0, a_h1, a_l0, a_l1, wh4, wl4;
    a_h0 = __ldcg((const uint4*)(Arh));
    a_h1 = __ldcg((const uint4*)(Arh + 8));
    a_l0 = __ldcg((const uint4*)(Arl));
    a_l1 = __ldcg((const uint4*)(Arl + 8));
    wh4 = *(const uint4*)(Wrowh);
    wl4 = *(const uint4*)(Wrowl);
    {
        __half* ah = AHI + arow*40 + acol;
        __half* al = ALO + arow*40 + acol;
        *(uint4*)ah = a_h0; *(uint4*)(ah+8) = a_h1;
        *(uint4*)al = a_l0; *(uint4*)(al+8) = a_l1;
        *(uint4*)(BHI + brow*40 + bcol) = wh4;
        *(uint4*)(BLO + brow*40 + bcol) = wl4;
    }
    __syncthreads();

    #pragma unroll 1
    for (int kt = 0; kt < 8; kt++) {
        const int buf = kt & 1;
        const __half* Ah = AHI + buf*5120;
        const __half* Al = ALO + buf*5120;
        const __half* Bh = BHI + buf*2560;
        const __half* Bl = BLO + buf*2560;

        if (kt < 7) {
            a_h0 = __ldcg((const uint4*)(Arh + (kt+1)*32));
            a_h1 = __ldcg((const uint4*)(Arh + (kt+1)*32 + 8));
            a_l0 = __ldcg((const uint4*)(Arl + (kt+1)*32));
            a_l1 = __ldcg((const uint4*)(Arl + (kt+1)*32 + 8));
            wh4 = *(const uint4*)(Wrowh + (kt+1)*32);
            wl4 = *(const uint4*)(Wrowl + (kt+1)*32);
        }

        #pragma unroll
        for (int k16 = 0; k16 < 2; k16++) {
            const int kb = k16*16 + tig*2;
            uint32_t ah[4][4], al[4][4];
            #pragma unroll
            for (int mi = 0; mi < 4; mi++) {
                const __half* arh = Ah + (wm + mi*16 + grp)*40;
                const __half* arl = Al + (wm + mi*16 + grp)*40;
                ah[mi][0] = *(const uint32_t*)(arh + kb);
                ah[mi][1] = *(const uint32_t*)(arh + 8*40 + kb);
                ah[mi][2] = *(const uint32_t*)(arh + kb + 8);
                ah[mi][3] = *(const uint32_t*)(arh + 8*40 + kb + 8);
                al[mi][0] = *(const uint32_t*)(arl + kb);
                al[mi][1] = *(const uint32_t*)(arl + 8*40 + kb);
                al[mi][2] = *(const uint32_t*)(arl + kb + 8);
                al[mi][3] = *(const uint32_t*)(arl + 8*40 + kb + 8);
            }
            #pragma unroll
            for (int nj = 0; nj < 2; nj++) {
                const __half* brh = Bh + (wn + nj*8 + grp)*40 + kb;
                const __half* brl = Bl + (wn + nj*8 + grp)*40 + kb;
                uint32_t b0h = *(const uint32_t*)(brh);
                uint32_t b1h = *(const uint32_t*)(brh + 8);
                uint32_t b0l = *(const uint32_t*)(brl);
                uint32_t b1l = *(const uint32_t*)(brl + 8);
                #pragma unroll
                for (int mi = 0; mi < 4; mi++) {
                    hmma_fp16(acc[mi][nj][0], acc[mi][nj][1], acc[mi][nj][2], acc[mi][nj][3],
                              ah[mi][0], ah[mi][1], ah[mi][2], ah[mi][3], b0h, b1h);
                    hmma_fp16(acc[mi][nj][0], acc[mi][nj][1], acc[mi][nj][2], acc[mi][nj][3],
                              ah[mi][0], ah[mi][1], ah[mi][2], ah[mi][3], b0l, b1l);
                    hmma_fp16(acc[mi][nj][0], acc[mi][nj][1], acc[mi][nj][2], acc[mi][nj][3],
                              al[mi][0], al[mi][1], al[mi][2], al[mi][3], b0h, b1h);
                }
            }
        }

        if (kt < 7) {
            const int nb = buf ^ 1;
            __half* ah = AHI + nb*5120 + arow*40 + acol;
            __half* al = ALO + nb*5120 + arow*40 + acol;
            *(uint4*)ah = a_h0; *(uint4*)(ah+8) = a_h1;
            *(uint4*)al = a_l0; *(uint4*)(al+8) = a_l1;
            *(uint4*)(BHI + nb*2560 + brow*40 + bcol) = wh4;
            *(uint4*)(BLO + nb*2560 + brow*40 + bcol) = wl4;
        }
        __syncthreads();
    }

    float* Q = g_qp + (size_t)kc * BH;
    #pragma unroll
    for (int mi = 0; mi < 4; mi++) {
        #pragma unroll
        for (int nj = 0; nj < 2; nj++) {
            int m = wm + mi*16 + grp;
            int nc = wn + nj*8 + tig*2;
            *(float2*)(Q + (size_t)m*512 + bn + nc) =
                make_float2(acc[mi][nj][0], acc[mi][nj][1]);
            *(float2*)(Q + (size_t)(m+8)*512 + bn + nc) =
                make_float2(acc[mi][nj][2], acc[mi][nj][3]);
        }
    }
    __syncthreads();
}

// ---- softmax + context ----
__device__ void att_soft(int b, int has_q, const float* __restrict__ bq,
                         const float* __restrict__ keys, const float* __restrict__ features,
                         const float* __restrict__ v_w, const float* __restrict__ v_b,
                         __half* __restrict__ coh, __half* __restrict__ col, float* sm)
{
    const int tid = threadIdx.x;
    float* qs = sm;
    float* vw = sm + 512;
    float* e  = sm + 1024;

    for (int i = tid; i < 512; i += 256) {
        float q = bq[i];
        if (has_q)
            q += __ldcg(g_qp + b*512 + i) + __ldcg(g_qp + BH + b*512 + i);
        qs[i] = q;
        vw[i] = v_w[i];
    }
    __syncthreads();

    const int warp = tid >> 5, lane = tid & 31;
    for (int s = warp; s < SEQ; s += 8) {
        const float* kp = keys + ((size_t)b * SEQ + s) * 512;
        float acc = 0.f;
        #pragma unroll
        for (int k = lane; k < 512; k += 32)
            acc += tanhf(qs[k] + kp[k]) * vw[k];
        #pragma unroll
        for (int o = 16; o; o >>= 1) acc += __shfl_xor_sync(0xffffffffu, acc, o);
        if (!lane) e[s] = acc + v_b[0];
    }
    __syncthreads();

    if (warp == 0) {
        float v1 = (lane < SEQ) ? e[lane] : -1e30f;
        float v2 = (lane + 32 < SEQ) ? e[lane + 32] : -1e30f;
        float m = fmaxf(v1, v2);
        #pragma unroll
        for (int o = 16; o; o >>= 1) m = fmaxf(m, __shfl_xor_sync(0xffffffffu, m, o));
        float e1 = (lane < SEQ) ? expf(v1 - m) : 0.f;
        float e2 = (lane + 32 < SEQ) ? expf(v2 - m) : 0.f;
        float s = e1 + e2;
        #pragma unroll
        for (int o = 16; o; o >>= 1) s += __shfl_xor_sync(0xffffffffu, s, o);
        float inv = 1.f / s;
        if (lane < SEQ) e[lane] = e1 * inv;
        if (lane + 32 < SEQ) e[lane + 32] = e2 * inv;
    }
    __syncthreads();

    for (int k = tid; k < 512; k += 256) {
        float acc = 0.f;
        const float* f = features + (size_t)b * SEQ * 512 + k;
        #pragma unroll 7
        for (int s = 0; s < SEQ; s++) acc += e[s] * f[(size_t)s * 512];
        __half hi = __float2half_rn(acc);
        __half lo = __float2half_rn(acc - __half2float(hi));
        coh[b*512 + k] = hi;
        col[b*512 + k] = lo;
    }
    __syncthreads();
}

// ---- GRU tile ----
template<int NK>
__device__ void gru_tile(int nt, int kc,
    const __half* __restrict__ sAh, const __half* __restrict__ sAl, int ldA,
    const __half* __restrict__ sBh, const __half* __restrict__ sBl,
    const __half* __restrict__ sCh, const __half* __restrict__ sCl,
    const __half* __restrict__ Wh, const __half* __restrict__ Wl, int ldK,
    const float* __restrict__ bih, const float* __restrict__ bhh,
    const float* __restrict__ h_old, float* __restrict__ h_new,
    __half* __restrict__ hnh, __half* __restrict__ hnl,
    __half* __restrict__ hs_out, __half* smg)
{
    __half* AHI = smg;
    __half* ALO = AHI + 2*5120;
    __half* BHI = ALO + 2*5120;
    __half* BLO = BHI + 2*2560;

    const int tid = threadIdx.x;
    const int lane = tid & 31, wid = tid >> 5;
    const int wm = (wid & 1) * 64;
    const int wn = (wid >> 1) * 16;
    const int grp = lane >> 2, tig = lane & 3;
    const int bn = nt * 64;

    const __half *Ahg, *Alg; int ld;
    {
        int sel = kc >> 1;
        if (sel == 0)      { Ahg = sAh; Alg = sAl; ld = ldA; }
        else if (sel == 1) { Ahg = sBh; Alg = sBl; ld = 512; }
        else               { Ahg = sCh; Alg = sCl; ld = 512; }
    }
    const int koff = (kc & 1) * 256;

    const int arow = tid >> 1;
    const int acol = (tid & 1) * 16;
    const int brow = tid >> 2;
    const int bcol = (tid & 3) * 8;

    const __half* Arh = Ahg + (size_t)arow * ld + koff + acol;
    const __half* Arl = Alg + (size_t)arow * ld + koff + acol;
    const __half* Wrowh = Wh + (size_t)(bn + brow) * ldK + kc*256 + bcol;
    const __half* Wrowl = Wl + (size_t)(bn + brow) * ldK + kc*256 + bcol;

    float acc[4][2][4];
    #pragma unroll
    for (int i = 0; i < 4; i++)
        #pragma unroll
        for (int j = 0; j < 2; j++)
            #pragma unroll
            for (int k = 0; k < 4; k++) acc[i][j][k] = 0.f;

    uint4 a_h0, a_h1, a_l0, a_l1, wh4, wl4;
    a_h0 = __ldcg((const uint4*)(Arh));
    a_h1 = __ldcg((const uint4*)(Arh + 8));
    a_l0 = __ldcg((const uint4*)(Arl));
    a_l1 = __ldcg((const uint4*)(Arl + 8));
    wh4 = *(const uint4*)(Wrowh);
    wl4 = *(const uint4*)(Wrowl);
    {
        __half* ah = AHI + arow*40 + acol;
        __half* al = ALO + arow*40 + acol;
        *(uint4*)ah = a_h0; *(uint4*)(ah+8) = a_h1;
        *(uint4*)al = a_l0; *(uint4*)(al+8) = a_l1;
        *(uint4*)(BHI + brow*40 + bcol) = wh4;
        *(uint4*)(BLO + brow*40 + bcol) = wl4;
    }
    __syncthreads();

    #pragma unroll 1
    for (int kt = 0; kt < 8; kt++) {
        const int buf = kt & 1;
        const __half* Ah = AHI + buf*5120;
        const __half* Al = ALO + buf*5120;
        const __half* Bh = BHI + buf*2560;
        const __half* Bl = BLO + buf*2560;

        if (kt < 7) {
            a_h0 = __ldcg((const uint4*)(Arh + (kt+1)*32));
            a_h1 = __ldcg((const uint4*)(Arh + (kt+1)*32 + 8));
            a_l0 = __ldcg((const uint4*)(Arl + (kt+1)*32));
            a_l1 = __ldcg((const uint4*)(Arl + (kt+1)*32 + 8));
            wh4 = *(const uint4*)(Wrowh + (kt+1)*32);
            wl4 = *(const uint4*)(Wrowl + (kt+1)*32);
        }

        #pragma unroll
        for (int k16 = 0; k16 < 2; k16++) {
            const int kb = k16*16 + tig*2;
            uint32_t ah[4][4], al[4][4];
            #pragma unroll
            for (int mi = 0; mi < 4; mi++) {
                const __half* arh = Ah + (wm + mi*16 + grp)*40;
                const __half* arl = Al + (wm + mi*16 + grp)*40;
                ah[mi][0] = *(const uint32_t*)(arh + kb);
                ah[mi][1] = *(const uint32_t*)(arh + 8*40 + kb);
                ah[mi][2] = *(const uint32_t*)(arh + kb + 8);
                ah[mi][3] = *(const uint32_t*)(arh + 8*40 + kb + 8);
                al[mi][0] = *(const uint32_t*)(arl + kb);
                al[mi][1] = *(const uint32_t*)(arl + 8*40 + kb);
                al[mi][2] = *(const uint32_t*)(arl + kb + 8);
                al[mi][3] = *(const uint32_t*)(arl + 8*40 + kb + 8);
            }
            #pragma unroll
            for (int nj = 0; nj < 2; nj++) {
                const __half* brh = Bh + (wn + nj*8 + grp)*40 + kb;
                const __half* brl = Bl + (wn + nj*8 + grp)*40 + kb;
                uint32_t b0h = *(const uint32_t*)(brh);
                uint32_t b1h = *(const uint32_t*)(brh + 8);
                uint32_t b0l = *(const uint32_t*)(brl);
                uint32_t b1l = *(const uint32_t*)(brl + 8);
                #pragma unroll
                for (int mi = 0; mi < 4; mi++) {
                    hmma_fp16(acc[mi][nj][0], acc[mi][nj][1], acc[mi][nj][2], acc[mi][nj][3],
                              ah[mi][0], ah[mi][1], ah[mi][2], ah[mi][3], b0h, b1h);
                    hmma_fp16(acc[mi][nj][0], acc[mi][nj][1], acc[mi][nj][2], acc[mi][nj][3],
                              ah[mi][0], ah[mi][1], ah[mi][2], ah[mi][3], b0l, b1l);
                    hmma_fp16(acc[mi][nj][0], acc[mi][nj][1], acc[mi][nj][2], acc[mi][nj][3],
                              al[mi][0], al[mi][1], al[mi][2], al[mi][3], b0h, b1h);
                }
            }
        }

        if (kt < 7) {
            const int nb = buf ^ 1;
            __half* ah = AHI + nb*5120 + arow*40 + acol;
            __half* al = ALO + nb*5120 + arow*40 + acol;
            *(uint4*)ah = a_h0; *(uint4*)(ah+8) = a_h1;
            *(uint4*)al = a_l0; *(uint4*)(al+8) = a_l1;
            *(uint4*)(BHI + nb*2560 + brow*40 + bcol) = wh4;
            *(uint4*)(BLO + nb*2560 + brow*40 + bcol) = wl4;
        }
        __syncthreads();
    }

    {
        float* P = g_part + ((size_t)(kc*24 + nt)) * 8192;
        #pragma unroll
        for (int mi = 0; mi < 4; mi++) {
            #pragma unroll
            for (int nj = 0; nj < 2; nj++) {
                int m = wm + mi*16 + grp;
                int nc = wn + nj*8 + tig*2;
                *(float2*)(P + m*64 + nc)     = make_float2(acc[mi][nj][0], acc[mi][nj][1]);
                *(float2*)(P + (m+8)*64 + nc) = make_float2(acc[mi][nj][2], acc[mi][nj][3]);
            }
        }
    }

    __threadfence();
    __shared__ int sdone;
    if (tid == 0) {
        int g = nt & 7;
        int v = atomicAdd(&g_cnt[g], 1);
        int done = (v == 3*NK - 1);
        if (done) g_cnt[g] = 0;
        sdone = done;
    }
    __syncthreads();
    if (!sdone) return;
    __threadfence();

    const int g = nt & 7;
    const int cc = (tid & 15) * 4;
    const int c  = g*64 + cc;
    float4 bir = *(const float4*)(bih + c);
    float4 biz = *(const float4*)(bih + 512 + c);
    float4 bin = *(const float4*)(bih + 1024 + c);
    float4 bhr = *(const float4*)(bhh + c);
    float4 bhz = *(const float4*)(bhh + 512 + c);
    float4 bhn = *(const float4*)(bhh + 1024 + c);

    #pragma unroll
    for (int i = 0; i < 8; i++) {
        const int m = (tid >> 4) * 8 + i;
        float4 r4 = make_float4(0,0,0,0), z4 = r4, in4 = r4, hn4 = r4;
        #pragma unroll
        for (int kx = 0; kx < NK; kx++) {
            const float* Pr = g_part + ((size_t)(kx*24 + g))      * 8192 + m*64 + cc;
            const float* Pz = g_part + ((size_t)(kx*24 + 8 + g))  * 8192 + m*64 + cc;
            const float* Pn = g_part + ((size_t)(kx*24 + 16 + g)) * 8192 + m*64 + cc;
            float4 a = __ldcg((const float4*)Pr);
            r4.x += a.x; r4.y += a.y; r4.z += a.z; r4.w += a.w;
            a = __ldcg((const float4*)Pz);
            z4.x += a.x; z4.y += a.y; z4.z += a.z; z4.w += a.w;
            a = __ldcg((const float4*)Pn);
            if (kx < NK-2) { in4.x += a.x; in4.y += a.y; in4.z += a.z; in4.w += a.w; }
            else           { hn4.x += a.x; hn4.y += a.y; hn4.z += a.z; hn4.w += a.w; }
        }
        float4 ho = __ldcg((const float4*)(h_old + (size_t)m*512 + c));
        float hv[4];
        #pragma unroll
        for (int q = 0; q < 4; q++) {
            float rp = ((float*)&r4)[q] + ((float*)&bir)[q] + ((float*)&bhr)[q];
            float zp = ((float*)&z4)[q] + ((float*)&biz)[q] + ((float*)&bhz)[q];
            float ip = ((float*)&in4)[q] + ((float*)&bin)[q];
            float hp = ((float*)&hn4)[q] + ((float*)&bhn)[q];
            float r = 1.f / (1.f + expf(-rp));
            float z = 1.f / (1.f + expf(-zp));
            float n = tanhf(ip + r * hp);
            hv[q] = (1.f - z) * n + z * ((float*)&ho)[q];
        }
        *(float4*)(h_new + (size_t)m*512 + c) = make_float4(hv[0], hv[1], hv[2], hv[3]);
        uint32_t hi0, lo0, hi1, lo1;
        split2(hv[0], hv[1], hi0, lo0);
        split2(hv[2], hv[3], hi1, lo1);
        *(uint32_t*)(hnh + (size_t)m*512 + c)     = hi0;
        *(uint32_t*)(hnh + (size_t)m*512 + c + 2) = hi1;
        *(uint32_t*)(hnl + (size_t)m*512 + c)     = lo0;
        *(uint32_t*)(hnl + (size_t)m*512 + c + 2) = lo1;
        if (hs_out) {
            uint2 ov; ov.x = hi0; ov.y = hi1;
            *(uint2*)(hs_out + (size_t)m*512 + c) = ov;
        }
    }
}

// ---- persistent chain kernel ----
__global__ void __launch_bounds__(256, 1) chain_kernel(
    const float* __restrict__ features,
    const float* __restrict__ bq,
    const float* __restrict__ v_w, const float* __restrict__ v_b,
    const float* __restrict__ bhh0,
    const float* __restrict__ bihr, const float* __restrict__ bhhr)
{
    extern __shared__ __half smg[];
    float* smf = (float*)smg;

    for (int t = 0; t < NSTEP; t++) {
        const int ho = (t & 1) * (4 * BH);
        const int no = ((t & 1) ^ 1) * (4 * BH);
        const float* hold = g_h + ho;
        float*       hnew = g_h + no;

        // Q (skip at t=0: h == 0 -> q = bq)
        if (t > 0) {
            for (int w = blockIdx.x; w < 16; w += gridDim.x)
                q_ktile(w & 7, w >> 3, g_hh + ho + 3*BH, g_hl + ho + 3*BH, smg);
            grid_bar();
        }

        // S: softmax + context -> hi/lo
        for (int b = blockIdx.x; b < BATCH; b += gridDim.x)
            att_soft(b, t > 0, bq, g_keys, features, v_w, v_b, g_coh, g_col, smf);
        grid_bar();

        // L0
        for (int w = blockIdx.x; w < 144; w += gridDim.x)
            gru_tile<6>(w % 24, w / 24,
                        g_xh + t*HID, g_xl + t*HID, NSTEP*HID,
                        g_coh, g_col,
                        g_hh + ho, g_hl + ho,
                        g_wh, g_wl, 1536, g_bihe, bhh0, hold, hnew,
                        g_hh + no, g_hl + no, nullptr, smg);
        grid_bar();

        // L1..L3
        for (int l = 1; l < 4; l++) {
            const size_t off = (size_t)1536*1536 + (size_t)(l-1)*1536*1024;
            __half* hs_out = (l == 3) ? (g_hsh + t * BH) : nullptr;
            for (int w = blockIdx.x; w < 96; w += gridDim.x)
                gru_tile<4>(w % 24, w / 24,
                            g_hh + no + (l-1)*BH, g_hl + no + (l-1)*BH, 512,
                            g_hh + ho + l*BH, g_hl + ho + l*BH,
                            nullptr, nullptr,
                            g_wh + off, g_wl + off, 1024,
                            bihr + (l-1)*1536, bhhr + (l-1)*1536,
                            hold + l*BH, hnew + l*BH,
                            g_hh + no + l*BH, g_hl + no + l*BH, hs_out, smg);
            grid_bar();
        }
    }
}

// ---------------- fc2 via mma.sync fp16 ----------------
#define F2_PAD  40
#define F2_ASZ  (128*F2_PAD)
#define F2_BSZ  (256*F2_PAD)
#define F2_SMEM ((2*F2_ASZ + 2*F2_BSZ)*2)

__global__ void __launch_bounds__(256, 1) fc2_mma_fp16(
    const __half* __restrict__ A, const __half* __restrict__ Bw,
    const float* __restrict__ bias, float* __restrict__ out)
{
    extern __shared__ __half smh[];
    __half* As = smh;
    __half* Bs = smh + 2*F2_ASZ;

    const int tid  = threadIdx.x;
    const int lane = tid & 31, wid = tid >> 5;
    const int wm = (wid >> 2) * 64;
    const int wn = (wid & 3)  * 64;
    const int grp = lane >> 2;
    const int tig = lane & 3;
    const int bn = blockIdx.x * 256;
    const int t  = blockIdx.y;

    const __half* Ab = A  + (size_t)t  * 128 * 512;
    const __half* Bb = Bw + (size_t)bn * 512;

    float acc[4][8][4];
    #pragma unroll
    for (int i = 0; i < 4; i++)
        #pragma unroll
        for (int j = 0; j < 8; j++)
            #pragma unroll
            for (int k = 0; k < 4; k++) acc[i][j][k] = 0.f;

    uint4 ra[2], rb[4];
    #pragma unroll
    for (int p = 0; p < 2; p++) {
        int idx = tid + p * 256;
        int row = idx >> 2, c8 = (idx & 3) * 8;
        ra[p] = *(const uint4*)(Ab + (size_t)row * 512 + c8);
    }
    #pragma unroll
    for (int p = 0; p < 4; p++) {
        int idx = tid + p * 256;
        int row = idx >> 2, c8 = (idx & 3) * 8;
        rb[p] = *(const uint4*)(Bb + (size_t)row * 512 + c8);
    }
    #pragma unroll
    for (int p = 0; p < 2; p++) {
        int idx = tid + p * 256;
        int row = idx >> 2, c8 = (idx & 3) * 8;
        *(uint4*)(As + row*F2_PAD + c8) = ra[p];
    }
    #pragma unroll
    for (int p = 0; p < 4; p++) {
        int idx = tid + p * 256;
        int row = idx >> 2, c8 = (idx & 3) * 8;
        *(uint4*)(Bs + row*F2_PAD + c8) = rb[p];
    }
    __syncthreads();

    #pragma unroll 1
    for (int kt = 0; kt < 16; kt++) {
        const int buf = kt & 1;
        const __half* Asb = As + buf * F2_ASZ;
        const __half* Bsb = Bs + buf * F2_BSZ;

        if (kt < 15) {
            const __half* Aq = Ab + (kt+1)*32;
            const __half* Bq = Bb + (kt+1)*32;
            #pragma unroll
            for (int p = 0; p < 2; p++) {
                int idx = tid + p * 256;
                int row = idx >> 2, c8 = (idx & 3) * 8;
                ra[p] = *(const uint4*)(Aq + (size_t)row * 512 + c8);
            }
            #pragma unroll
            for (int p = 0; p < 4; p++) {
                int idx = tid + p * 256;
                int row = idx >> 2, c8 = (idx & 3) * 8;
                rb[p] = *(const uint4*)(Bq + (size_t)row * 512 + c8);
            }
        }

        #pragma unroll
        for (int k16 = 0; k16 < 2; k16++) {
            const int kb = k16*16 + tig*2;
            uint32_t af[4][4];
            #pragma unroll
            for (int mi = 0; mi < 4; mi++) {
                const __half* ar = Asb + (wm + mi*16 + grp)*F2_PAD;
                af[mi][0] = *(const uint32_t*)(ar + kb);
                af[mi][1] = *(const uint32_t*)(ar + 8*F2_PAD + kb);
                af[mi][2] = *(const uint32_t*)(ar + kb + 8);
                af[mi][3] = *(const uint32_t*)(ar + 8*F2_PAD + kb + 8);
            }
            #pragma unroll
            for (int nj = 0; nj < 8; nj++) {
                const __half* br = Bsb + (wn + nj*8 + grp)*F2_PAD + kb;
                uint32_t b0 = *(const uint32_t*)(br);
                uint32_t b1 = *(const uint32_t*)(br + 8);
                #pragma unroll
                for (int mi = 0; mi < 4; mi++)
                    hmma_fp16(acc[mi][nj][0], acc[mi][nj][1], acc[mi][nj][2], acc[mi][nj][3],
                              af[mi][0], af[mi][1], af[mi][2], af[mi][3], b0, b1);
            }
        }

        if (kt < 15) {
            __half* Asn = As + (buf ^ 1) * F2_ASZ;
            __half* Bsn = Bs + (buf ^ 1) * F2_BSZ;
            #pragma unroll
            for (int p = 0; p < 2; p++) {
                int idx = tid + p * 256;
                int row = idx >> 2, c8 = (idx & 3) * 8;
                *(uint4*)(Asn + row*F2_PAD + c8) = ra[p];
            }
            #pragma unroll
            for (int p = 0; p < 4; p++) {
                int idx = tid + p * 256;
                int row = idx >> 2, c8 = (idx & 3) * 8;
                *(uint4*)(Bsn + row*F2_PAD + c8) = rb[p];
            }
        }
        __syncthreads();
    }

    #pragma unroll
    for (int mi = 0; mi < 4; mi++) {
        const int b0 = wm + mi*16 + grp;
        float* o0 = out + ((size_t)b0       * NSTEP + t) * VOCAB + bn + wn;
        float* o8 = out + ((size_t)(b0 + 8) * NSTEP + t) * VOCAB + bn + wn;
        #pragma unroll
        for (int nj = 0; nj < 8; nj++) {
            const int n = nj*8 + 2*tig;
            float bx = bias[bn + wn + n];
            float by = bias[bn + wn + n + 1];
            *(float2*)(o0 + n) = make_float2(acc[mi][nj][0] + bx, acc[mi][nj][1] + by);
            *(float2*)(o8 + n) = make_float2(acc[mi][nj][2] + bx, acc[mi][nj][3] + by);
        }
    }
}

// ---------------- host launch ----------------
extern "C" void kernel_launch(void* const* d_in, const int* in_sizes, int n_in,
                              void* d_out, int out_size)
{
    const float* features = (const float*)d_in[0];
    const int*   caps     = (const int*)  d_in[1];
    const float* emb      = (const float*)d_in[2];
    const float* fc1_w    = (const float*)d_in[3];
    const float* fc1_b    = (const float*)d_in[4];
    const float* fc0_w    = (const float*)d_in[5];
    const float* fc0_b    = (const float*)d_in[6];
    const float* wq       = (const float*)d_in[7];
    const float* bq       = (const float*)d_in[8];
    const float* wk       = (const float*)d_in[9];
    const float* bk       = (const float*)d_in[10];
    const float* v_w      = (const float*)d_in[11];
    const float* v_b      = (const float*)d_in[12];
    const float* wih0     = (const float*)d_in[13];
    const float* whh0     = (const float*)d_in[14];
    const float* bih0     = (const float*)d_in[15];
    const float* bhh0     = (const float*)d_in[16];
    const float* wihr     = (const float*)d_in[17];
    const float* whhr     = (const float*)d_in[18];
    const float* bihr     = (const float*)d_in[19];
    const float* bhhr     = (const float*)d_in[20];
    const float* fc2_w    = (const float*)d_in[21];
    const float* fc2_b    = (const float*)d_in[22];
    float* out = (float*)d_out;

    float* pkeys;
    __half *phsh, *pw2h;
    cudaGetSymbolAddress((void**)&pkeys, g_keys);
    cudaGetSymbolAddress((void**)&phsh,  g_hsh);
    cudaGetSymbolAddress((void**)&pw2h,  g_w2h);

    cudaFuncSetAttribute(fc2_mma_fp16, cudaFuncAttributeMaxDynamicSharedMemorySize, F2_SMEM);
    cudaFuncSetAttribute(keys_mma,     cudaFuncAttributeMaxDynamicSharedMemorySize, K_SMEMB);
    cudaFuncSetAttribute(chain_kernel, cudaFuncAttributeMaxDynamicSharedMemorySize, GR_SMEM);
    cudaFuncSetAttribute(xgemm_mma,    cudaFuncAttributeMaxDynamicSharedMemorySize, GR_SMEM);
    cudaFuncSetAttribute(w0c_mma,      cudaFuncAttributeMaxDynamicSharedMemorySize, GR_SMEM);

    int nsm = 0;
    cudaDeviceGetAttribute(&nsm, cudaDevAttrMultiProcessorCount, 0);
    int nb = nsm;
    if (nb > 144) nb = 144;

    // chain is 6th launch (ncu -s 5 -c 1)
    init_kernel<<<1030, 256>>>(wih0, fc0_b, bih0);                                // 1
    wsplit_all<<<11840, 256>>>(wih0, whh0, wihr, whhr, wq, fc0_w, fc1_w, fc2_w);  // 2
    w0c_mma<<<dim3(8, 12), 256, GR_SMEM>>>(wih0);                                 // 3
    xgemm_mma<<<dim3(8, 15), 256, GR_SMEM>>>(emb, caps, fc1_b);                   // 4
    keys_mma<<<dim3(2, 49), 256, K_SMEMB>>>(features, wk, bk, pkeys);             // 5

    chain_kernel<<<nb, 256, GR_SMEM>>>(features, bq, v_w, v_b,                    // 6
                                       bhh0, bihr, bhhr);

    fc2_mma_fp16<<<dim3(VOCAB/256, NSTEP), 256, F2_SMEM>>>(phsh, pw2h, fc2_b, out);  // 7
}